// round 11
// baseline (speedup 1.0000x reference)
#include <cuda_runtime.h>
#include <cuda_bf16.h>
#include <cstdint>
#include <cstddef>

#define S_LEN 2048
#define D_EMB 2048
#define NHEAD 16
#define HDIM 64
#define DVDIM 128
#define BATCH 2
#define MROWS (BATCH * S_LEN)   // 4096
#define NQKV 6144
#define WCOLS 8192

#define LAMBDA_INIT_F 0.78360576653162435f
#define ONE_MINUS_LI_F 0.21639423346837565f
#define LN1E4_OVER_32 (9.210340371976184f / 32.0f)
#define SCALE_LOG2 0.18033688011112042f   // 0.125 * log2(e)

// ---------------- scratch (device globals) -------------------------------
__device__ float2 g_rope[S_LEN * 32];          // [s][j] -> (cos, sin)

__device__ __nv_bfloat16 g_xhi[(size_t)MROWS * D_EMB];
__device__ __nv_bfloat16 g_xlo[(size_t)MROWS * D_EMB];
__device__ __nv_bfloat16 g_whi[(size_t)D_EMB * WCOLS];   // [K, Wq|Wk|Wv|Wo]
__device__ __nv_bfloat16 g_wlo[(size_t)D_EMB * WCOLS];
__device__ __nv_bfloat16 g_ahi[(size_t)MROWS * D_EMB];
__device__ __nv_bfloat16 g_alo[(size_t)MROWS * D_EMB];

__device__ __nv_bfloat16 g_Qhi[(size_t)MROWS * D_EMB];
__device__ __nv_bfloat16 g_Qlo[(size_t)MROWS * D_EMB];
__device__ __nv_bfloat16 g_Khi[(size_t)MROWS * D_EMB];
__device__ __nv_bfloat16 g_Klo[(size_t)MROWS * D_EMB];
__device__ __nv_bfloat16 g_Vhi[(size_t)MROWS * D_EMB];
__device__ __nv_bfloat16 g_Vlo[(size_t)MROWS * D_EMB];

// ---------------- common PTX helpers --------------------------------------
__device__ __forceinline__ uint32_t smem_u32(const void* p) {
    return (uint32_t)__cvta_generic_to_shared(p);
}
__device__ __forceinline__ void cp16(uint32_t s, const void* g) {
    asm volatile("cp.async.ca.shared.global [%0], [%1], 16;" :: "r"(s), "l"(g));
}
__device__ __forceinline__ void cp16cg(uint32_t s, const void* g) {
    asm volatile("cp.async.cg.shared.global [%0], [%1], 16;" :: "r"(s), "l"(g));
}
__device__ __forceinline__ void ldmx4(uint32_t r[4], uint32_t addr) {
    asm volatile("ldmatrix.sync.aligned.m8n8.x4.shared.b16 {%0,%1,%2,%3}, [%4];"
        : "=r"(r[0]), "=r"(r[1]), "=r"(r[2]), "=r"(r[3]) : "r"(addr));
}
__device__ __forceinline__ void ldmx4t(uint32_t r[4], uint32_t addr) {
    asm volatile("ldmatrix.sync.aligned.m8n8.x4.trans.shared.b16 {%0,%1,%2,%3}, [%4];"
        : "=r"(r[0]), "=r"(r[1]), "=r"(r[2]), "=r"(r[3]) : "r"(addr));
}
__device__ __forceinline__ void mma_bf16(float c[4], const uint32_t a[4], const uint32_t b[2]) {
    asm volatile("mma.sync.aligned.m16n8k16.row.col.f32.bf16.bf16.f32 "
        "{%0,%1,%2,%3}, {%4,%5,%6,%7}, {%8,%9}, {%0,%1,%2,%3};"
        : "+f"(c[0]), "+f"(c[1]), "+f"(c[2]), "+f"(c[3])
        : "r"(a[0]), "r"(a[1]), "r"(a[2]), "r"(a[3]), "r"(b[0]), "r"(b[1]));
}
__device__ __forceinline__ uint32_t pack_bf16(float lo, float hi) {
    uint32_t r;
    asm("cvt.rn.bf16x2.f32 %0, %1, %2;" : "=r"(r) : "f"(hi), "f"(lo));
    return r;
}
__device__ __forceinline__ float fexp2(float x) {
    float r;
    asm("ex2.approx.f32 %0, %1;" : "=f"(r) : "f"(x));
    return r;
}
__device__ __forceinline__ void split2(float v0, float v1, uint32_t& hw, uint32_t& lw) {
    __nv_bfloat16 h0 = __float2bfloat16(v0);
    __nv_bfloat16 h1 = __float2bfloat16(v1);
    __nv_bfloat162 hh = __halves2bfloat162(h0, h1);
    hw = *(uint32_t*)&hh;
    lw = pack_bf16(v0 - __bfloat162float(h0), v1 - __bfloat162float(h1));
}

// =================== fp32 -> (bf16 hi, bf16 lo) split ====================
__global__ void split_kernel(const float* __restrict__ in,
                             __nv_bfloat16* __restrict__ hi,
                             __nv_bfloat16* __restrict__ lo, int n4)
{
    int i = blockIdx.x * blockDim.x + threadIdx.x;
    if (i >= n4) return;
    float4 v = ((const float4*)in)[i];
    uint32_t h0, l0, h1, l1;
    split2(v.x, v.y, h0, l0);
    split2(v.z, v.w, h1, l1);
    ((uint32_t*)hi)[2 * i]     = h0;
    ((uint32_t*)hi)[2 * i + 1] = h1;
    ((uint32_t*)lo)[2 * i]     = l0;
    ((uint32_t*)lo)[2 * i + 1] = l1;
}

// ===== all 4 W -> packed [2048, 8192] + split; also fills rope table =====
__global__ void wsplit_all_kernel(const float* __restrict__ W0, const float* __restrict__ W1,
                                  const float* __restrict__ W2, const float* __restrict__ W3,
                                  __nv_bfloat16* __restrict__ hi, __nv_bfloat16* __restrict__ lo)
{
    const int wsel = blockIdx.y;
    if (wsel == 0 && blockIdx.x < 256) {
        int idx = blockIdx.x * 256 + threadIdx.x;
        int s = idx >> 5, j = idx & 31;
        float inv = expf(-(float)j * LN1E4_OVER_32);
        float sn, cs;
        sincosf((float)s * inv, &sn, &cs);
        g_rope[idx] = make_float2(cs, sn);
    }
    int i = blockIdx.x * blockDim.x + threadIdx.x;
    if (i >= (D_EMB * D_EMB) / 4) return;
    const float* in = (wsel == 0) ? W0 : (wsel == 1) ? W1 : (wsel == 2) ? W2 : W3;
    int r = i >> 9;
    int c4 = (i & 511) << 2;
    float4 v = ((const float4*)in)[i];
    uint32_t h0, l0, h1, l1;
    split2(v.x, v.y, h0, l0);
    split2(v.z, v.w, h1, l1);
    size_t o = ((size_t)r * WCOLS + wsel * 2048 + c4) >> 1;
    ((uint32_t*)hi)[o]     = h0;
    ((uint32_t*)hi)[o + 1] = h1;
    ((uint32_t*)lo)[o]     = l0;
    ((uint32_t*)lo)[o + 1] = l1;
}

// =================== tensor-core GEMM (bf16 x3 split) ====================
// C[M,N] = A[M,K] * B[K,N]. 256 threads, 128x128 tile, BK=32, 3 stages,
// prefetch distance 2, 1 barrier/iter, 2 CTAs per SM.
// 1D grid with GROUP_M=16 rasterization (L2 reuse: wave covers ~16x18 tiles).
#define GBK 32
#define GAP 80
#define GBP 272
#define GOFF_AL (128 * GAP)
#define GOFF_BH (2 * 128 * GAP)
#define GOFF_BL (GOFF_BH + GBK * GBP)
#define GSTAGE (GOFF_BL + GBK * GBP)
#define G_SMEM (3 * GSTAGE)
#define GROUP_M 16

template <int MODE>
__global__ __launch_bounds__(256, 2)
void gemm_bf16x3(const __nv_bfloat16* __restrict__ Ahi, const __nv_bfloat16* __restrict__ Alo,
                 const __nv_bfloat16* __restrict__ Bhi, const __nv_bfloat16* __restrict__ Blo,
                 float* __restrict__ C, int M, int N, int K, int ldb, int ldc)
{
    extern __shared__ __align__(16) uint8_t gsm[];
    const uint32_t sbase = smem_u32(gsm);
    const int tid = threadIdx.x;
    const int lane = tid & 31;
    const int wid = tid >> 5;

    // grouped rasterization
    const int grid_m = M >> 7;
    const int grid_n = N >> 7;
    int pid = blockIdx.x;
    int npg = GROUP_M * grid_n;
    int gid2 = pid / npg;
    int fm = gid2 * GROUP_M;
    int gsmz = min(grid_m - fm, GROUP_M);
    int pm = fm + (pid % gsmz);
    int pn = (pid % npg) / gsmz;
    const int m0 = pm * 128;
    const int n0 = pn * 128;

    const int wm = wid & 3;
    const int wn = wid >> 2;

    const int KT = K / GBK;

    auto load_stage = [&](int t) {
        uint32_t st = sbase + (t % 3) * GSTAGE;
        int k0 = t * GBK;
#pragma unroll
        for (int j = 0; j < 8; j++) {
            int cid = tid + 256 * j;
            if (cid < 1024) {
                int hl = cid >> 9;
                int sub = cid & 511;
                int row = sub >> 2;
                int ch = sub & 3;
                const __nv_bfloat16* src = (hl ? Alo : Ahi)
                    + (size_t)(m0 + row) * K + k0 + ch * 8;
                cp16cg(st + (hl ? GOFF_AL : 0) + row * GAP + ch * 16, src);
            } else {
                int c2 = cid - 1024;
                int hl = c2 >> 9;
                int sub = c2 & 511;
                int row = sub >> 4;
                int ch = sub & 15;
                const __nv_bfloat16* src = (hl ? Blo : Bhi)
                    + (size_t)(k0 + row) * ldb + n0 + ch * 8;
                cp16cg(st + (hl ? GOFF_BL : GOFF_BH) + row * GBP + ch * 16, src);
            }
        }
        asm volatile("cp.async.commit_group;");
    };

    load_stage(0);
    load_stage(1);

    float acc[2][8][4];
#pragma unroll
    for (int i = 0; i < 2; i++)
#pragma unroll
        for (int j = 0; j < 8; j++)
#pragma unroll
            for (int l = 0; l < 4; l++) acc[i][j][l] = 0.f;

    const uint32_t aoff = (uint32_t)(wm * 32 + (lane & 15)) * GAP + ((lane >> 4) & 1) * 16;
    const uint32_t boff = (uint32_t)(lane & 15) * GBP + (uint32_t)wn * 128
                        + ((lane >> 4) & 1) * 16;

    for (int t = 0; t < KT; t++) {
        if (t + 1 < KT) asm volatile("cp.async.wait_group 1;");
        else            asm volatile("cp.async.wait_group 0;");
        __syncthreads();
        if (t + 2 < KT) load_stage(t + 2);

        uint32_t st = sbase + (t % 3) * GSTAGE;
#pragma unroll
        for (int kk = 0; kk < 2; kk++) {
            uint32_t ah[2][4], al[2][4];
            ldmx4(ah[0], st + aoff + kk * 32);
            ldmx4(ah[1], st + aoff + 16 * GAP + kk * 32);
            ldmx4(al[0], st + GOFF_AL + aoff + kk * 32);
            ldmx4(al[1], st + GOFF_AL + aoff + 16 * GAP + kk * 32);
            uint32_t bb = st + boff + (uint32_t)kk * 16 * GBP;
#pragma unroll
            for (int half = 0; half < 2; half++) {
                uint32_t bh[8], bl[8];
                ldmx4t(&bh[0], bb + GOFF_BH + half * 64);
                ldmx4t(&bh[4], bb + GOFF_BH + half * 64 + 32);
                ldmx4t(&bl[0], bb + GOFF_BL + half * 64);
                ldmx4t(&bl[4], bb + GOFF_BL + half * 64 + 32);
#pragma unroll
                for (int mt = 0; mt < 2; mt++)
#pragma unroll
                    for (int nt = 0; nt < 4; nt++) {
                        int ng = half * 4 + nt;
                        mma_bf16(acc[mt][ng], ah[mt], &bh[nt * 2]);
                        mma_bf16(acc[mt][ng], al[mt], &bh[nt * 2]);
                        mma_bf16(acc[mt][ng], ah[mt], &bl[nt * 2]);
                    }
            }
        }
    }

    // epilogue
    const int gid = lane >> 2, tig = lane & 3;
    if (MODE == 0) {
#pragma unroll
        for (int mt = 0; mt < 2; mt++) {
            int row = m0 + wm * 32 + mt * 16 + gid;
#pragma unroll
            for (int nt = 0; nt < 8; nt++) {
                int col = n0 + wn * 64 + nt * 8 + 2 * tig;
                *(float2*)&C[(size_t)row * ldc + col] = make_float2(acc[mt][nt][0], acc[mt][nt][1]);
                *(float2*)&C[(size_t)(row + 8) * ldc + col] = make_float2(acc[mt][nt][2], acc[mt][nt][3]);
            }
        }
    } else {
        const int region = n0 >> 11;    // 0=Q, 1=K, 2=V
        __nv_bfloat16* dh = (region == 0) ? g_Qhi : (region == 1) ? g_Khi : g_Vhi;
        __nv_bfloat16* dl = (region == 0) ? g_Qlo : (region == 1) ? g_Klo : g_Vlo;
#pragma unroll
        for (int mt = 0; mt < 2; mt++) {
#pragma unroll
            for (int nt = 0; nt < 8; nt++) {
                int col = n0 + wn * 64 + nt * 8 + 2 * tig;
                int cl = col & 2047;
                int j = (cl & 63) >> 1;
#pragma unroll
                for (int rr = 0; rr < 2; rr++) {
                    int row = m0 + wm * 32 + mt * 16 + gid + rr * 8;
                    float v0 = acc[mt][nt][rr * 2 + 0];
                    float v1 = acc[mt][nt][rr * 2 + 1];
                    if (region < 2) {
                        int s = row & (S_LEN - 1);
                        float2 t = g_rope[(s << 5) + j];
                        float f0 = v0 * t.x - v1 * t.y;
                        float f1 = v1 * t.x + v0 * t.y;
                        v0 = f0; v1 = f1;
                    }
                    uint32_t hw, lw;
                    split2(v0, v1, hw, lw);
                    size_t o = ((size_t)row * D_EMB + cl) >> 1;
                    ((uint32_t*)dh)[o] = hw;
                    ((uint32_t*)dl)[o] = lw;
                }
            }
        }
    }
}

// ================= MMA dual-branch flash attention (double-buffered) ======
#define PQB 144
#define PVB 272
#define QK_TILE (64 * PQB)              // 9216
#define V_TILE  (64 * PVB)              // 17408
#define FOFF_Q 0
#define FSTG (4 * QK_TILE + 2 * V_TILE) // 71680
#define FOFF_S0 (4 * QK_TILE)           // 36864
#define FOFF_LAM (FOFF_S0 + 2 * FSTG)   // 180224
#define FL_SMEM (FOFF_LAM + 16)

__global__ __launch_bounds__(256, 1)
void flash_mma_kernel(const __nv_bfloat16* __restrict__ Qhi, const __nv_bfloat16* __restrict__ Qlo,
                      const __nv_bfloat16* __restrict__ Khi, const __nv_bfloat16* __restrict__ Klo,
                      const __nv_bfloat16* __restrict__ Vhi, const __nv_bfloat16* __restrict__ Vlo,
                      const float* __restrict__ lq1, const float* __restrict__ lk1,
                      const float* __restrict__ lq2, const float* __restrict__ lk2,
                      const float* __restrict__ lnw, const float* __restrict__ lnb,
                      __nv_bfloat16* __restrict__ Ahi, __nv_bfloat16* __restrict__ Alo)
{
    extern __shared__ __align__(16) uint8_t smraw[];
    const uint32_t sbase = smem_u32(smraw);
    float* sOut = (float*)smraw;
    float* sLam = (float*)(smraw + FOFF_LAM);

    const int tid = threadIdx.x;
    const int lane = tid & 31;
    const int wid = tid >> 5;
    const int br = wid >> 2;
    const int rbase = (wid & 3) * 16;
    const int g = lane >> 2;
    const int tg = lane & 3;

    const int qt = (int)gridDim.x - 1 - (int)blockIdx.x;
    const int h = blockIdx.y;
    const int b = blockIdx.z;
    const int q0t = qt * 64;
    const size_t rowBase = (size_t)b * S_LEN;
    const int colH = h * 128;

    if (wid == 0) {
        float d1 = lq1[lane] * lk1[lane] + lq1[lane + 32] * lk1[lane + 32];
        float d2 = lq2[lane] * lk2[lane] + lq2[lane + 32] * lk2[lane + 32];
#pragma unroll
        for (int ofs = 16; ofs > 0; ofs >>= 1) {
            d1 += __shfl_xor_sync(0xffffffffu, d1, ofs);
            d2 += __shfl_xor_sync(0xffffffffu, d2, ofs);
        }
        if (lane == 0) sLam[0] = expf(d1) - expf(d2) + LAMBDA_INIT_F;
    }

#pragma unroll
    for (int it = 0; it < 8; it++) {
        int idx = tid + 256 * it;
        int ch = idx & 7, r = (idx >> 3) & 63, t = idx >> 9;
        const __nv_bfloat16* src = ((t & 1) ? Qlo : Qhi)
            + (rowBase + q0t + r) * D_EMB + colH + (t >> 1) * 64 + ch * 8;
        cp16(sbase + FOFF_Q + t * QK_TILE + r * PQB + ch * 16, src);
    }
    asm volatile("cp.async.commit_group;");
    asm volatile("cp.async.wait_group 0;");
    __syncthreads();

    uint32_t qh[4][4], ql[4][4];
    {
        uint32_t qoff = (uint32_t)(rbase + (lane & 15)) * PQB + ((lane >> 4) << 4);
        uint32_t bh_ = sbase + FOFF_Q + (br * 2) * QK_TILE;
#pragma unroll
        for (int s = 0; s < 4; s++) {
            ldmx4(qh[s], bh_ + qoff + s * 32);
            ldmx4(ql[s], bh_ + QK_TILE + qoff + s * 32);
        }
    }

    auto load_kv = [&](int kt) {
        uint32_t stb = sbase + FOFF_S0 + (kt & 1) * FSTG;
#pragma unroll
        for (int it = 0; it < 8; it++) {
            int idx = tid + 256 * it;
            int ch = idx & 7, r = (idx >> 3) & 63, t = idx >> 9;
            const __nv_bfloat16* src = ((t & 1) ? Klo : Khi)
                + (rowBase + (size_t)kt * 64 + r) * D_EMB + colH + (t >> 1) * 64 + ch * 8;
            cp16(stb + t * QK_TILE + r * PQB + ch * 16, src);
        }
#pragma unroll
        for (int it = 0; it < 8; it++) {
            int idx = tid + 256 * it;
            int ch = idx & 15, r = (idx >> 4) & 63, t = idx >> 10;
            const __nv_bfloat16* src = (t ? Vlo : Vhi)
                + (rowBase + (size_t)kt * 64 + r) * D_EMB + colH + ch * 8;
            cp16(stb + 4 * QK_TILE + t * V_TILE + r * PVB + ch * 16, src);
        }
        asm volatile("cp.async.commit_group;");
    };

    float o[16][4];
#pragma unroll
    for (int i = 0; i < 16; i++)
#pragma unroll
        for (int j = 0; j < 4; j++) o[i][j] = 0.f;
    float m_a = -1e30f, m_b = -1e30f, l_a = 0.f, l_b = 0.f;

    load_kv(0);

    for (int kt = 0; kt <= qt; kt++) {
        if (kt < qt) {
            load_kv(kt + 1);
            asm volatile("cp.async.wait_group 1;");
        } else {
            asm volatile("cp.async.wait_group 0;");
        }
        __syncthreads();

        const uint32_t stb = sbase + FOFF_S0 + (kt & 1) * FSTG;

        float sc[8][4];
#pragma unroll
        for (int i = 0; i < 8; i++)
#pragma unroll
            for (int j = 0; j < 4; j++) sc[i][j] = 0.f;

        const uint32_t kbh = stb + (br * 2) * QK_TILE;
        const uint32_t koff = (uint32_t)(lane & 7) * PQB + ((lane >> 3) << 4);
#pragma unroll
        for (int nt = 0; nt < 8; nt++) {
            uint32_t a = koff + (uint32_t)nt * 8 * PQB;
            uint32_t kh0[4], kh1[4], kl0[4], kl1[4];
            ldmx4(kh0, kbh + a);
            ldmx4(kh1, kbh + a + 64);
            ldmx4(kl0, kbh + QK_TILE + a);
            ldmx4(kl1, kbh + QK_TILE + a + 64);
            mma_bf16(sc[nt], qh[0], &kh0[0]);
            mma_bf16(sc[nt], ql[0], &kh0[0]);
            mma_bf16(sc[nt], qh[0], &kl0[0]);
            mma_bf16(sc[nt], qh[1], &kh0[2]);
            mma_bf16(sc[nt], ql[1], &kh0[2]);
            mma_bf16(sc[nt], qh[1], &kl0[2]);
            mma_bf16(sc[nt], qh[2], &kh1[0]);
            mma_bf16(sc[nt], ql[2], &kh1[0]);
            mma_bf16(sc[nt], qh[2], &kl1[0]);
            mma_bf16(sc[nt], qh[3], &kh1[2]);
            mma_bf16(sc[nt], ql[3], &kh1[2]);
            mma_bf16(sc[nt], qh[3], &kl1[2]);
        }

        const bool diag = (kt == qt);
        float mxa = -1e30f, mxb = -1e30f;
#pragma unroll
        for (int nt = 0; nt < 8; nt++) {
            int c0 = nt * 8 + 2 * tg;
#pragma unroll
            for (int e = 0; e < 4; e++) {
                int row = rbase + g + ((e >> 1) << 3);
                int col = c0 + (e & 1);
                float v = sc[nt][e] * SCALE_LOG2;
                if (diag && col > row) v = -1e30f;
                sc[nt][e] = v;
            }
            mxa = fmaxf(mxa, fmaxf(sc[nt][0], sc[nt][1]));
            mxb = fmaxf(mxb, fmaxf(sc[nt][2], sc[nt][3]));
        }
        mxa = fmaxf(mxa, __shfl_xor_sync(0xffffffffu, mxa, 1));
        mxa = fmaxf(mxa, __shfl_xor_sync(0xffffffffu, mxa, 2));
        mxb = fmaxf(mxb, __shfl_xor_sync(0xffffffffu, mxb, 1));
        mxb = fmaxf(mxb, __shfl_xor_sync(0xffffffffu, mxb, 2));
        float mna = fmaxf(m_a, mxa), mnb = fmaxf(m_b, mxb);
        float alf_a = fexp2(m_a - mna), alf_b = fexp2(m_b - mnb);
        m_a = mna; m_b = mnb;

        float suma = 0.f, sumb = 0.f;
        uint32_t ph[4][4], pl[4][4];
#pragma unroll
        for (int s2 = 0; s2 < 4; s2++) {
#pragma unroll
            for (int hf = 0; hf < 2; hf++) {
                int nt = 2 * s2 + hf;
                float p0 = fexp2(sc[nt][0] - m_a);
                float p1 = fexp2(sc[nt][1] - m_a);
                float p2 = fexp2(sc[nt][2] - m_b);
                float p3 = fexp2(sc[nt][3] - m_b);
                suma += p0 + p1; sumb += p2 + p3;
                __nv_bfloat16 h0 = __float2bfloat16(p0);
                __nv_bfloat16 h1 = __float2bfloat16(p1);
                __nv_bfloat16 h2 = __float2bfloat16(p2);
                __nv_bfloat16 h3 = __float2bfloat16(p3);
                __nv_bfloat162 t01 = __halves2bfloat162(h0, h1);
                __nv_bfloat162 t23 = __halves2bfloat162(h2, h3);
                ph[s2][hf * 2 + 0] = *(uint32_t*)&t01;
                ph[s2][hf * 2 + 1] = *(uint32_t*)&t23;
                pl[s2][hf * 2 + 0] = pack_bf16(p0 - __bfloat162float(h0),
                                               p1 - __bfloat162float(h1));
                pl[s2][hf * 2 + 1] = pack_bf16(p2 - __bfloat162float(h2),
                                               p3 - __bfloat162float(h3));
            }
        }
        suma += __shfl_xor_sync(0xffffffffu, suma, 1);
        suma += __shfl_xor_sync(0xffffffffu, suma, 2);
        sumb += __shfl_xor_sync(0xffffffffu, sumb, 1);
        sumb += __shfl_xor_sync(0xffffffffu, sumb, 2);
        l_a = alf_a * l_a + suma;
        l_b = alf_b * l_b + sumb;

#pragma unroll
        for (int vt = 0; vt < 16; vt++) {
            o[vt][0] *= alf_a; o[vt][1] *= alf_a;
            o[vt][2] *= alf_b; o[vt][3] *= alf_b;
        }

        const uint32_t vb = stb + 4 * QK_TILE;
        const uint32_t vrow4 = (uint32_t)(lane & 15) * PVB + ((lane >> 4) << 4);
#pragma unroll
        for (int vt2 = 0; vt2 < 8; vt2++) {
#pragma unroll
            for (int s2 = 0; s2 < 4; s2++) {
                uint32_t addr = (uint32_t)(s2 * 16) * PVB + vrow4 + vt2 * 32;
                uint32_t bh4[4], bl4[4];
                ldmx4t(bh4, vb + addr);
                ldmx4t(bl4, vb + V_TILE + addr);
                mma_bf16(o[2 * vt2],     ph[s2], &bh4[0]);
                mma_bf16(o[2 * vt2],     pl[s2], &bh4[0]);
                mma_bf16(o[2 * vt2],     ph[s2], &bl4[0]);
                mma_bf16(o[2 * vt2 + 1], ph[s2], &bh4[2]);
                mma_bf16(o[2 * vt2 + 1], pl[s2], &bh4[2]);
                mma_bf16(o[2 * vt2 + 1], ph[s2], &bl4[2]);
            }
        }
        __syncthreads();
    }

    float lam = sLam[0];
    float ra = 1.0f / l_a, rb = 1.0f / l_b;

    if (br == 0) {
#pragma unroll
        for (int vt = 0; vt < 16; vt++) {
            int c = vt * 8 + 2 * tg;
            *(float2*)&sOut[(rbase + g) * 128 + c] = make_float2(o[vt][0] * ra, o[vt][1] * ra);
            *(float2*)&sOut[(rbase + g + 8) * 128 + c] = make_float2(o[vt][2] * rb, o[vt][3] * rb);
        }
    }
    __syncthreads();
    if (br == 1) {
#pragma unroll
        for (int vt = 0; vt < 16; vt++) {
            int c = vt * 8 + 2 * tg;
            float2* p0 = (float2*)&sOut[(rbase + g) * 128 + c];
            float2 v0 = *p0;
            v0.x -= lam * o[vt][0] * ra; v0.y -= lam * o[vt][1] * ra;
            *p0 = v0;
            float2* p1 = (float2*)&sOut[(rbase + g + 8) * 128 + c];
            float2 v1 = *p1;
            v1.x -= lam * o[vt][2] * rb; v1.y -= lam * o[vt][3] * rb;
            *p1 = v1;
        }
    }
    __syncthreads();

    {
        int r = tid >> 2;
        int q4 = tid & 3;
        float ss = 0.f;
#pragma unroll
        for (int u = 0; u < 32; u++) {
            float v = sOut[r * 128 + q4 * 32 + u];
            ss += v * v;
        }
        ss += __shfl_xor_sync(0xffffffffu, ss, 1);
        ss += __shfl_xor_sync(0xffffffffu, ss, 2);
        float rn = rsqrtf(ss * (1.0f / 128.0f) + 1e-8f);
        size_t outrow = (rowBase + q0t + r) * D_EMB + colH;
#pragma unroll
        for (int u = 0; u < 32; u += 2) {
            int e = q4 * 32 + u;
            float v0 = (sOut[r * 128 + e] * rn * lnw[e] + lnb[e]) * ONE_MINUS_LI_F;
            float v1 = (sOut[r * 128 + e + 1] * rn * lnw[e + 1] + lnb[e + 1]) * ONE_MINUS_LI_F;
            uint32_t hw, lw;
            split2(v0, v1, hw, lw);
            *(uint32_t*)&Ahi[outrow + e] = hw;
            *(uint32_t*)&Alo[outrow + e] = lw;
        }
    }
}

// ---------------- launch ---------------------------------------------------
extern "C" void kernel_launch(void* const* d_in, const int* in_sizes, int n_in,
                              void* d_out, int out_size)
{
    (void)in_sizes; (void)n_in; (void)out_size;
    const float* x   = (const float*)d_in[0];
    const float* Wq  = (const float*)d_in[1];
    const float* Wk  = (const float*)d_in[2];
    const float* Wv  = (const float*)d_in[3];
    const float* Wo  = (const float*)d_in[4];
    const float* lq1 = (const float*)d_in[5];
    const float* lk1 = (const float*)d_in[6];
    const float* lq2 = (const float*)d_in[7];
    const float* lk2 = (const float*)d_in[8];
    const float* lnw = (const float*)d_in[9];
    const float* lnb = (const float*)d_in[10];
    float* out = (float*)d_out;

    __nv_bfloat16 *xhi, *xlo, *whi, *wlo, *ahi, *alo;
    __nv_bfloat16 *qhi, *qlo, *khi, *klo, *vhi, *vlo;
    cudaGetSymbolAddress((void**)&xhi, g_xhi);
    cudaGetSymbolAddress((void**)&xlo, g_xlo);
    cudaGetSymbolAddress((void**)&whi, g_whi);
    cudaGetSymbolAddress((void**)&wlo, g_wlo);
    cudaGetSymbolAddress((void**)&ahi, g_ahi);
    cudaGetSymbolAddress((void**)&alo, g_alo);
    cudaGetSymbolAddress((void**)&qhi, g_Qhi);
    cudaGetSymbolAddress((void**)&qlo, g_Qlo);
    cudaGetSymbolAddress((void**)&khi, g_Khi);
    cudaGetSymbolAddress((void**)&klo, g_Klo);
    cudaGetSymbolAddress((void**)&vhi, g_Vhi);
    cudaGetSymbolAddress((void**)&vlo, g_Vlo);

    const int nx4 = (MROWS * D_EMB) / 4;
    const int nw4 = (D_EMB * D_EMB) / 4;

    dim3 wsg((nw4 + 255) / 256, 4);
    wsplit_all_kernel<<<wsg, 256>>>(Wq, Wk, Wv, Wo, whi, wlo);
    split_kernel<<<(nx4 + 255) / 256, 256>>>(x, xhi, xlo, nx4);

    cudaFuncSetAttribute(gemm_bf16x3<0>, cudaFuncAttributeMaxDynamicSharedMemorySize, G_SMEM);
    cudaFuncSetAttribute(gemm_bf16x3<1>, cudaFuncAttributeMaxDynamicSharedMemorySize, G_SMEM);

    // fused QKV projection + rope + split epilogue (1D grid, grouped raster)
    gemm_bf16x3<1><<<(NQKV / 128) * (MROWS / 128), 256, G_SMEM>>>(
        xhi, xlo, whi, wlo, nullptr, MROWS, NQKV, D_EMB, WCOLS, 0);

    cudaFuncSetAttribute(flash_mma_kernel, cudaFuncAttributeMaxDynamicSharedMemorySize, FL_SMEM);
    flash_mma_kernel<<<dim3(32, NHEAD, BATCH), 256, FL_SMEM>>>(
        qhi, qlo, khi, klo, vhi, vlo, lq1, lk1, lq2, lk2, lnw, lnb, ahi, alo);

    // output projection (1D grid, grouped raster)
    gemm_bf16x3<0><<<(D_EMB / 128) * (MROWS / 128), 256, G_SMEM>>>(
        ahi, alo, whi + 6144, wlo + 6144, out, MROWS, D_EMB, D_EMB, WCOLS, D_EMB);
}

// round 12
// speedup vs baseline: 1.0035x; 1.0035x over previous
#include <cuda_runtime.h>
#include <cuda_bf16.h>
#include <cstdint>
#include <cstddef>

#define S_LEN 2048
#define D_EMB 2048
#define NHEAD 16
#define HDIM 64
#define DVDIM 128
#define BATCH 2
#define MROWS (BATCH * S_LEN)   // 4096
#define NQKV 6144
#define WCOLS 8192

#define LAMBDA_INIT_F 0.78360576653162435f
#define ONE_MINUS_LI_F 0.21639423346837565f
#define LN1E4_OVER_32 (9.210340371976184f / 32.0f)
#define SCALE_LOG2 0.18033688011112042f   // 0.125 * log2(e)

// ---------------- scratch (device globals) -------------------------------
__device__ float2 g_rope[S_LEN * 32];          // [s][j] -> (cos, sin)

__device__ __nv_bfloat16 g_xhi[(size_t)MROWS * D_EMB];
__device__ __nv_bfloat16 g_xlo[(size_t)MROWS * D_EMB];
__device__ __nv_bfloat16 g_whi[(size_t)D_EMB * WCOLS];   // [K, Wq|Wk|Wv|Wo]
__device__ __nv_bfloat16 g_wlo[(size_t)D_EMB * WCOLS];
__device__ __nv_bfloat16 g_ahi[(size_t)MROWS * D_EMB];
__device__ __nv_bfloat16 g_alo[(size_t)MROWS * D_EMB];

__device__ __nv_bfloat16 g_Qhi[(size_t)MROWS * D_EMB];
__device__ __nv_bfloat16 g_Qlo[(size_t)MROWS * D_EMB];
__device__ __nv_bfloat16 g_Khi[(size_t)MROWS * D_EMB];
__device__ __nv_bfloat16 g_Klo[(size_t)MROWS * D_EMB];
__device__ __nv_bfloat16 g_Vhi[(size_t)MROWS * D_EMB];
__device__ __nv_bfloat16 g_Vlo[(size_t)MROWS * D_EMB];

// ---------------- common PTX helpers --------------------------------------
__device__ __forceinline__ uint32_t smem_u32(const void* p) {
    return (uint32_t)__cvta_generic_to_shared(p);
}
__device__ __forceinline__ void cp16(uint32_t s, const void* g) {
    asm volatile("cp.async.ca.shared.global [%0], [%1], 16;" :: "r"(s), "l"(g));
}
__device__ __forceinline__ void cp16cg(uint32_t s, const void* g) {
    asm volatile("cp.async.cg.shared.global [%0], [%1], 16;" :: "r"(s), "l"(g));
}
__device__ __forceinline__ void ldmx4(uint32_t r[4], uint32_t addr) {
    asm volatile("ldmatrix.sync.aligned.m8n8.x4.shared.b16 {%0,%1,%2,%3}, [%4];"
        : "=r"(r[0]), "=r"(r[1]), "=r"(r[2]), "=r"(r[3]) : "r"(addr));
}
__device__ __forceinline__ void ldmx4t(uint32_t r[4], uint32_t addr) {
    asm volatile("ldmatrix.sync.aligned.m8n8.x4.trans.shared.b16 {%0,%1,%2,%3}, [%4];"
        : "=r"(r[0]), "=r"(r[1]), "=r"(r[2]), "=r"(r[3]) : "r"(addr));
}
__device__ __forceinline__ void mma_bf16(float c[4], const uint32_t a[4], const uint32_t b[2]) {
    asm volatile("mma.sync.aligned.m16n8k16.row.col.f32.bf16.bf16.f32 "
        "{%0,%1,%2,%3}, {%4,%5,%6,%7}, {%8,%9}, {%0,%1,%2,%3};"
        : "+f"(c[0]), "+f"(c[1]), "+f"(c[2]), "+f"(c[3])
        : "r"(a[0]), "r"(a[1]), "r"(a[2]), "r"(a[3]), "r"(b[0]), "r"(b[1]));
}
__device__ __forceinline__ uint32_t pack_bf16(float lo, float hi) {
    uint32_t r;
    asm("cvt.rn.bf16x2.f32 %0, %1, %2;" : "=r"(r) : "f"(hi), "f"(lo));
    return r;
}
__device__ __forceinline__ float fexp2(float x) {
    float r;
    asm("ex2.approx.f32 %0, %1;" : "=f"(r) : "f"(x));
    return r;
}
__device__ __forceinline__ void split2(float v0, float v1, uint32_t& hw, uint32_t& lw) {
    __nv_bfloat16 h0 = __float2bfloat16(v0);
    __nv_bfloat16 h1 = __float2bfloat16(v1);
    __nv_bfloat162 hh = __halves2bfloat162(h0, h1);
    hw = *(uint32_t*)&hh;
    lw = pack_bf16(v0 - __bfloat162float(h0), v1 - __bfloat162float(h1));
}

// =================== fp32 -> (bf16 hi, bf16 lo) split ====================
__global__ void split_kernel(const float* __restrict__ in,
                             __nv_bfloat16* __restrict__ hi,
                             __nv_bfloat16* __restrict__ lo, int n4)
{
    int i = blockIdx.x * blockDim.x + threadIdx.x;
    if (i >= n4) return;
    float4 v = ((const float4*)in)[i];
    uint32_t h0, l0, h1, l1;
    split2(v.x, v.y, h0, l0);
    split2(v.z, v.w, h1, l1);
    ((uint32_t*)hi)[2 * i]     = h0;
    ((uint32_t*)hi)[2 * i + 1] = h1;
    ((uint32_t*)lo)[2 * i]     = l0;
    ((uint32_t*)lo)[2 * i + 1] = l1;
}

// ===== all 4 W -> packed [2048, 8192] + split; also fills rope table =====
__global__ void wsplit_all_kernel(const float* __restrict__ W0, const float* __restrict__ W1,
                                  const float* __restrict__ W2, const float* __restrict__ W3,
                                  __nv_bfloat16* __restrict__ hi, __nv_bfloat16* __restrict__ lo)
{
    const int wsel = blockIdx.y;
    if (wsel == 0 && blockIdx.x < 256) {
        int idx = blockIdx.x * 256 + threadIdx.x;
        int s = idx >> 5, j = idx & 31;
        float inv = expf(-(float)j * LN1E4_OVER_32);
        float sn, cs;
        sincosf((float)s * inv, &sn, &cs);
        g_rope[idx] = make_float2(cs, sn);
    }
    int i = blockIdx.x * blockDim.x + threadIdx.x;
    if (i >= (D_EMB * D_EMB) / 4) return;
    const float* in = (wsel == 0) ? W0 : (wsel == 1) ? W1 : (wsel == 2) ? W2 : W3;
    int r = i >> 9;
    int c4 = (i & 511) << 2;
    float4 v = ((const float4*)in)[i];
    uint32_t h0, l0, h1, l1;
    split2(v.x, v.y, h0, l0);
    split2(v.z, v.w, h1, l1);
    size_t o = ((size_t)r * WCOLS + wsel * 2048 + c4) >> 1;
    ((uint32_t*)hi)[o]     = h0;
    ((uint32_t*)hi)[o + 1] = h1;
    ((uint32_t*)lo)[o]     = l0;
    ((uint32_t*)lo)[o + 1] = l1;
}

// =================== tensor-core GEMM (bf16 x3 split) ====================
// C[M,N] = A[M,K] * B[K,N]. 256 threads, 128x128 tile, BK=32, 3 stages,
// prefetch distance 2, 1 barrier/iter, 2 CTAs per SM. 2D grid (row raster).
#define GBK 32
#define GAP 80
#define GBP 272
#define GOFF_AL (128 * GAP)
#define GOFF_BH (2 * 128 * GAP)
#define GOFF_BL (GOFF_BH + GBK * GBP)
#define GSTAGE (GOFF_BL + GBK * GBP)
#define G_SMEM (3 * GSTAGE)

template <int MODE>
__global__ __launch_bounds__(256, 2)
void gemm_bf16x3(const __nv_bfloat16* __restrict__ Ahi, const __nv_bfloat16* __restrict__ Alo,
                 const __nv_bfloat16* __restrict__ Bhi, const __nv_bfloat16* __restrict__ Blo,
                 float* __restrict__ C, int M, int N, int K, int ldb, int ldc)
{
    extern __shared__ __align__(16) uint8_t gsm[];
    const uint32_t sbase = smem_u32(gsm);
    const int tid = threadIdx.x;
    const int lane = tid & 31;
    const int wid = tid >> 5;
    const int m0 = blockIdx.y * 128;
    const int n0 = blockIdx.x * 128;

    const int wm = wid & 3;
    const int wn = wid >> 2;

    const int KT = K / GBK;

    auto load_stage = [&](int t) {
        uint32_t st = sbase + (t % 3) * GSTAGE;
        int k0 = t * GBK;
#pragma unroll
        for (int j = 0; j < 8; j++) {
            int cid = tid + 256 * j;
            if (cid < 1024) {
                int hl = cid >> 9;
                int sub = cid & 511;
                int row = sub >> 2;
                int ch = sub & 3;
                const __nv_bfloat16* src = (hl ? Alo : Ahi)
                    + (size_t)(m0 + row) * K + k0 + ch * 8;
                cp16cg(st + (hl ? GOFF_AL : 0) + row * GAP + ch * 16, src);
            } else {
                int c2 = cid - 1024;
                int hl = c2 >> 9;
                int sub = c2 & 511;
                int row = sub >> 4;
                int ch = sub & 15;
                const __nv_bfloat16* src = (hl ? Blo : Bhi)
                    + (size_t)(k0 + row) * ldb + n0 + ch * 8;
                cp16cg(st + (hl ? GOFF_BL : GOFF_BH) + row * GBP + ch * 16, src);
            }
        }
        asm volatile("cp.async.commit_group;");
    };

    load_stage(0);
    load_stage(1);

    float acc[2][8][4];
#pragma unroll
    for (int i = 0; i < 2; i++)
#pragma unroll
        for (int j = 0; j < 8; j++)
#pragma unroll
            for (int l = 0; l < 4; l++) acc[i][j][l] = 0.f;

    const uint32_t aoff = (uint32_t)(wm * 32 + (lane & 15)) * GAP + ((lane >> 4) & 1) * 16;
    const uint32_t boff = (uint32_t)(lane & 15) * GBP + (uint32_t)wn * 128
                        + ((lane >> 4) & 1) * 16;

    for (int t = 0; t < KT; t++) {
        if (t + 1 < KT) asm volatile("cp.async.wait_group 1;");
        else            asm volatile("cp.async.wait_group 0;");
        __syncthreads();
        if (t + 2 < KT) load_stage(t + 2);

        uint32_t st = sbase + (t % 3) * GSTAGE;
#pragma unroll
        for (int kk = 0; kk < 2; kk++) {
            uint32_t ah[2][4], al[2][4];
            ldmx4(ah[0], st + aoff + kk * 32);
            ldmx4(ah[1], st + aoff + 16 * GAP + kk * 32);
            ldmx4(al[0], st + GOFF_AL + aoff + kk * 32);
            ldmx4(al[1], st + GOFF_AL + aoff + 16 * GAP + kk * 32);
            uint32_t bb = st + boff + (uint32_t)kk * 16 * GBP;
#pragma unroll
            for (int half = 0; half < 2; half++) {
                uint32_t bh[8], bl[8];
                ldmx4t(&bh[0], bb + GOFF_BH + half * 64);
                ldmx4t(&bh[4], bb + GOFF_BH + half * 64 + 32);
                ldmx4t(&bl[0], bb + GOFF_BL + half * 64);
                ldmx4t(&bl[4], bb + GOFF_BL + half * 64 + 32);
#pragma unroll
                for (int mt = 0; mt < 2; mt++)
#pragma unroll
                    for (int nt = 0; nt < 4; nt++) {
                        int ng = half * 4 + nt;
                        mma_bf16(acc[mt][ng], ah[mt], &bh[nt * 2]);
                        mma_bf16(acc[mt][ng], al[mt], &bh[nt * 2]);
                        mma_bf16(acc[mt][ng], ah[mt], &bl[nt * 2]);
                    }
            }
        }
    }

    // epilogue
    const int gid = lane >> 2, tig = lane & 3;
    if (MODE == 0) {
#pragma unroll
        for (int mt = 0; mt < 2; mt++) {
            int row = m0 + wm * 32 + mt * 16 + gid;
#pragma unroll
            for (int nt = 0; nt < 8; nt++) {
                int col = n0 + wn * 64 + nt * 8 + 2 * tig;
                *(float2*)&C[(size_t)row * ldc + col] = make_float2(acc[mt][nt][0], acc[mt][nt][1]);
                *(float2*)&C[(size_t)(row + 8) * ldc + col] = make_float2(acc[mt][nt][2], acc[mt][nt][3]);
            }
        }
    } else {
        const int region = n0 >> 11;    // 0=Q, 1=K, 2=V
        __nv_bfloat16* dh = (region == 0) ? g_Qhi : (region == 1) ? g_Khi : g_Vhi;
        __nv_bfloat16* dl = (region == 0) ? g_Qlo : (region == 1) ? g_Klo : g_Vlo;
#pragma unroll
        for (int mt = 0; mt < 2; mt++) {
#pragma unroll
            for (int nt = 0; nt < 8; nt++) {
                int col = n0 + wn * 64 + nt * 8 + 2 * tig;
                int cl = col & 2047;
                int j = (cl & 63) >> 1;
#pragma unroll
                for (int rr = 0; rr < 2; rr++) {
                    int row = m0 + wm * 32 + mt * 16 + gid + rr * 8;
                    float v0 = acc[mt][nt][rr * 2 + 0];
                    float v1 = acc[mt][nt][rr * 2 + 1];
                    if (region < 2) {
                        int s = row & (S_LEN - 1);
                        float2 t = g_rope[(s << 5) + j];
                        float f0 = v0 * t.x - v1 * t.y;
                        float f1 = v1 * t.x + v0 * t.y;
                        v0 = f0; v1 = f1;
                    }
                    uint32_t hw, lw;
                    split2(v0, v1, hw, lw);
                    size_t o = ((size_t)row * D_EMB + cl) >> 1;
                    ((uint32_t*)dh)[o] = hw;
                    ((uint32_t*)dl)[o] = lw;
                }
            }
        }
    }
}

// ====== MMA dual-branch flash attention (pipelined QK ahead of softmax) ====
#define PQB 144
#define PVB 272
#define QK_TILE (64 * PQB)              // 9216
#define V_TILE  (64 * PVB)              // 17408
#define FOFF_Q 0
#define FSTG (4 * QK_TILE + 2 * V_TILE) // 71680
#define FOFF_S0 (4 * QK_TILE)           // 36864
#define FOFF_LAM (FOFF_S0 + 2 * FSTG)   // 180224
#define FL_SMEM (FOFF_LAM + 16)

__global__ __launch_bounds__(256, 1)
void flash_mma_kernel(const __nv_bfloat16* __restrict__ Qhi, const __nv_bfloat16* __restrict__ Qlo,
                      const __nv_bfloat16* __restrict__ Khi, const __nv_bfloat16* __restrict__ Klo,
                      const __nv_bfloat16* __restrict__ Vhi, const __nv_bfloat16* __restrict__ Vlo,
                      const float* __restrict__ lq1, const float* __restrict__ lk1,
                      const float* __restrict__ lq2, const float* __restrict__ lk2,
                      const float* __restrict__ lnw, const float* __restrict__ lnb,
                      __nv_bfloat16* __restrict__ Ahi, __nv_bfloat16* __restrict__ Alo)
{
    extern __shared__ __align__(16) uint8_t smraw[];
    const uint32_t sbase = smem_u32(smraw);
    float* sOut = (float*)smraw;
    float* sLam = (float*)(smraw + FOFF_LAM);

    const int tid = threadIdx.x;
    const int lane = tid & 31;
    const int wid = tid >> 5;
    const int br = wid >> 2;
    const int rbase = (wid & 3) * 16;
    const int g = lane >> 2;
    const int tg = lane & 3;

    const int qt = (int)gridDim.x - 1 - (int)blockIdx.x;
    const int h = blockIdx.y;
    const int b = blockIdx.z;
    const int q0t = qt * 64;
    const size_t rowBase = (size_t)b * S_LEN;
    const int colH = h * 128;

    if (wid == 0) {
        float d1 = lq1[lane] * lk1[lane] + lq1[lane + 32] * lk1[lane + 32];
        float d2 = lq2[lane] * lk2[lane] + lq2[lane + 32] * lk2[lane + 32];
#pragma unroll
        for (int ofs = 16; ofs > 0; ofs >>= 1) {
            d1 += __shfl_xor_sync(0xffffffffu, d1, ofs);
            d2 += __shfl_xor_sync(0xffffffffu, d2, ofs);
        }
        if (lane == 0) sLam[0] = expf(d1) - expf(d2) + LAMBDA_INIT_F;
    }

    // ---- Q tiles ----
#pragma unroll
    for (int it = 0; it < 8; it++) {
        int idx = tid + 256 * it;
        int ch = idx & 7, r = (idx >> 3) & 63, t = idx >> 9;
        const __nv_bfloat16* src = ((t & 1) ? Qlo : Qhi)
            + (rowBase + q0t + r) * D_EMB + colH + (t >> 1) * 64 + ch * 8;
        cp16(sbase + FOFF_Q + t * QK_TILE + r * PQB + ch * 16, src);
    }
    asm volatile("cp.async.commit_group;");

    auto load_kv = [&](int kt) {
        uint32_t stb = sbase + FOFF_S0 + (kt & 1) * FSTG;
#pragma unroll
        for (int it = 0; it < 8; it++) {
            int idx = tid + 256 * it;
            int ch = idx & 7, r = (idx >> 3) & 63, t = idx >> 9;
            const __nv_bfloat16* src = ((t & 1) ? Klo : Khi)
                + (rowBase + (size_t)kt * 64 + r) * D_EMB + colH + (t >> 1) * 64 + ch * 8;
            cp16(stb + t * QK_TILE + r * PQB + ch * 16, src);
        }
#pragma unroll
        for (int it = 0; it < 8; it++) {
            int idx = tid + 256 * it;
            int ch = idx & 15, r = (idx >> 4) & 63, t = idx >> 10;
            const __nv_bfloat16* src = (t ? Vlo : Vhi)
                + (rowBase + (size_t)kt * 64 + r) * D_EMB + colH + ch * 8;
            cp16(stb + 4 * QK_TILE + t * V_TILE + r * PVB + ch * 16, src);
        }
        asm volatile("cp.async.commit_group;");
    };

    // QK phase: compute scores for tile kt into scv (loads Q frags from smem)
    const uint32_t qoff = (uint32_t)(rbase + (lane & 15)) * PQB + ((lane >> 4) << 4);
    const uint32_t qb = sbase + FOFF_Q + (br * 2) * QK_TILE;
    const uint32_t koff = (uint32_t)(lane & 7) * PQB + ((lane >> 3) << 4);

    auto qk_phase = [&](int kt, float scv[8][4]) {
        const uint32_t kbh = sbase + FOFF_S0 + (kt & 1) * FSTG + (br * 2) * QK_TILE;
        uint32_t qh[4][4], ql[4][4];
#pragma unroll
        for (int s = 0; s < 4; s++) {
            ldmx4(qh[s], qb + qoff + s * 32);
            ldmx4(ql[s], qb + QK_TILE + qoff + s * 32);
        }
#pragma unroll
        for (int i = 0; i < 8; i++)
#pragma unroll
            for (int j = 0; j < 4; j++) scv[i][j] = 0.f;
#pragma unroll
        for (int nt = 0; nt < 8; nt++) {
            uint32_t a = koff + (uint32_t)nt * 8 * PQB;
            uint32_t kh0[4], kh1[4], kl0[4], kl1[4];
            ldmx4(kh0, kbh + a);
            ldmx4(kh1, kbh + a + 64);
            ldmx4(kl0, kbh + QK_TILE + a);
            ldmx4(kl1, kbh + QK_TILE + a + 64);
            mma_bf16(scv[nt], qh[0], &kh0[0]);
            mma_bf16(scv[nt], ql[0], &kh0[0]);
            mma_bf16(scv[nt], qh[0], &kl0[0]);
            mma_bf16(scv[nt], qh[1], &kh0[2]);
            mma_bf16(scv[nt], ql[1], &kh0[2]);
            mma_bf16(scv[nt], qh[1], &kl0[2]);
            mma_bf16(scv[nt], qh[2], &kh1[0]);
            mma_bf16(scv[nt], ql[2], &kh1[0]);
            mma_bf16(scv[nt], qh[2], &kl1[0]);
            mma_bf16(scv[nt], qh[3], &kh1[2]);
            mma_bf16(scv[nt], ql[3], &kh1[2]);
            mma_bf16(scv[nt], qh[3], &kl1[2]);
        }
    };

    float o[16][4];
#pragma unroll
    for (int i = 0; i < 16; i++)
#pragma unroll
        for (int j = 0; j < 4; j++) o[i][j] = 0.f;
    float m_a = -1e30f, m_b = -1e30f, l_a = 0.f, l_b = 0.f;

    // prologue: load KV(0), KV(1); compute QK(0)
    load_kv(0);
    if (qt >= 1) {
        load_kv(1);
        asm volatile("cp.async.wait_group 1;");
    } else {
        asm volatile("cp.async.wait_group 0;");
    }
    __syncthreads();

    float sc[8][4];
    qk_phase(0, sc);

    for (int kt = 0; kt <= qt; kt++) {
        float scn[8][4];
        const bool haveNext = (kt < qt);
        if (haveNext) {
            asm volatile("cp.async.wait_group 0;");
            __syncthreads();
            qk_phase(kt + 1, scn);   // tensor pipe busy during softmax below
        }

        // ---- softmax on sc (log2 domain) ----
        const bool diag = (kt == qt);
        float mxa = -1e30f, mxb = -1e30f;
#pragma unroll
        for (int nt = 0; nt < 8; nt++) {
            int c0 = nt * 8 + 2 * tg;
#pragma unroll
            for (int e = 0; e < 4; e++) {
                int row = rbase + g + ((e >> 1) << 3);
                int col = c0 + (e & 1);
                float v = sc[nt][e] * SCALE_LOG2;
                if (diag && col > row) v = -1e30f;
                sc[nt][e] = v;
            }
            mxa = fmaxf(mxa, fmaxf(sc[nt][0], sc[nt][1]));
            mxb = fmaxf(mxb, fmaxf(sc[nt][2], sc[nt][3]));
        }
        mxa = fmaxf(mxa, __shfl_xor_sync(0xffffffffu, mxa, 1));
        mxa = fmaxf(mxa, __shfl_xor_sync(0xffffffffu, mxa, 2));
        mxb = fmaxf(mxb, __shfl_xor_sync(0xffffffffu, mxb, 1));
        mxb = fmaxf(mxb, __shfl_xor_sync(0xffffffffu, mxb, 2));
        float mna = fmaxf(m_a, mxa), mnb = fmaxf(m_b, mxb);
        float alf_a = fexp2(m_a - mna), alf_b = fexp2(m_b - mnb);
        m_a = mna; m_b = mnb;

        float suma = 0.f, sumb = 0.f;
        uint32_t ph[4][4], pl[4][4];
#pragma unroll
        for (int s2 = 0; s2 < 4; s2++) {
#pragma unroll
            for (int hf = 0; hf < 2; hf++) {
                int nt = 2 * s2 + hf;
                float p0 = fexp2(sc[nt][0] - m_a);
                float p1 = fexp2(sc[nt][1] - m_a);
                float p2 = fexp2(sc[nt][2] - m_b);
                float p3 = fexp2(sc[nt][3] - m_b);
                suma += p0 + p1; sumb += p2 + p3;
                __nv_bfloat16 h0 = __float2bfloat16(p0);
                __nv_bfloat16 h1 = __float2bfloat16(p1);
                __nv_bfloat16 h2 = __float2bfloat16(p2);
                __nv_bfloat16 h3 = __float2bfloat16(p3);
                __nv_bfloat162 t01 = __halves2bfloat162(h0, h1);
                __nv_bfloat162 t23 = __halves2bfloat162(h2, h3);
                ph[s2][hf * 2 + 0] = *(uint32_t*)&t01;
                ph[s2][hf * 2 + 1] = *(uint32_t*)&t23;
                pl[s2][hf * 2 + 0] = pack_bf16(p0 - __bfloat162float(h0),
                                               p1 - __bfloat162float(h1));
                pl[s2][hf * 2 + 1] = pack_bf16(p2 - __bfloat162float(h2),
                                               p3 - __bfloat162float(h3));
            }
        }
        suma += __shfl_xor_sync(0xffffffffu, suma, 1);
        suma += __shfl_xor_sync(0xffffffffu, suma, 2);
        sumb += __shfl_xor_sync(0xffffffffu, sumb, 1);
        sumb += __shfl_xor_sync(0xffffffffu, sumb, 2);
        l_a = alf_a * l_a + suma;
        l_b = alf_b * l_b + sumb;

#pragma unroll
        for (int vt = 0; vt < 16; vt++) {
            o[vt][0] *= alf_a; o[vt][1] *= alf_a;
            o[vt][2] *= alf_b; o[vt][3] *= alf_b;
        }

        // ---- PV(kt) ----
        const uint32_t vb = sbase + FOFF_S0 + (kt & 1) * FSTG + 4 * QK_TILE;
        const uint32_t vrow4 = (uint32_t)(lane & 15) * PVB + ((lane >> 4) << 4);
#pragma unroll
        for (int vt2 = 0; vt2 < 8; vt2++) {
#pragma unroll
            for (int s2 = 0; s2 < 4; s2++) {
                uint32_t addr = (uint32_t)(s2 * 16) * PVB + vrow4 + vt2 * 32;
                uint32_t bh4[4], bl4[4];
                ldmx4t(bh4, vb + addr);
                ldmx4t(bl4, vb + V_TILE + addr);
                mma_bf16(o[2 * vt2],     ph[s2], &bh4[0]);
                mma_bf16(o[2 * vt2],     pl[s2], &bh4[0]);
                mma_bf16(o[2 * vt2],     ph[s2], &bl4[0]);
                mma_bf16(o[2 * vt2 + 1], ph[s2], &bh4[2]);
                mma_bf16(o[2 * vt2 + 1], pl[s2], &bh4[2]);
                mma_bf16(o[2 * vt2 + 1], ph[s2], &bl4[2]);
            }
        }
        __syncthreads();   // buffer kt fully consumed by all warps
        if (kt + 2 <= qt) load_kv(kt + 2);

        if (haveNext) {
#pragma unroll
            for (int i = 0; i < 8; i++)
#pragma unroll
                for (int j = 0; j < 4; j++) sc[i][j] = scn[i][j];
        }
    }

    float lam = sLam[0];
    float ra = 1.0f / l_a, rb = 1.0f / l_b;

    if (br == 0) {
#pragma unroll
        for (int vt = 0; vt < 16; vt++) {
            int c = vt * 8 + 2 * tg;
            *(float2*)&sOut[(rbase + g) * 128 + c] = make_float2(o[vt][0] * ra, o[vt][1] * ra);
            *(float2*)&sOut[(rbase + g + 8) * 128 + c] = make_float2(o[vt][2] * rb, o[vt][3] * rb);
        }
    }
    __syncthreads();
    if (br == 1) {
#pragma unroll
        for (int vt = 0; vt < 16; vt++) {
            int c = vt * 8 + 2 * tg;
            float2* p0 = (float2*)&sOut[(rbase + g) * 128 + c];
            float2 v0 = *p0;
            v0.x -= lam * o[vt][0] * ra; v0.y -= lam * o[vt][1] * ra;
            *p0 = v0;
            float2* p1 = (float2*)&sOut[(rbase + g + 8) * 128 + c];
            float2 v1 = *p1;
            v1.x -= lam * o[vt][2] * rb; v1.y -= lam * o[vt][3] * rb;
            *p1 = v1;
        }
    }
    __syncthreads();

    // ---- RMSNorm + scale + split bf16 write ----
    {
        int r = tid >> 2;
        int q4 = tid & 3;
        float ss = 0.f;
#pragma unroll
        for (int u = 0; u < 32; u++) {
            float v = sOut[r * 128 + q4 * 32 + u];
            ss += v * v;
        }
        ss += __shfl_xor_sync(0xffffffffu, ss, 1);
        ss += __shfl_xor_sync(0xffffffffu, ss, 2);
        float rn = rsqrtf(ss * (1.0f / 128.0f) + 1e-8f);
        size_t outrow = (rowBase + q0t + r) * D_EMB + colH;
#pragma unroll
        for (int u = 0; u < 32; u += 2) {
            int e = q4 * 32 + u;
            float v0 = (sOut[r * 128 + e] * rn * lnw[e] + lnb[e]) * ONE_MINUS_LI_F;
            float v1 = (sOut[r * 128 + e + 1] * rn * lnw[e + 1] + lnb[e + 1]) * ONE_MINUS_LI_F;
            uint32_t hw, lw;
            split2(v0, v1, hw, lw);
            *(uint32_t*)&Ahi[outrow + e] = hw;
            *(uint32_t*)&Alo[outrow + e] = lw;
        }
    }
}

// ---------------- launch ---------------------------------------------------
extern "C" void kernel_launch(void* const* d_in, const int* in_sizes, int n_in,
                              void* d_out, int out_size)
{
    (void)in_sizes; (void)n_in; (void)out_size;
    const float* x   = (const float*)d_in[0];
    const float* Wq  = (const float*)d_in[1];
    const float* Wk  = (const float*)d_in[2];
    const float* Wv  = (const float*)d_in[3];
    const float* Wo  = (const float*)d_in[4];
    const float* lq1 = (const float*)d_in[5];
    const float* lk1 = (const float*)d_in[6];
    const float* lq2 = (const float*)d_in[7];
    const float* lk2 = (const float*)d_in[8];
    const float* lnw = (const float*)d_in[9];
    const float* lnb = (const float*)d_in[10];
    float* out = (float*)d_out;

    __nv_bfloat16 *xhi, *xlo, *whi, *wlo, *ahi, *alo;
    __nv_bfloat16 *qhi, *qlo, *khi, *klo, *vhi, *vlo;
    cudaGetSymbolAddress((void**)&xhi, g_xhi);
    cudaGetSymbolAddress((void**)&xlo, g_xlo);
    cudaGetSymbolAddress((void**)&whi, g_whi);
    cudaGetSymbolAddress((void**)&wlo, g_wlo);
    cudaGetSymbolAddress((void**)&ahi, g_ahi);
    cudaGetSymbolAddress((void**)&alo, g_alo);
    cudaGetSymbolAddress((void**)&qhi, g_Qhi);
    cudaGetSymbolAddress((void**)&qlo, g_Qlo);
    cudaGetSymbolAddress((void**)&khi, g_Khi);
    cudaGetSymbolAddress((void**)&klo, g_Klo);
    cudaGetSymbolAddress((void**)&vhi, g_Vhi);
    cudaGetSymbolAddress((void**)&vlo, g_Vlo);

    const int nx4 = (MROWS * D_EMB) / 4;
    const int nw4 = (D_EMB * D_EMB) / 4;

    dim3 wsg((nw4 + 255) / 256, 4);
    wsplit_all_kernel<<<wsg, 256>>>(Wq, Wk, Wv, Wo, whi, wlo);
    split_kernel<<<(nx4 + 255) / 256, 256>>>(x, xhi, xlo, nx4);

    cudaFuncSetAttribute(gemm_bf16x3<0>, cudaFuncAttributeMaxDynamicSharedMemorySize, G_SMEM);
    cudaFuncSetAttribute(gemm_bf16x3<1>, cudaFuncAttributeMaxDynamicSharedMemorySize, G_SMEM);

    // fused QKV projection + rope + split epilogue
    dim3 gqkv(NQKV / 128, MROWS / 128);   // (48, 32)
    gemm_bf16x3<1><<<gqkv, 256, G_SMEM>>>(xhi, xlo, whi, wlo, nullptr,
                                          MROWS, NQKV, D_EMB, WCOLS, 0);

    cudaFuncSetAttribute(flash_mma_kernel, cudaFuncAttributeMaxDynamicSharedMemorySize, FL_SMEM);
    flash_mma_kernel<<<dim3(32, NHEAD, BATCH), 256, FL_SMEM>>>(
        qhi, qlo, khi, klo, vhi, vlo, lq1, lk1, lq2, lk2, lnw, lnb, ahi, alo);

    // output projection
    dim3 go(D_EMB / 128, MROWS / 128);    // (16, 32)
    gemm_bf16x3<0><<<go, 256, G_SMEM>>>(ahi, alo, whi + 6144, wlo + 6144, out,
                                        MROWS, D_EMB, D_EMB, WCOLS, D_EMB);
}

// round 13
// speedup vs baseline: 1.0500x; 1.0463x over previous
#include <cuda_runtime.h>
#include <cuda_bf16.h>
#include <cuda_fp16.h>
#include <cstdint>
#include <cstddef>

#define S_LEN 2048
#define D_EMB 2048
#define NHEAD 16
#define HDIM 64
#define DVDIM 128
#define BATCH 2
#define MROWS (BATCH * S_LEN)   // 4096
#define NQKV 6144
#define WCOLS 8192

#define LAMBDA_INIT_F 0.78360576653162435f
#define ONE_MINUS_LI_F 0.21639423346837565f
#define LN1E4_OVER_32 (9.210340371976184f / 32.0f)
#define SCALE_LOG2 0.18033688011112042f   // 0.125 * log2(e)

// ---------------- scratch (device globals) -------------------------------
__device__ float2 g_rope[S_LEN * 32];          // [s][j] -> (cos, sin)

__device__ __nv_bfloat16 g_xhi[(size_t)MROWS * D_EMB];
__device__ __nv_bfloat16 g_xlo[(size_t)MROWS * D_EMB];
__device__ __nv_bfloat16 g_whi[(size_t)D_EMB * WCOLS];   // [K, Wq|Wk|Wv|Wo]
__device__ __nv_bfloat16 g_wlo[(size_t)D_EMB * WCOLS];
__device__ __nv_bfloat16 g_ahi[(size_t)MROWS * D_EMB];
__device__ __nv_bfloat16 g_alo[(size_t)MROWS * D_EMB];

// fp16 Q/K/V for flash
__device__ __half g_Qhi[(size_t)MROWS * D_EMB];
__device__ __half g_Qlo[(size_t)MROWS * D_EMB];
__device__ __half g_Khi[(size_t)MROWS * D_EMB];
__device__ __half g_Klo[(size_t)MROWS * D_EMB];
__device__ __half g_Vhi[(size_t)MROWS * D_EMB];
__device__ __half g_Vlo[(size_t)MROWS * D_EMB];

// ---------------- common PTX helpers --------------------------------------
__device__ __forceinline__ uint32_t smem_u32(const void* p) {
    return (uint32_t)__cvta_generic_to_shared(p);
}
__device__ __forceinline__ void cp16(uint32_t s, const void* g) {
    asm volatile("cp.async.ca.shared.global [%0], [%1], 16;" :: "r"(s), "l"(g));
}
__device__ __forceinline__ void cp16cg(uint32_t s, const void* g) {
    asm volatile("cp.async.cg.shared.global [%0], [%1], 16;" :: "r"(s), "l"(g));
}
__device__ __forceinline__ void ldmx4(uint32_t r[4], uint32_t addr) {
    asm volatile("ldmatrix.sync.aligned.m8n8.x4.shared.b16 {%0,%1,%2,%3}, [%4];"
        : "=r"(r[0]), "=r"(r[1]), "=r"(r[2]), "=r"(r[3]) : "r"(addr));
}
__device__ __forceinline__ void ldmx4t(uint32_t r[4], uint32_t addr) {
    asm volatile("ldmatrix.sync.aligned.m8n8.x4.trans.shared.b16 {%0,%1,%2,%3}, [%4];"
        : "=r"(r[0]), "=r"(r[1]), "=r"(r[2]), "=r"(r[3]) : "r"(addr));
}
__device__ __forceinline__ void mma_bf16(float c[4], const uint32_t a[4], const uint32_t b[2]) {
    asm volatile("mma.sync.aligned.m16n8k16.row.col.f32.bf16.bf16.f32 "
        "{%0,%1,%2,%3}, {%4,%5,%6,%7}, {%8,%9}, {%0,%1,%2,%3};"
        : "+f"(c[0]), "+f"(c[1]), "+f"(c[2]), "+f"(c[3])
        : "r"(a[0]), "r"(a[1]), "r"(a[2]), "r"(a[3]), "r"(b[0]), "r"(b[1]));
}
__device__ __forceinline__ void mma_fp16(float c[4], const uint32_t a[4], const uint32_t b[2]) {
    asm volatile("mma.sync.aligned.m16n8k16.row.col.f32.f16.f16.f32 "
        "{%0,%1,%2,%3}, {%4,%5,%6,%7}, {%8,%9}, {%0,%1,%2,%3};"
        : "+f"(c[0]), "+f"(c[1]), "+f"(c[2]), "+f"(c[3])
        : "r"(a[0]), "r"(a[1]), "r"(a[2]), "r"(a[3]), "r"(b[0]), "r"(b[1]));
}
__device__ __forceinline__ uint32_t pack_bf16(float lo, float hi) {
    uint32_t r;
    asm("cvt.rn.bf16x2.f32 %0, %1, %2;" : "=r"(r) : "f"(hi), "f"(lo));
    return r;
}
__device__ __forceinline__ uint32_t pack_f16(float lo, float hi) {
    uint32_t r;
    asm("cvt.rn.f16x2.f32 %0, %1, %2;" : "=r"(r) : "f"(hi), "f"(lo));
    return r;
}
__device__ __forceinline__ float fexp2(float x) {
    float r;
    asm("ex2.approx.f32 %0, %1;" : "=f"(r) : "f"(x));
    return r;
}
// fp32 -> bf16 hi/lo
__device__ __forceinline__ void split2(float v0, float v1, uint32_t& hw, uint32_t& lw) {
    __nv_bfloat16 h0 = __float2bfloat16(v0);
    __nv_bfloat16 h1 = __float2bfloat16(v1);
    __nv_bfloat162 hh = __halves2bfloat162(h0, h1);
    hw = *(uint32_t*)&hh;
    lw = pack_bf16(v0 - __bfloat162float(h0), v1 - __bfloat162float(h1));
}
// fp32 -> fp16 hi/lo
__device__ __forceinline__ void split2h(float v0, float v1, uint32_t& hw, uint32_t& lw) {
    __half h0 = __float2half_rn(v0);
    __half h1 = __float2half_rn(v1);
    __half2 hh = __halves2half2(h0, h1);
    hw = *(uint32_t*)&hh;
    lw = pack_f16(v0 - __half2float(h0), v1 - __half2float(h1));
}

// =================== fp32 -> (bf16 hi, bf16 lo) split ====================
__global__ void split_kernel(const float* __restrict__ in,
                             __nv_bfloat16* __restrict__ hi,
                             __nv_bfloat16* __restrict__ lo, int n4)
{
    int i = blockIdx.x * blockDim.x + threadIdx.x;
    if (i >= n4) return;
    float4 v = ((const float4*)in)[i];
    uint32_t h0, l0, h1, l1;
    split2(v.x, v.y, h0, l0);
    split2(v.z, v.w, h1, l1);
    ((uint32_t*)hi)[2 * i]     = h0;
    ((uint32_t*)hi)[2 * i + 1] = h1;
    ((uint32_t*)lo)[2 * i]     = l0;
    ((uint32_t*)lo)[2 * i + 1] = l1;
}

// ===== all 4 W -> packed [2048, 8192] + split; also fills rope table =====
__global__ void wsplit_all_kernel(const float* __restrict__ W0, const float* __restrict__ W1,
                                  const float* __restrict__ W2, const float* __restrict__ W3,
                                  __nv_bfloat16* __restrict__ hi, __nv_bfloat16* __restrict__ lo)
{
    const int wsel = blockIdx.y;
    if (wsel == 0 && blockIdx.x < 256) {
        int idx = blockIdx.x * 256 + threadIdx.x;
        int s = idx >> 5, j = idx & 31;
        float inv = expf(-(float)j * LN1E4_OVER_32);
        float sn, cs;
        sincosf((float)s * inv, &sn, &cs);
        g_rope[idx] = make_float2(cs, sn);
    }
    int i = blockIdx.x * blockDim.x + threadIdx.x;
    if (i >= (D_EMB * D_EMB) / 4) return;
    const float* in = (wsel == 0) ? W0 : (wsel == 1) ? W1 : (wsel == 2) ? W2 : W3;
    int r = i >> 9;
    int c4 = (i & 511) << 2;
    float4 v = ((const float4*)in)[i];
    uint32_t h0, l0, h1, l1;
    split2(v.x, v.y, h0, l0);
    split2(v.z, v.w, h1, l1);
    size_t o = ((size_t)r * WCOLS + wsel * 2048 + c4) >> 1;
    ((uint32_t*)hi)[o]     = h0;
    ((uint32_t*)hi)[o + 1] = h1;
    ((uint32_t*)lo)[o]     = l0;
    ((uint32_t*)lo)[o + 1] = l1;
}

// =================== tensor-core GEMM (bf16 x3 split) ====================
// C[M,N] = A[M,K] * B[K,N]. 256 threads, 128x128 tile, BK=32, 3 stages,
// prefetch distance 2, 1 barrier/iter, 2 CTAs per SM.
#define GBK 32
#define GAP 80
#define GBP 272
#define GOFF_AL (128 * GAP)
#define GOFF_BH (2 * 128 * GAP)
#define GOFF_BL (GOFF_BH + GBK * GBP)
#define GSTAGE (GOFF_BL + GBK * GBP)
#define G_SMEM (3 * GSTAGE)

template <int MODE>
__global__ __launch_bounds__(256, 2)
void gemm_bf16x3(const __nv_bfloat16* __restrict__ Ahi, const __nv_bfloat16* __restrict__ Alo,
                 const __nv_bfloat16* __restrict__ Bhi, const __nv_bfloat16* __restrict__ Blo,
                 float* __restrict__ C, int M, int N, int K, int ldb, int ldc)
{
    extern __shared__ __align__(16) uint8_t gsm[];
    const uint32_t sbase = smem_u32(gsm);
    const int tid = threadIdx.x;
    const int lane = tid & 31;
    const int wid = tid >> 5;
    const int m0 = blockIdx.y * 128;
    const int n0 = blockIdx.x * 128;

    const int wm = wid & 3;
    const int wn = wid >> 2;

    const int KT = K / GBK;

    auto load_stage = [&](int t) {
        uint32_t st = sbase + (t % 3) * GSTAGE;
        int k0 = t * GBK;
#pragma unroll
        for (int j = 0; j < 8; j++) {
            int cid = tid + 256 * j;
            if (cid < 1024) {
                int hl = cid >> 9;
                int sub = cid & 511;
                int row = sub >> 2;
                int ch = sub & 3;
                const __nv_bfloat16* src = (hl ? Alo : Ahi)
                    + (size_t)(m0 + row) * K + k0 + ch * 8;
                cp16cg(st + (hl ? GOFF_AL : 0) + row * GAP + ch * 16, src);
            } else {
                int c2 = cid - 1024;
                int hl = c2 >> 9;
                int sub = c2 & 511;
                int row = sub >> 4;
                int ch = sub & 15;
                const __nv_bfloat16* src = (hl ? Blo : Bhi)
                    + (size_t)(k0 + row) * ldb + n0 + ch * 8;
                cp16cg(st + (hl ? GOFF_BL : GOFF_BH) + row * GBP + ch * 16, src);
            }
        }
        asm volatile("cp.async.commit_group;");
    };

    load_stage(0);
    load_stage(1);

    float acc[2][8][4];
#pragma unroll
    for (int i = 0; i < 2; i++)
#pragma unroll
        for (int j = 0; j < 8; j++)
#pragma unroll
            for (int l = 0; l < 4; l++) acc[i][j][l] = 0.f;

    const uint32_t aoff = (uint32_t)(wm * 32 + (lane & 15)) * GAP + ((lane >> 4) & 1) * 16;
    const uint32_t boff = (uint32_t)(lane & 15) * GBP + (uint32_t)wn * 128
                        + ((lane >> 4) & 1) * 16;

    for (int t = 0; t < KT; t++) {
        if (t + 1 < KT) asm volatile("cp.async.wait_group 1;");
        else            asm volatile("cp.async.wait_group 0;");
        __syncthreads();
        if (t + 2 < KT) load_stage(t + 2);

        uint32_t st = sbase + (t % 3) * GSTAGE;
#pragma unroll
        for (int kk = 0; kk < 2; kk++) {
            uint32_t ah[2][4], al[2][4];
            ldmx4(ah[0], st + aoff + kk * 32);
            ldmx4(ah[1], st + aoff + 16 * GAP + kk * 32);
            ldmx4(al[0], st + GOFF_AL + aoff + kk * 32);
            ldmx4(al[1], st + GOFF_AL + aoff + 16 * GAP + kk * 32);
            uint32_t bb = st + boff + (uint32_t)kk * 16 * GBP;
#pragma unroll
            for (int half = 0; half < 2; half++) {
                uint32_t bh[8], bl[8];
                ldmx4t(&bh[0], bb + GOFF_BH + half * 64);
                ldmx4t(&bh[4], bb + GOFF_BH + half * 64 + 32);
                ldmx4t(&bl[0], bb + GOFF_BL + half * 64);
                ldmx4t(&bl[4], bb + GOFF_BL + half * 64 + 32);
#pragma unroll
                for (int mt = 0; mt < 2; mt++)
#pragma unroll
                    for (int nt = 0; nt < 4; nt++) {
                        int ng = half * 4 + nt;
                        mma_bf16(acc[mt][ng], ah[mt], &bh[nt * 2]);
                        mma_bf16(acc[mt][ng], al[mt], &bh[nt * 2]);
                        mma_bf16(acc[mt][ng], ah[mt], &bl[nt * 2]);
                    }
            }
        }
    }

    // epilogue
    const int gid = lane >> 2, tig = lane & 3;
    if (MODE == 0) {
#pragma unroll
        for (int mt = 0; mt < 2; mt++) {
            int row = m0 + wm * 32 + mt * 16 + gid;
#pragma unroll
            for (int nt = 0; nt < 8; nt++) {
                int col = n0 + wn * 64 + nt * 8 + 2 * tig;
                *(float2*)&C[(size_t)row * ldc + col] = make_float2(acc[mt][nt][0], acc[mt][nt][1]);
                *(float2*)&C[(size_t)(row + 8) * ldc + col] = make_float2(acc[mt][nt][2], acc[mt][nt][3]);
            }
        }
    } else {
        const int region = n0 >> 11;    // 0=Q, 1=K, 2=V
        __half* dh = (region == 0) ? g_Qhi : (region == 1) ? g_Khi : g_Vhi;
        __half* dl = (region == 0) ? g_Qlo : (region == 1) ? g_Klo : g_Vlo;
#pragma unroll
        for (int mt = 0; mt < 2; mt++) {
#pragma unroll
            for (int nt = 0; nt < 8; nt++) {
                int col = n0 + wn * 64 + nt * 8 + 2 * tig;
                int cl = col & 2047;
                int j = (cl & 63) >> 1;
#pragma unroll
                for (int rr = 0; rr < 2; rr++) {
                    int row = m0 + wm * 32 + mt * 16 + gid + rr * 8;
                    float v0 = acc[mt][nt][rr * 2 + 0];
                    float v1 = acc[mt][nt][rr * 2 + 1];
                    if (region < 2) {
                        int s = row & (S_LEN - 1);
                        float2 t = g_rope[(s << 5) + j];
                        float f0 = v0 * t.x - v1 * t.y;
                        float f1 = v1 * t.x + v0 * t.y;
                        v0 = f0; v1 = f1;
                    }
                    uint32_t hw, lw;
                    split2h(v0, v1, hw, lw);
                    size_t o = ((size_t)row * D_EMB + cl) >> 1;
                    ((uint32_t*)dh)[o] = hw;
                    ((uint32_t*)dl)[o] = lw;
                }
            }
        }
    }
}

// ====== MMA dual-branch flash attention (fp16, P unsplit, V hi/lo) ========
#define PQB 144
#define PVB 272
#define QK_TILE (64 * PQB)              // 9216
#define V_TILE  (64 * PVB)              // 17408
#define FOFF_Q 0
#define FSTG (4 * QK_TILE + 2 * V_TILE) // 71680
#define FOFF_S0 (4 * QK_TILE)           // 36864
#define FOFF_LAM (FOFF_S0 + 2 * FSTG)   // 180224
#define FL_SMEM (FOFF_LAM + 16)

__global__ __launch_bounds__(256, 1)
void flash_mma_kernel(const __half* __restrict__ Qhi, const __half* __restrict__ Qlo,
                      const __half* __restrict__ Khi, const __half* __restrict__ Klo,
                      const __half* __restrict__ Vhi, const __half* __restrict__ Vlo,
                      const float* __restrict__ lq1, const float* __restrict__ lk1,
                      const float* __restrict__ lq2, const float* __restrict__ lk2,
                      const float* __restrict__ lnw, const float* __restrict__ lnb,
                      __nv_bfloat16* __restrict__ Ahi, __nv_bfloat16* __restrict__ Alo)
{
    extern __shared__ __align__(16) uint8_t smraw[];
    const uint32_t sbase = smem_u32(smraw);
    float* sOut = (float*)smraw;
    float* sLam = (float*)(smraw + FOFF_LAM);

    const int tid = threadIdx.x;
    const int lane = tid & 31;
    const int wid = tid >> 5;
    const int br = wid >> 2;
    const int rbase = (wid & 3) * 16;
    const int g = lane >> 2;
    const int tg = lane & 3;

    const int qt = (int)gridDim.x - 1 - (int)blockIdx.x;
    const int h = blockIdx.y;
    const int b = blockIdx.z;
    const int q0t = qt * 64;
    const size_t rowBase = (size_t)b * S_LEN;
    const int colH = h * 128;

    if (wid == 0) {
        float d1 = lq1[lane] * lk1[lane] + lq1[lane + 32] * lk1[lane + 32];
        float d2 = lq2[lane] * lk2[lane] + lq2[lane + 32] * lk2[lane + 32];
#pragma unroll
        for (int ofs = 16; ofs > 0; ofs >>= 1) {
            d1 += __shfl_xor_sync(0xffffffffu, d1, ofs);
            d2 += __shfl_xor_sync(0xffffffffu, d2, ofs);
        }
        if (lane == 0) sLam[0] = expf(d1) - expf(d2) + LAMBDA_INIT_F;
    }

    // ---- Q tiles ----
#pragma unroll
    for (int it = 0; it < 8; it++) {
        int idx = tid + 256 * it;
        int ch = idx & 7, r = (idx >> 3) & 63, t = idx >> 9;
        const __half* src = ((t & 1) ? Qlo : Qhi)
            + (rowBase + q0t + r) * D_EMB + colH + (t >> 1) * 64 + ch * 8;
        cp16(sbase + FOFF_Q + t * QK_TILE + r * PQB + ch * 16, src);
    }
    asm volatile("cp.async.commit_group;");
    asm volatile("cp.async.wait_group 0;");
    __syncthreads();

    uint32_t qh[4][4], ql[4][4];
    {
        uint32_t qoff = (uint32_t)(rbase + (lane & 15)) * PQB + ((lane >> 4) << 4);
        uint32_t bh_ = sbase + FOFF_Q + (br * 2) * QK_TILE;
#pragma unroll
        for (int s = 0; s < 4; s++) {
            ldmx4(qh[s], bh_ + qoff + s * 32);
            ldmx4(ql[s], bh_ + QK_TILE + qoff + s * 32);
        }
    }

    auto load_kv = [&](int kt) {
        uint32_t stb = sbase + FOFF_S0 + (kt & 1) * FSTG;
#pragma unroll
        for (int it = 0; it < 8; it++) {
            int idx = tid + 256 * it;
            int ch = idx & 7, r = (idx >> 3) & 63, t = idx >> 9;
            const __half* src = ((t & 1) ? Klo : Khi)
                + (rowBase + (size_t)kt * 64 + r) * D_EMB + colH + (t >> 1) * 64 + ch * 8;
            cp16(stb + t * QK_TILE + r * PQB + ch * 16, src);
        }
#pragma unroll
        for (int it = 0; it < 8; it++) {
            int idx = tid + 256 * it;
            int ch = idx & 15, r = (idx >> 4) & 63, t = idx >> 10;
            const __half* src = (t ? Vlo : Vhi)
                + (rowBase + (size_t)kt * 64 + r) * D_EMB + colH + ch * 8;
            cp16(stb + 4 * QK_TILE + t * V_TILE + r * PVB + ch * 16, src);
        }
        asm volatile("cp.async.commit_group;");
    };

    float o[16][4];
#pragma unroll
    for (int i = 0; i < 16; i++)
#pragma unroll
        for (int j = 0; j < 4; j++) o[i][j] = 0.f;
    float m_a = -1e30f, m_b = -1e30f, l_a = 0.f, l_b = 0.f;

    load_kv(0);

    for (int kt = 0; kt <= qt; kt++) {
        if (kt < qt) {
            load_kv(kt + 1);
            asm volatile("cp.async.wait_group 1;");
        } else {
            asm volatile("cp.async.wait_group 0;");
        }
        __syncthreads();

        const uint32_t stb = sbase + FOFF_S0 + (kt & 1) * FSTG;

        float sc[8][4];
#pragma unroll
        for (int i = 0; i < 8; i++)
#pragma unroll
            for (int j = 0; j < 4; j++) sc[i][j] = 0.f;

        const uint32_t kbh = stb + (br * 2) * QK_TILE;
        const uint32_t koff = (uint32_t)(lane & 7) * PQB + ((lane >> 3) << 4);
#pragma unroll
        for (int nt = 0; nt < 8; nt++) {
            uint32_t a = koff + (uint32_t)nt * 8 * PQB;
            uint32_t kh0[4], kh1[4], kl0[4], kl1[4];
            ldmx4(kh0, kbh + a);
            ldmx4(kh1, kbh + a + 64);
            ldmx4(kl0, kbh + QK_TILE + a);
            ldmx4(kl1, kbh + QK_TILE + a + 64);
            mma_fp16(sc[nt], qh[0], &kh0[0]);
            mma_fp16(sc[nt], ql[0], &kh0[0]);
            mma_fp16(sc[nt], qh[0], &kl0[0]);
            mma_fp16(sc[nt], qh[1], &kh0[2]);
            mma_fp16(sc[nt], ql[1], &kh0[2]);
            mma_fp16(sc[nt], qh[1], &kl0[2]);
            mma_fp16(sc[nt], qh[2], &kh1[0]);
            mma_fp16(sc[nt], ql[2], &kh1[0]);
            mma_fp16(sc[nt], qh[2], &kl1[0]);
            mma_fp16(sc[nt], qh[3], &kh1[2]);
            mma_fp16(sc[nt], ql[3], &kh1[2]);
            mma_fp16(sc[nt], qh[3], &kl1[2]);
        }

        const bool diag = (kt == qt);
        float mxa = -1e30f, mxb = -1e30f;
#pragma unroll
        for (int nt = 0; nt < 8; nt++) {
            int c0 = nt * 8 + 2 * tg;
#pragma unroll
            for (int e = 0; e < 4; e++) {
                int row = rbase + g + ((e >> 1) << 3);
                int col = c0 + (e & 1);
                float v = sc[nt][e] * SCALE_LOG2;
                if (diag && col > row) v = -1e30f;
                sc[nt][e] = v;
            }
            mxa = fmaxf(mxa, fmaxf(sc[nt][0], sc[nt][1]));
            mxb = fmaxf(mxb, fmaxf(sc[nt][2], sc[nt][3]));
        }
        mxa = fmaxf(mxa, __shfl_xor_sync(0xffffffffu, mxa, 1));
        mxa = fmaxf(mxa, __shfl_xor_sync(0xffffffffu, mxa, 2));
        mxb = fmaxf(mxb, __shfl_xor_sync(0xffffffffu, mxb, 1));
        mxb = fmaxf(mxb, __shfl_xor_sync(0xffffffffu, mxb, 2));
        float mna = fmaxf(m_a, mxa), mnb = fmaxf(m_b, mxb);
        float alf_a = fexp2(m_a - mna), alf_b = fexp2(m_b - mnb);
        m_a = mna; m_b = mnb;

        // P = exp2(s - m) in fp16, no split
        float suma = 0.f, sumb = 0.f;
        uint32_t ph[4][4];
#pragma unroll
        for (int s2 = 0; s2 < 4; s2++) {
#pragma unroll
            for (int hf = 0; hf < 2; hf++) {
                int nt = 2 * s2 + hf;
                float p0 = fexp2(sc[nt][0] - m_a);
                float p1 = fexp2(sc[nt][1] - m_a);
                float p2 = fexp2(sc[nt][2] - m_b);
                float p3 = fexp2(sc[nt][3] - m_b);
                suma += p0 + p1; sumb += p2 + p3;
                ph[s2][hf * 2 + 0] = pack_f16(p0, p1);
                ph[s2][hf * 2 + 1] = pack_f16(p2, p3);
            }
        }
        suma += __shfl_xor_sync(0xffffffffu, suma, 1);
        suma += __shfl_xor_sync(0xffffffffu, suma, 2);
        sumb += __shfl_xor_sync(0xffffffffu, sumb, 1);
        sumb += __shfl_xor_sync(0xffffffffu, sumb, 2);
        l_a = alf_a * l_a + suma;
        l_b = alf_b * l_b + sumb;

#pragma unroll
        for (int vt = 0; vt < 16; vt++) {
            o[vt][0] *= alf_a; o[vt][1] *= alf_a;
            o[vt][2] *= alf_b; o[vt][3] *= alf_b;
        }

        // ---- O += P (Vhi + Vlo): 2 MMAs per tile ----
        const uint32_t vb = stb + 4 * QK_TILE;
        const uint32_t vrow4 = (uint32_t)(lane & 15) * PVB + ((lane >> 4) << 4);
#pragma unroll
        for (int vt2 = 0; vt2 < 8; vt2++) {
#pragma unroll
            for (int s2 = 0; s2 < 4; s2++) {
                uint32_t addr = (uint32_t)(s2 * 16) * PVB + vrow4 + vt2 * 32;
                uint32_t bh4[4], bl4[4];
                ldmx4t(bh4, vb + addr);
                ldmx4t(bl4, vb + V_TILE + addr);
                mma_fp16(o[2 * vt2],     ph[s2], &bh4[0]);
                mma_fp16(o[2 * vt2],     ph[s2], &bl4[0]);
                mma_fp16(o[2 * vt2 + 1], ph[s2], &bh4[2]);
                mma_fp16(o[2 * vt2 + 1], ph[s2], &bl4[2]);
            }
        }
        __syncthreads();
    }

    float lam = sLam[0];
    float ra = 1.0f / l_a, rb = 1.0f / l_b;

    if (br == 0) {
#pragma unroll
        for (int vt = 0; vt < 16; vt++) {
            int c = vt * 8 + 2 * tg;
            *(float2*)&sOut[(rbase + g) * 128 + c] = make_float2(o[vt][0] * ra, o[vt][1] * ra);
            *(float2*)&sOut[(rbase + g + 8) * 128 + c] = make_float2(o[vt][2] * rb, o[vt][3] * rb);
        }
    }
    __syncthreads();
    if (br == 1) {
#pragma unroll
        for (int vt = 0; vt < 16; vt++) {
            int c = vt * 8 + 2 * tg;
            float2* p0 = (float2*)&sOut[(rbase + g) * 128 + c];
            float2 v0 = *p0;
            v0.x -= lam * o[vt][0] * ra; v0.y -= lam * o[vt][1] * ra;
            *p0 = v0;
            float2* p1 = (float2*)&sOut[(rbase + g + 8) * 128 + c];
            float2 v1 = *p1;
            v1.x -= lam * o[vt][2] * rb; v1.y -= lam * o[vt][3] * rb;
            *p1 = v1;
        }
    }
    __syncthreads();

    // ---- RMSNorm + scale + split bf16 write ----
    {
        int r = tid >> 2;
        int q4 = tid & 3;
        float ss = 0.f;
#pragma unroll
        for (int u = 0; u < 32; u++) {
            float v = sOut[r * 128 + q4 * 32 + u];
            ss += v * v;
        }
        ss += __shfl_xor_sync(0xffffffffu, ss, 1);
        ss += __shfl_xor_sync(0xffffffffu, ss, 2);
        float rn = rsqrtf(ss * (1.0f / 128.0f) + 1e-8f);
        size_t outrow = (rowBase + q0t + r) * D_EMB + colH;
#pragma unroll
        for (int u = 0; u < 32; u += 2) {
            int e = q4 * 32 + u;
            float v0 = (sOut[r * 128 + e] * rn * lnw[e] + lnb[e]) * ONE_MINUS_LI_F;
            float v1 = (sOut[r * 128 + e + 1] * rn * lnw[e + 1] + lnb[e + 1]) * ONE_MINUS_LI_F;
            uint32_t hw, lw;
            split2(v0, v1, hw, lw);
            *(uint32_t*)&Ahi[outrow + e] = hw;
            *(uint32_t*)&Alo[outrow + e] = lw;
        }
    }
}

// ---------------- launch ---------------------------------------------------
extern "C" void kernel_launch(void* const* d_in, const int* in_sizes, int n_in,
                              void* d_out, int out_size)
{
    (void)in_sizes; (void)n_in; (void)out_size;
    const float* x   = (const float*)d_in[0];
    const float* Wq  = (const float*)d_in[1];
    const float* Wk  = (const float*)d_in[2];
    const float* Wv  = (const float*)d_in[3];
    const float* Wo  = (const float*)d_in[4];
    const float* lq1 = (const float*)d_in[5];
    const float* lk1 = (const float*)d_in[6];
    const float* lq2 = (const float*)d_in[7];
    const float* lk2 = (const float*)d_in[8];
    const float* lnw = (const float*)d_in[9];
    const float* lnb = (const float*)d_in[10];
    float* out = (float*)d_out;

    __nv_bfloat16 *xhi, *xlo, *whi, *wlo, *ahi, *alo;
    __half *qhi, *qlo, *khi, *klo, *vhi, *vlo;
    cudaGetSymbolAddress((void**)&xhi, g_xhi);
    cudaGetSymbolAddress((void**)&xlo, g_xlo);
    cudaGetSymbolAddress((void**)&whi, g_whi);
    cudaGetSymbolAddress((void**)&wlo, g_wlo);
    cudaGetSymbolAddress((void**)&ahi, g_ahi);
    cudaGetSymbolAddress((void**)&alo, g_alo);
    cudaGetSymbolAddress((void**)&qhi, g_Qhi);
    cudaGetSymbolAddress((void**)&qlo, g_Qlo);
    cudaGetSymbolAddress((void**)&khi, g_Khi);
    cudaGetSymbolAddress((void**)&klo, g_Klo);
    cudaGetSymbolAddress((void**)&vhi, g_Vhi);
    cudaGetSymbolAddress((void**)&vlo, g_Vlo);

    const int nx4 = (MROWS * D_EMB) / 4;
    const int nw4 = (D_EMB * D_EMB) / 4;

    dim3 wsg((nw4 + 255) / 256, 4);
    wsplit_all_kernel<<<wsg, 256>>>(Wq, Wk, Wv, Wo, whi, wlo);
    split_kernel<<<(nx4 + 255) / 256, 256>>>(x, xhi, xlo, nx4);

    cudaFuncSetAttribute(gemm_bf16x3<0>, cudaFuncAttributeMaxDynamicSharedMemorySize, G_SMEM);
    cudaFuncSetAttribute(gemm_bf16x3<1>, cudaFuncAttributeMaxDynamicSharedMemorySize, G_SMEM);

    // fused QKV projection + rope + fp16 split epilogue
    dim3 gqkv(NQKV / 128, MROWS / 128);   // (48, 32)
    gemm_bf16x3<1><<<gqkv, 256, G_SMEM>>>(xhi, xlo, whi, wlo, nullptr,
                                          MROWS, NQKV, D_EMB, WCOLS, 0);

    cudaFuncSetAttribute(flash_mma_kernel, cudaFuncAttributeMaxDynamicSharedMemorySize, FL_SMEM);
    flash_mma_kernel<<<dim3(32, NHEAD, BATCH), 256, FL_SMEM>>>(
        qhi, qlo, khi, klo, vhi, vlo, lq1, lk1, lq2, lk2, lnw, lnb, ahi, alo);

    // output projection
    dim3 go(D_EMB / 128, MROWS / 128);    // (16, 32)
    gemm_bf16x3<0><<<go, 256, G_SMEM>>>(ahi, alo, whi + 6144, wlo + 6144, out,
                                        MROWS, D_EMB, D_EMB, WCOLS, D_EMB);
}

// round 14
// speedup vs baseline: 1.2647x; 1.2045x over previous
#include <cuda_runtime.h>
#include <cuda_bf16.h>
#include <cuda_fp16.h>
#include <cstdint>
#include <cstddef>

#define S_LEN 2048
#define D_EMB 2048
#define NHEAD 16
#define HDIM 64
#define DVDIM 128
#define BATCH 2
#define MROWS (BATCH * S_LEN)   // 4096
#define NQKV 6144
#define WCOLS 8192

#define LAMBDA_INIT_F 0.78360576653162435f
#define ONE_MINUS_LI_F 0.21639423346837565f
#define LN1E4_OVER_32 (9.210340371976184f / 32.0f)
#define SCALE_LOG2 0.18033688011112042f   // 0.125 * log2(e)

// ---------------- scratch (device globals) -------------------------------
__device__ float2 g_rope[S_LEN * 32];          // [s][j] -> (cos, sin)

__device__ __half g_x16h[(size_t)MROWS * D_EMB];
__device__ __half g_x16l[(size_t)MROWS * D_EMB];
__device__ __half g_w16[(size_t)D_EMB * WCOLS];   // [K, Wq|Wk|Wv|Wo], single fp16
__device__ __half g_a16h[(size_t)MROWS * D_EMB];
__device__ __half g_a16l[(size_t)MROWS * D_EMB];

// fp16 Q/K/V for flash
__device__ __half g_Qhi[(size_t)MROWS * D_EMB];
__device__ __half g_Qlo[(size_t)MROWS * D_EMB];
__device__ __half g_Khi[(size_t)MROWS * D_EMB];
__device__ __half g_Klo[(size_t)MROWS * D_EMB];
__device__ __half g_Vhi[(size_t)MROWS * D_EMB];
__device__ __half g_Vlo[(size_t)MROWS * D_EMB];

// ---------------- common PTX helpers --------------------------------------
__device__ __forceinline__ uint32_t smem_u32(const void* p) {
    return (uint32_t)__cvta_generic_to_shared(p);
}
__device__ __forceinline__ void cp16(uint32_t s, const void* g) {
    asm volatile("cp.async.ca.shared.global [%0], [%1], 16;" :: "r"(s), "l"(g));
}
__device__ __forceinline__ void cp16cg(uint32_t s, const void* g) {
    asm volatile("cp.async.cg.shared.global [%0], [%1], 16;" :: "r"(s), "l"(g));
}
__device__ __forceinline__ void ldmx4(uint32_t r[4], uint32_t addr) {
    asm volatile("ldmatrix.sync.aligned.m8n8.x4.shared.b16 {%0,%1,%2,%3}, [%4];"
        : "=r"(r[0]), "=r"(r[1]), "=r"(r[2]), "=r"(r[3]) : "r"(addr));
}
__device__ __forceinline__ void ldmx4t(uint32_t r[4], uint32_t addr) {
    asm volatile("ldmatrix.sync.aligned.m8n8.x4.trans.shared.b16 {%0,%1,%2,%3}, [%4];"
        : "=r"(r[0]), "=r"(r[1]), "=r"(r[2]), "=r"(r[3]) : "r"(addr));
}
__device__ __forceinline__ void mma_fp16(float c[4], const uint32_t a[4], const uint32_t b[2]) {
    asm volatile("mma.sync.aligned.m16n8k16.row.col.f32.f16.f16.f32 "
        "{%0,%1,%2,%3}, {%4,%5,%6,%7}, {%8,%9}, {%0,%1,%2,%3};"
        : "+f"(c[0]), "+f"(c[1]), "+f"(c[2]), "+f"(c[3])
        : "r"(a[0]), "r"(a[1]), "r"(a[2]), "r"(a[3]), "r"(b[0]), "r"(b[1]));
}
__device__ __forceinline__ uint32_t pack_f16(float lo, float hi) {
    uint32_t r;
    asm("cvt.rn.f16x2.f32 %0, %1, %2;" : "=r"(r) : "f"(hi), "f"(lo));
    return r;
}
__device__ __forceinline__ float fexp2(float x) {
    float r;
    asm("ex2.approx.f32 %0, %1;" : "=f"(r) : "f"(x));
    return r;
}
// fp32 -> fp16 hi/lo
__device__ __forceinline__ void split2h(float v0, float v1, uint32_t& hw, uint32_t& lw) {
    __half h0 = __float2half_rn(v0);
    __half h1 = __float2half_rn(v1);
    __half2 hh = __halves2half2(h0, h1);
    hw = *(uint32_t*)&hh;
    lw = pack_f16(v0 - __half2float(h0), v1 - __half2float(h1));
}

// =================== fp32 -> (fp16 hi, fp16 lo) split ====================
__global__ void split_kernel(const float* __restrict__ in,
                             __half* __restrict__ hi,
                             __half* __restrict__ lo, int n4)
{
    int i = blockIdx.x * blockDim.x + threadIdx.x;
    if (i >= n4) return;
    float4 v = ((const float4*)in)[i];
    uint32_t h0, l0, h1, l1;
    split2h(v.x, v.y, h0, l0);
    split2h(v.z, v.w, h1, l1);
    ((uint32_t*)hi)[2 * i]     = h0;
    ((uint32_t*)hi)[2 * i + 1] = h1;
    ((uint32_t*)lo)[2 * i]     = l0;
    ((uint32_t*)lo)[2 * i + 1] = l1;
}

// ===== all 4 W -> packed [2048, 8192] fp16; also fills rope table =====
__global__ void wsplit_all_kernel(const float* __restrict__ W0, const float* __restrict__ W1,
                                  const float* __restrict__ W2, const float* __restrict__ W3,
                                  __half* __restrict__ w)
{
    const int wsel = blockIdx.y;
    if (wsel == 0 && blockIdx.x < 256) {
        int idx = blockIdx.x * 256 + threadIdx.x;
        int s = idx >> 5, j = idx & 31;
        float inv = expf(-(float)j * LN1E4_OVER_32);
        float sn, cs;
        sincosf((float)s * inv, &sn, &cs);
        g_rope[idx] = make_float2(cs, sn);
    }
    int i = blockIdx.x * blockDim.x + threadIdx.x;
    if (i >= (D_EMB * D_EMB) / 4) return;
    const float* in = (wsel == 0) ? W0 : (wsel == 1) ? W1 : (wsel == 2) ? W2 : W3;
    int r = i >> 9;
    int c4 = (i & 511) << 2;
    float4 v = ((const float4*)in)[i];
    size_t o = ((size_t)r * WCOLS + wsel * 2048 + c4) >> 1;
    ((uint32_t*)w)[o]     = pack_f16(v.x, v.y);
    ((uint32_t*)w)[o + 1] = pack_f16(v.z, v.w);
}

// =================== tensor-core GEMM (fp16 x2 split) ====================
// C[M,N] = A[M,K] * B[K,N]. A fp16 hi/lo, B single fp16. 256 threads,
// 128x128 tile, BK=32, 3 stages, prefetch distance 2, 2 CTAs per SM.
#define GBK 32
#define GAP 80
#define GBP 272
#define GOFF_AL (128 * GAP)               // 10240
#define GOFF_B  (2 * 128 * GAP)           // 20480
#define GSTAGE (GOFF_B + GBK * GBP)       // 29184
#define G_SMEM (3 * GSTAGE)               // 87552

template <int MODE>
__global__ __launch_bounds__(256, 2)
void gemm_fp16x2(const __half* __restrict__ Ahi, const __half* __restrict__ Alo,
                 const __half* __restrict__ B,
                 float* __restrict__ C, int M, int N, int K, int ldb, int ldc)
{
    extern __shared__ __align__(16) uint8_t gsm[];
    const uint32_t sbase = smem_u32(gsm);
    const int tid = threadIdx.x;
    const int lane = tid & 31;
    const int wid = tid >> 5;
    const int m0 = blockIdx.y * 128;
    const int n0 = blockIdx.x * 128;

    const int wm = wid & 3;
    const int wn = wid >> 2;

    const int KT = K / GBK;

    // per stage: A 1024 chunks (128r x 4ch x 2hl), B 512 (32r x 16ch)
    auto load_stage = [&](int t) {
        uint32_t st = sbase + (t % 3) * GSTAGE;
        int k0 = t * GBK;
#pragma unroll
        for (int j = 0; j < 6; j++) {
            int cid = tid + 256 * j;
            if (cid < 1024) {
                int hl = cid >> 9;
                int sub = cid & 511;
                int row = sub >> 2;
                int ch = sub & 3;
                const __half* src = (hl ? Alo : Ahi)
                    + (size_t)(m0 + row) * K + k0 + ch * 8;
                cp16cg(st + (hl ? GOFF_AL : 0) + row * GAP + ch * 16, src);
            } else {
                int c2 = cid - 1024;
                int row = c2 >> 4;
                int ch = c2 & 15;
                const __half* src = B + (size_t)(k0 + row) * ldb + n0 + ch * 8;
                cp16cg(st + GOFF_B + row * GBP + ch * 16, src);
            }
        }
        asm volatile("cp.async.commit_group;");
    };

    load_stage(0);
    load_stage(1);

    float acc[2][8][4];
#pragma unroll
    for (int i = 0; i < 2; i++)
#pragma unroll
        for (int j = 0; j < 8; j++)
#pragma unroll
            for (int l = 0; l < 4; l++) acc[i][j][l] = 0.f;

    const uint32_t aoff = (uint32_t)(wm * 32 + (lane & 15)) * GAP + ((lane >> 4) & 1) * 16;
    const uint32_t boff = (uint32_t)(lane & 15) * GBP + (uint32_t)wn * 128
                        + ((lane >> 4) & 1) * 16 + GOFF_B;

    for (int t = 0; t < KT; t++) {
        if (t + 1 < KT) asm volatile("cp.async.wait_group 1;");
        else            asm volatile("cp.async.wait_group 0;");
        __syncthreads();
        if (t + 2 < KT) load_stage(t + 2);

        uint32_t st = sbase + (t % 3) * GSTAGE;
#pragma unroll
        for (int kk = 0; kk < 2; kk++) {
            uint32_t ah[2][4], al[2][4];
            ldmx4(ah[0], st + aoff + kk * 32);
            ldmx4(ah[1], st + aoff + 16 * GAP + kk * 32);
            ldmx4(al[0], st + GOFF_AL + aoff + kk * 32);
            ldmx4(al[1], st + GOFF_AL + aoff + 16 * GAP + kk * 32);
            uint32_t bb = st + boff + (uint32_t)kk * 16 * GBP;
#pragma unroll
            for (int half = 0; half < 2; half++) {
                uint32_t b4[8];
                ldmx4t(&b4[0], bb + half * 64);
                ldmx4t(&b4[4], bb + half * 64 + 32);
#pragma unroll
                for (int mt = 0; mt < 2; mt++)
#pragma unroll
                    for (int nt = 0; nt < 4; nt++) {
                        int ng = half * 4 + nt;
                        mma_fp16(acc[mt][ng], ah[mt], &b4[nt * 2]);
                        mma_fp16(acc[mt][ng], al[mt], &b4[nt * 2]);
                    }
            }
        }
    }

    // epilogue
    const int gid = lane >> 2, tig = lane & 3;
    if (MODE == 0) {
#pragma unroll
        for (int mt = 0; mt < 2; mt++) {
            int row = m0 + wm * 32 + mt * 16 + gid;
#pragma unroll
            for (int nt = 0; nt < 8; nt++) {
                int col = n0 + wn * 64 + nt * 8 + 2 * tig;
                *(float2*)&C[(size_t)row * ldc + col] = make_float2(acc[mt][nt][0], acc[mt][nt][1]);
                *(float2*)&C[(size_t)(row + 8) * ldc + col] = make_float2(acc[mt][nt][2], acc[mt][nt][3]);
            }
        }
    } else {
        const int region = n0 >> 11;    // 0=Q, 1=K, 2=V
        __half* dh = (region == 0) ? g_Qhi : (region == 1) ? g_Khi : g_Vhi;
        __half* dl = (region == 0) ? g_Qlo : (region == 1) ? g_Klo : g_Vlo;
#pragma unroll
        for (int mt = 0; mt < 2; mt++) {
#pragma unroll
            for (int nt = 0; nt < 8; nt++) {
                int col = n0 + wn * 64 + nt * 8 + 2 * tig;
                int cl = col & 2047;
                int j = (cl & 63) >> 1;
#pragma unroll
                for (int rr = 0; rr < 2; rr++) {
                    int row = m0 + wm * 32 + mt * 16 + gid + rr * 8;
                    float v0 = acc[mt][nt][rr * 2 + 0];
                    float v1 = acc[mt][nt][rr * 2 + 1];
                    if (region < 2) {
                        int s = row & (S_LEN - 1);
                        float2 t = g_rope[(s << 5) + j];
                        float f0 = v0 * t.x - v1 * t.y;
                        float f1 = v1 * t.x + v0 * t.y;
                        v0 = f0; v1 = f1;
                    }
                    uint32_t hw, lw;
                    split2h(v0, v1, hw, lw);
                    size_t o = ((size_t)row * D_EMB + cl) >> 1;
                    ((uint32_t*)dh)[o] = hw;
                    ((uint32_t*)dl)[o] = lw;
                }
            }
        }
    }
}

// ====== MMA dual-branch flash attention (fp16, P unsplit, V hi/lo) ========
#define PQB 144
#define PVB 272
#define QK_TILE (64 * PQB)              // 9216
#define V_TILE  (64 * PVB)              // 17408
#define FOFF_Q 0
#define FSTG (4 * QK_TILE + 2 * V_TILE) // 71680
#define FOFF_S0 (4 * QK_TILE)           // 36864
#define FOFF_LAM (FOFF_S0 + 2 * FSTG)   // 180224
#define FL_SMEM (FOFF_LAM + 16)

__global__ __launch_bounds__(256, 1)
void flash_mma_kernel(const __half* __restrict__ Qhi, const __half* __restrict__ Qlo,
                      const __half* __restrict__ Khi, const __half* __restrict__ Klo,
                      const __half* __restrict__ Vhi, const __half* __restrict__ Vlo,
                      const float* __restrict__ lq1, const float* __restrict__ lk1,
                      const float* __restrict__ lq2, const float* __restrict__ lk2,
                      const float* __restrict__ lnw, const float* __restrict__ lnb,
                      __half* __restrict__ Ahi, __half* __restrict__ Alo)
{
    extern __shared__ __align__(16) uint8_t smraw[];
    const uint32_t sbase = smem_u32(smraw);
    float* sOut = (float*)smraw;
    float* sLam = (float*)(smraw + FOFF_LAM);

    const int tid = threadIdx.x;
    const int lane = tid & 31;
    const int wid = tid >> 5;
    const int br = wid >> 2;
    const int rbase = (wid & 3) * 16;
    const int g = lane >> 2;
    const int tg = lane & 3;

    const int qt = (int)gridDim.x - 1 - (int)blockIdx.x;
    const int h = blockIdx.y;
    const int b = blockIdx.z;
    const int q0t = qt * 64;
    const size_t rowBase = (size_t)b * S_LEN;
    const int colH = h * 128;

    if (wid == 0) {
        float d1 = lq1[lane] * lk1[lane] + lq1[lane + 32] * lk1[lane + 32];
        float d2 = lq2[lane] * lk2[lane] + lq2[lane + 32] * lk2[lane + 32];
#pragma unroll
        for (int ofs = 16; ofs > 0; ofs >>= 1) {
            d1 += __shfl_xor_sync(0xffffffffu, d1, ofs);
            d2 += __shfl_xor_sync(0xffffffffu, d2, ofs);
        }
        if (lane == 0) sLam[0] = expf(d1) - expf(d2) + LAMBDA_INIT_F;
    }

    // ---- Q tiles ----
#pragma unroll
    for (int it = 0; it < 8; it++) {
        int idx = tid + 256 * it;
        int ch = idx & 7, r = (idx >> 3) & 63, t = idx >> 9;
        const __half* src = ((t & 1) ? Qlo : Qhi)
            + (rowBase + q0t + r) * D_EMB + colH + (t >> 1) * 64 + ch * 8;
        cp16(sbase + FOFF_Q + t * QK_TILE + r * PQB + ch * 16, src);
    }
    asm volatile("cp.async.commit_group;");
    asm volatile("cp.async.wait_group 0;");
    __syncthreads();

    uint32_t qh[4][4], ql[4][4];
    {
        uint32_t qoff = (uint32_t)(rbase + (lane & 15)) * PQB + ((lane >> 4) << 4);
        uint32_t bh_ = sbase + FOFF_Q + (br * 2) * QK_TILE;
#pragma unroll
        for (int s = 0; s < 4; s++) {
            ldmx4(qh[s], bh_ + qoff + s * 32);
            ldmx4(ql[s], bh_ + QK_TILE + qoff + s * 32);
        }
    }

    auto load_kv = [&](int kt) {
        uint32_t stb = sbase + FOFF_S0 + (kt & 1) * FSTG;
#pragma unroll
        for (int it = 0; it < 8; it++) {
            int idx = tid + 256 * it;
            int ch = idx & 7, r = (idx >> 3) & 63, t = idx >> 9;
            const __half* src = ((t & 1) ? Klo : Khi)
                + (rowBase + (size_t)kt * 64 + r) * D_EMB + colH + (t >> 1) * 64 + ch * 8;
            cp16(stb + t * QK_TILE + r * PQB + ch * 16, src);
        }
#pragma unroll
        for (int it = 0; it < 8; it++) {
            int idx = tid + 256 * it;
            int ch = idx & 15, r = (idx >> 4) & 63, t = idx >> 10;
            const __half* src = (t ? Vlo : Vhi)
                + (rowBase + (size_t)kt * 64 + r) * D_EMB + colH + ch * 8;
            cp16(stb + 4 * QK_TILE + t * V_TILE + r * PVB + ch * 16, src);
        }
        asm volatile("cp.async.commit_group;");
    };

    float o[16][4];
#pragma unroll
    for (int i = 0; i < 16; i++)
#pragma unroll
        for (int j = 0; j < 4; j++) o[i][j] = 0.f;
    float m_a = -1e30f, m_b = -1e30f, l_a = 0.f, l_b = 0.f;

    load_kv(0);

    for (int kt = 0; kt <= qt; kt++) {
        if (kt < qt) {
            load_kv(kt + 1);
            asm volatile("cp.async.wait_group 1;");
        } else {
            asm volatile("cp.async.wait_group 0;");
        }
        __syncthreads();

        const uint32_t stb = sbase + FOFF_S0 + (kt & 1) * FSTG;

        float sc[8][4];
#pragma unroll
        for (int i = 0; i < 8; i++)
#pragma unroll
            for (int j = 0; j < 4; j++) sc[i][j] = 0.f;

        const uint32_t kbh = stb + (br * 2) * QK_TILE;
        const uint32_t koff = (uint32_t)(lane & 7) * PQB + ((lane >> 3) << 4);
#pragma unroll
        for (int nt = 0; nt < 8; nt++) {
            uint32_t a = koff + (uint32_t)nt * 8 * PQB;
            uint32_t kh0[4], kh1[4], kl0[4], kl1[4];
            ldmx4(kh0, kbh + a);
            ldmx4(kh1, kbh + a + 64);
            ldmx4(kl0, kbh + QK_TILE + a);
            ldmx4(kl1, kbh + QK_TILE + a + 64);
            mma_fp16(sc[nt], qh[0], &kh0[0]);
            mma_fp16(sc[nt], ql[0], &kh0[0]);
            mma_fp16(sc[nt], qh[0], &kl0[0]);
            mma_fp16(sc[nt], qh[1], &kh0[2]);
            mma_fp16(sc[nt], ql[1], &kh0[2]);
            mma_fp16(sc[nt], qh[1], &kl0[2]);
            mma_fp16(sc[nt], qh[2], &kh1[0]);
            mma_fp16(sc[nt], ql[2], &kh1[0]);
            mma_fp16(sc[nt], qh[2], &kl1[0]);
            mma_fp16(sc[nt], qh[3], &kh1[2]);
            mma_fp16(sc[nt], ql[3], &kh1[2]);
            mma_fp16(sc[nt], qh[3], &kl1[2]);
        }

        const bool diag = (kt == qt);
        float mxa = -1e30f, mxb = -1e30f;
#pragma unroll
        for (int nt = 0; nt < 8; nt++) {
            int c0 = nt * 8 + 2 * tg;
#pragma unroll
            for (int e = 0; e < 4; e++) {
                int row = rbase + g + ((e >> 1) << 3);
                int col = c0 + (e & 1);
                float v = sc[nt][e] * SCALE_LOG2;
                if (diag && col > row) v = -1e30f;
                sc[nt][e] = v;
            }
            mxa = fmaxf(mxa, fmaxf(sc[nt][0], sc[nt][1]));
            mxb = fmaxf(mxb, fmaxf(sc[nt][2], sc[nt][3]));
        }
        mxa = fmaxf(mxa, __shfl_xor_sync(0xffffffffu, mxa, 1));
        mxa = fmaxf(mxa, __shfl_xor_sync(0xffffffffu, mxa, 2));
        mxb = fmaxf(mxb, __shfl_xor_sync(0xffffffffu, mxb, 1));
        mxb = fmaxf(mxb, __shfl_xor_sync(0xffffffffu, mxb, 2));
        float mna = fmaxf(m_a, mxa), mnb = fmaxf(m_b, mxb);
        float alf_a = fexp2(m_a - mna), alf_b = fexp2(m_b - mnb);
        m_a = mna; m_b = mnb;

        // P = exp2(s - m) in fp16, no split
        float suma = 0.f, sumb = 0.f;
        uint32_t ph[4][4];
#pragma unroll
        for (int s2 = 0; s2 < 4; s2++) {
#pragma unroll
            for (int hf = 0; hf < 2; hf++) {
                int nt = 2 * s2 + hf;
                float p0 = fexp2(sc[nt][0] - m_a);
                float p1 = fexp2(sc[nt][1] - m_a);
                float p2 = fexp2(sc[nt][2] - m_b);
                float p3 = fexp2(sc[nt][3] - m_b);
                suma += p0 + p1; sumb += p2 + p3;
                ph[s2][hf * 2 + 0] = pack_f16(p0, p1);
                ph[s2][hf * 2 + 1] = pack_f16(p2, p3);
            }
        }
        suma += __shfl_xor_sync(0xffffffffu, suma, 1);
        suma += __shfl_xor_sync(0xffffffffu, suma, 2);
        sumb += __shfl_xor_sync(0xffffffffu, sumb, 1);
        sumb += __shfl_xor_sync(0xffffffffu, sumb, 2);
        l_a = alf_a * l_a + suma;
        l_b = alf_b * l_b + sumb;

#pragma unroll
        for (int vt = 0; vt < 16; vt++) {
            o[vt][0] *= alf_a; o[vt][1] *= alf_a;
            o[vt][2] *= alf_b; o[vt][3] *= alf_b;
        }

        // ---- O += P (Vhi + Vlo) ----
        const uint32_t vb = stb + 4 * QK_TILE;
        const uint32_t vrow4 = (uint32_t)(lane & 15) * PVB + ((lane >> 4) << 4);
#pragma unroll
        for (int vt2 = 0; vt2 < 8; vt2++) {
#pragma unroll
            for (int s2 = 0; s2 < 4; s2++) {
                uint32_t addr = (uint32_t)(s2 * 16) * PVB + vrow4 + vt2 * 32;
                uint32_t bh4[4], bl4[4];
                ldmx4t(bh4, vb + addr);
                ldmx4t(bl4, vb + V_TILE + addr);
                mma_fp16(o[2 * vt2],     ph[s2], &bh4[0]);
                mma_fp16(o[2 * vt2],     ph[s2], &bl4[0]);
                mma_fp16(o[2 * vt2 + 1], ph[s2], &bh4[2]);
                mma_fp16(o[2 * vt2 + 1], ph[s2], &bl4[2]);
            }
        }
        __syncthreads();
    }

    float lam = sLam[0];
    float ra = 1.0f / l_a, rb = 1.0f / l_b;

    if (br == 0) {
#pragma unroll
        for (int vt = 0; vt < 16; vt++) {
            int c = vt * 8 + 2 * tg;
            *(float2*)&sOut[(rbase + g) * 128 + c] = make_float2(o[vt][0] * ra, o[vt][1] * ra);
            *(float2*)&sOut[(rbase + g + 8) * 128 + c] = make_float2(o[vt][2] * rb, o[vt][3] * rb);
        }
    }
    __syncthreads();
    if (br == 1) {
#pragma unroll
        for (int vt = 0; vt < 16; vt++) {
            int c = vt * 8 + 2 * tg;
            float2* p0 = (float2*)&sOut[(rbase + g) * 128 + c];
            float2 v0 = *p0;
            v0.x -= lam * o[vt][0] * ra; v0.y -= lam * o[vt][1] * ra;
            *p0 = v0;
            float2* p1 = (float2*)&sOut[(rbase + g + 8) * 128 + c];
            float2 v1 = *p1;
            v1.x -= lam * o[vt][2] * rb; v1.y -= lam * o[vt][3] * rb;
            *p1 = v1;
        }
    }
    __syncthreads();

    // ---- RMSNorm + scale + fp16 split write ----
    {
        int r = tid >> 2;
        int q4 = tid & 3;
        float ss = 0.f;
#pragma unroll
        for (int u = 0; u < 32; u++) {
            float v = sOut[r * 128 + q4 * 32 + u];
            ss += v * v;
        }
        ss += __shfl_xor_sync(0xffffffffu, ss, 1);
        ss += __shfl_xor_sync(0xffffffffu, ss, 2);
        float rn = rsqrtf(ss * (1.0f / 128.0f) + 1e-8f);
        size_t outrow = (rowBase + q0t + r) * D_EMB + colH;
#pragma unroll
        for (int u = 0; u < 32; u += 2) {
            int e = q4 * 32 + u;
            float v0 = (sOut[r * 128 + e] * rn * lnw[e] + lnb[e]) * ONE_MINUS_LI_F;
            float v1 = (sOut[r * 128 + e + 1] * rn * lnw[e + 1] + lnb[e + 1]) * ONE_MINUS_LI_F;
            uint32_t hw, lw;
            split2h(v0, v1, hw, lw);
            *(uint32_t*)&Ahi[outrow + e] = hw;
            *(uint32_t*)&Alo[outrow + e] = lw;
        }
    }
}

// ---------------- launch ---------------------------------------------------
extern "C" void kernel_launch(void* const* d_in, const int* in_sizes, int n_in,
                              void* d_out, int out_size)
{
    (void)in_sizes; (void)n_in; (void)out_size;
    const float* x   = (const float*)d_in[0];
    const float* Wq  = (const float*)d_in[1];
    const float* Wk  = (const float*)d_in[2];
    const float* Wv  = (const float*)d_in[3];
    const float* Wo  = (const float*)d_in[4];
    const float* lq1 = (const float*)d_in[5];
    const float* lk1 = (const float*)d_in[6];
    const float* lq2 = (const float*)d_in[7];
    const float* lk2 = (const float*)d_in[8];
    const float* lnw = (const float*)d_in[9];
    const float* lnb = (const float*)d_in[10];
    float* out = (float*)d_out;

    __half *xhi, *xlo, *w16, *ahi, *alo;
    __half *qhi, *qlo, *khi, *klo, *vhi, *vlo;
    cudaGetSymbolAddress((void**)&xhi, g_x16h);
    cudaGetSymbolAddress((void**)&xlo, g_x16l);
    cudaGetSymbolAddress((void**)&w16, g_w16);
    cudaGetSymbolAddress((void**)&ahi, g_a16h);
    cudaGetSymbolAddress((void**)&alo, g_a16l);
    cudaGetSymbolAddress((void**)&qhi, g_Qhi);
    cudaGetSymbolAddress((void**)&qlo, g_Qlo);
    cudaGetSymbolAddress((void**)&khi, g_Khi);
    cudaGetSymbolAddress((void**)&klo, g_Klo);
    cudaGetSymbolAddress((void**)&vhi, g_Vhi);
    cudaGetSymbolAddress((void**)&vlo, g_Vlo);

    const int nx4 = (MROWS * D_EMB) / 4;
    const int nw4 = (D_EMB * D_EMB) / 4;

    dim3 wsg((nw4 + 255) / 256, 4);
    wsplit_all_kernel<<<wsg, 256>>>(Wq, Wk, Wv, Wo, w16);
    split_kernel<<<(nx4 + 255) / 256, 256>>>(x, xhi, xlo, nx4);

    cudaFuncSetAttribute(gemm_fp16x2<0>, cudaFuncAttributeMaxDynamicSharedMemorySize, G_SMEM);
    cudaFuncSetAttribute(gemm_fp16x2<1>, cudaFuncAttributeMaxDynamicSharedMemorySize, G_SMEM);

    // fused QKV projection + rope + fp16 split epilogue
    dim3 gqkv(NQKV / 128, MROWS / 128);   // (48, 32)
    gemm_fp16x2<1><<<gqkv, 256, G_SMEM>>>(xhi, xlo, w16, nullptr,
                                          MROWS, NQKV, D_EMB, WCOLS, 0);

    cudaFuncSetAttribute(flash_mma_kernel, cudaFuncAttributeMaxDynamicSharedMemorySize, FL_SMEM);
    flash_mma_kernel<<<dim3(32, NHEAD, BATCH), 256, FL_SMEM>>>(
        qhi, qlo, khi, klo, vhi, vlo, lq1, lk1, lq2, lk2, lnw, lnb, ahi, alo);

    // output projection
    dim3 go(D_EMB / 128, MROWS / 128);    // (16, 32)
    gemm_fp16x2<0><<<go, 256, G_SMEM>>>(ahi, alo, w16 + 6144, out,
                                        MROWS, D_EMB, D_EMB, WCOLS, D_EMB);
}

// round 15
// speedup vs baseline: 1.3892x; 1.0984x over previous
#include <cuda_runtime.h>
#include <cuda_bf16.h>
#include <cuda_fp16.h>
#include <cstdint>
#include <cstddef>

#define S_LEN 2048
#define D_EMB 2048
#define NHEAD 16
#define HDIM 64
#define DVDIM 128
#define BATCH 2
#define MROWS (BATCH * S_LEN)   // 4096
#define NQKV 6144
#define WCOLS 8192

#define LAMBDA_INIT_F 0.78360576653162435f
#define ONE_MINUS_LI_F 0.21639423346837565f
#define LN1E4_OVER_32 (9.210340371976184f / 32.0f)
#define SCALE_LOG2 0.18033688011112042f   // 0.125 * log2(e)

// ---------------- scratch (device globals) -------------------------------
__device__ float2 g_rope[S_LEN * 32];          // [s][j] -> (cos, sin)

__device__ __half g_x16h[(size_t)MROWS * D_EMB];
__device__ __half g_x16l[(size_t)MROWS * D_EMB];
__device__ __half g_w16[(size_t)D_EMB * WCOLS];   // [K, Wq|Wk|Wv|Wo], single fp16
__device__ __half g_a16h[(size_t)MROWS * D_EMB];
__device__ __half g_a16l[(size_t)MROWS * D_EMB];

// fp16 Q/K/V for flash (V single precision)
__device__ __half g_Qhi[(size_t)MROWS * D_EMB];
__device__ __half g_Qlo[(size_t)MROWS * D_EMB];
__device__ __half g_Khi[(size_t)MROWS * D_EMB];
__device__ __half g_Klo[(size_t)MROWS * D_EMB];
__device__ __half g_Vhi[(size_t)MROWS * D_EMB];
__device__ __half g_Vlo[(size_t)MROWS * D_EMB];   // written but unused by flash

// ---------------- common PTX helpers --------------------------------------
__device__ __forceinline__ uint32_t smem_u32(const void* p) {
    return (uint32_t)__cvta_generic_to_shared(p);
}
__device__ __forceinline__ void cp16(uint32_t s, const void* g) {
    asm volatile("cp.async.ca.shared.global [%0], [%1], 16;" :: "r"(s), "l"(g));
}
__device__ __forceinline__ void cp16cg(uint32_t s, const void* g) {
    asm volatile("cp.async.cg.shared.global [%0], [%1], 16;" :: "r"(s), "l"(g));
}
__device__ __forceinline__ void ldmx4(uint32_t r[4], uint32_t addr) {
    asm volatile("ldmatrix.sync.aligned.m8n8.x4.shared.b16 {%0,%1,%2,%3}, [%4];"
        : "=r"(r[0]), "=r"(r[1]), "=r"(r[2]), "=r"(r[3]) : "r"(addr));
}
__device__ __forceinline__ void ldmx4t(uint32_t r[4], uint32_t addr) {
    asm volatile("ldmatrix.sync.aligned.m8n8.x4.trans.shared.b16 {%0,%1,%2,%3}, [%4];"
        : "=r"(r[0]), "=r"(r[1]), "=r"(r[2]), "=r"(r[3]) : "r"(addr));
}
__device__ __forceinline__ void mma_fp16(float c[4], const uint32_t a[4], const uint32_t b[2]) {
    asm volatile("mma.sync.aligned.m16n8k16.row.col.f32.f16.f16.f32 "
        "{%0,%1,%2,%3}, {%4,%5,%6,%7}, {%8,%9}, {%0,%1,%2,%3};"
        : "+f"(c[0]), "+f"(c[1]), "+f"(c[2]), "+f"(c[3])
        : "r"(a[0]), "r"(a[1]), "r"(a[2]), "r"(a[3]), "r"(b[0]), "r"(b[1]));
}
__device__ __forceinline__ uint32_t pack_f16(float lo, float hi) {
    uint32_t r;
    asm("cvt.rn.f16x2.f32 %0, %1, %2;" : "=r"(r) : "f"(hi), "f"(lo));
    return r;
}
__device__ __forceinline__ float fexp2(float x) {
    float r;
    asm("ex2.approx.f32 %0, %1;" : "=f"(r) : "f"(x));
    return r;
}
__device__ __forceinline__ void split2h(float v0, float v1, uint32_t& hw, uint32_t& lw) {
    __half h0 = __float2half_rn(v0);
    __half h1 = __float2half_rn(v1);
    __half2 hh = __halves2half2(h0, h1);
    hw = *(uint32_t*)&hh;
    lw = pack_f16(v0 - __half2float(h0), v1 - __half2float(h1));
}

// =================== fp32 -> (fp16 hi, fp16 lo) split ====================
__global__ void split_kernel(const float* __restrict__ in,
                             __half* __restrict__ hi,
                             __half* __restrict__ lo, int n4)
{
    int i = blockIdx.x * blockDim.x + threadIdx.x;
    if (i >= n4) return;
    float4 v = ((const float4*)in)[i];
    uint32_t h0, l0, h1, l1;
    split2h(v.x, v.y, h0, l0);
    split2h(v.z, v.w, h1, l1);
    ((uint32_t*)hi)[2 * i]     = h0;
    ((uint32_t*)hi)[2 * i + 1] = h1;
    ((uint32_t*)lo)[2 * i]     = l0;
    ((uint32_t*)lo)[2 * i + 1] = l1;
}

// ===== all 4 W -> packed [2048, 8192] fp16; also fills rope table =====
__global__ void wsplit_all_kernel(const float* __restrict__ W0, const float* __restrict__ W1,
                                  const float* __restrict__ W2, const float* __restrict__ W3,
                                  __half* __restrict__ w)
{
    const int wsel = blockIdx.y;
    if (wsel == 0 && blockIdx.x < 256) {
        int idx = blockIdx.x * 256 + threadIdx.x;
        int s = idx >> 5, j = idx & 31;
        float inv = expf(-(float)j * LN1E4_OVER_32);
        float sn, cs;
        sincosf((float)s * inv, &sn, &cs);
        g_rope[idx] = make_float2(cs, sn);
    }
    int i = blockIdx.x * blockDim.x + threadIdx.x;
    if (i >= (D_EMB * D_EMB) / 4) return;
    const float* in = (wsel == 0) ? W0 : (wsel == 1) ? W1 : (wsel == 2) ? W2 : W3;
    int r = i >> 9;
    int c4 = (i & 511) << 2;
    float4 v = ((const float4*)in)[i];
    size_t o = ((size_t)r * WCOLS + wsel * 2048 + c4) >> 1;
    ((uint32_t*)w)[o]     = pack_f16(v.x, v.y);
    ((uint32_t*)w)[o + 1] = pack_f16(v.z, v.w);
}

// =================== tensor-core GEMM (fp16 x2 split) ====================
#define GBK 32
#define GAP 80
#define GBP 272
#define GOFF_AL (128 * GAP)               // 10240
#define GOFF_B  (2 * 128 * GAP)           // 20480
#define GSTAGE (GOFF_B + GBK * GBP)       // 29184
#define G_SMEM (3 * GSTAGE)               // 87552

template <int MODE>
__global__ __launch_bounds__(256, 2)
void gemm_fp16x2(const __half* __restrict__ Ahi, const __half* __restrict__ Alo,
                 const __half* __restrict__ B,
                 float* __restrict__ C, int M, int N, int K, int ldb, int ldc)
{
    extern __shared__ __align__(16) uint8_t gsm[];
    const uint32_t sbase = smem_u32(gsm);
    const int tid = threadIdx.x;
    const int lane = tid & 31;
    const int wid = tid >> 5;
    const int m0 = blockIdx.y * 128;
    const int n0 = blockIdx.x * 128;

    const int wm = wid & 3;
    const int wn = wid >> 2;

    const int KT = K / GBK;

    auto load_stage = [&](int t) {
        uint32_t st = sbase + (t % 3) * GSTAGE;
        int k0 = t * GBK;
#pragma unroll
        for (int j = 0; j < 6; j++) {
            int cid = tid + 256 * j;
            if (cid < 1024) {
                int hl = cid >> 9;
                int sub = cid & 511;
                int row = sub >> 2;
                int ch = sub & 3;
                const __half* src = (hl ? Alo : Ahi)
                    + (size_t)(m0 + row) * K + k0 + ch * 8;
                cp16cg(st + (hl ? GOFF_AL : 0) + row * GAP + ch * 16, src);
            } else {
                int c2 = cid - 1024;
                int row = c2 >> 4;
                int ch = c2 & 15;
                const __half* src = B + (size_t)(k0 + row) * ldb + n0 + ch * 8;
                cp16cg(st + GOFF_B + row * GBP + ch * 16, src);
            }
        }
        asm volatile("cp.async.commit_group;");
    };

    load_stage(0);
    load_stage(1);

    float acc[2][8][4];
#pragma unroll
    for (int i = 0; i < 2; i++)
#pragma unroll
        for (int j = 0; j < 8; j++)
#pragma unroll
            for (int l = 0; l < 4; l++) acc[i][j][l] = 0.f;

    const uint32_t aoff = (uint32_t)(wm * 32 + (lane & 15)) * GAP + ((lane >> 4) & 1) * 16;
    const uint32_t boff = (uint32_t)(lane & 15) * GBP + (uint32_t)wn * 128
                        + ((lane >> 4) & 1) * 16 + GOFF_B;

    for (int t = 0; t < KT; t++) {
        if (t + 1 < KT) asm volatile("cp.async.wait_group 1;");
        else            asm volatile("cp.async.wait_group 0;");
        __syncthreads();
        if (t + 2 < KT) load_stage(t + 2);

        uint32_t st = sbase + (t % 3) * GSTAGE;
#pragma unroll
        for (int kk = 0; kk < 2; kk++) {
            uint32_t ah[2][4], al[2][4];
            ldmx4(ah[0], st + aoff + kk * 32);
            ldmx4(ah[1], st + aoff + 16 * GAP + kk * 32);
            ldmx4(al[0], st + GOFF_AL + aoff + kk * 32);
            ldmx4(al[1], st + GOFF_AL + aoff + 16 * GAP + kk * 32);
            uint32_t bb = st + boff + (uint32_t)kk * 16 * GBP;
#pragma unroll
            for (int half = 0; half < 2; half++) {
                uint32_t b4[8];
                ldmx4t(&b4[0], bb + half * 64);
                ldmx4t(&b4[4], bb + half * 64 + 32);
#pragma unroll
                for (int mt = 0; mt < 2; mt++)
#pragma unroll
                    for (int nt = 0; nt < 4; nt++) {
                        int ng = half * 4 + nt;
                        mma_fp16(acc[mt][ng], ah[mt], &b4[nt * 2]);
                        mma_fp16(acc[mt][ng], al[mt], &b4[nt * 2]);
                    }
            }
        }
    }

    // epilogue
    const int gid = lane >> 2, tig = lane & 3;
    if (MODE == 0) {
#pragma unroll
        for (int mt = 0; mt < 2; mt++) {
            int row = m0 + wm * 32 + mt * 16 + gid;
#pragma unroll
            for (int nt = 0; nt < 8; nt++) {
                int col = n0 + wn * 64 + nt * 8 + 2 * tig;
                *(float2*)&C[(size_t)row * ldc + col] = make_float2(acc[mt][nt][0], acc[mt][nt][1]);
                *(float2*)&C[(size_t)(row + 8) * ldc + col] = make_float2(acc[mt][nt][2], acc[mt][nt][3]);
            }
        }
    } else {
        const int region = n0 >> 11;    // 0=Q, 1=K, 2=V
        __half* dh = (region == 0) ? g_Qhi : (region == 1) ? g_Khi : g_Vhi;
        __half* dl = (region == 0) ? g_Qlo : (region == 1) ? g_Klo : g_Vlo;
#pragma unroll
        for (int mt = 0; mt < 2; mt++) {
#pragma unroll
            for (int nt = 0; nt < 8; nt++) {
                int col = n0 + wn * 64 + nt * 8 + 2 * tig;
                int cl = col & 2047;
                int j = (cl & 63) >> 1;
#pragma unroll
                for (int rr = 0; rr < 2; rr++) {
                    int row = m0 + wm * 32 + mt * 16 + gid + rr * 8;
                    float v0 = acc[mt][nt][rr * 2 + 0];
                    float v1 = acc[mt][nt][rr * 2 + 1];
                    if (region < 2) {
                        int s = row & (S_LEN - 1);
                        float2 t = g_rope[(s << 5) + j];
                        float f0 = v0 * t.x - v1 * t.y;
                        float f1 = v1 * t.x + v0 * t.y;
                        v0 = f0; v1 = f1;
                    }
                    uint32_t hw, lw;
                    split2h(v0, v1, hw, lw);
                    size_t o = ((size_t)row * D_EMB + cl) >> 1;
                    ((uint32_t*)dh)[o] = hw;
                    ((uint32_t*)dl)[o] = lw;
                }
            }
        }
    }
}

// ====== MMA dual-branch flash attention (fp16; P unsplit; V single) =======
#define PQB 144
#define PVB 272
#define QK_TILE (64 * PQB)              // 9216
#define V_TILE  (64 * PVB)              // 17408
#define FOFF_Q 0
#define FSTG (4 * QK_TILE + V_TILE)     // 54272
#define FOFF_S0 (4 * QK_TILE)           // 36864
#define FOFF_LAM (FOFF_S0 + 2 * FSTG)   // 145408
#define FL_SMEM (FOFF_LAM + 16)

__global__ __launch_bounds__(256, 1)
void flash_mma_kernel(const __half* __restrict__ Qhi, const __half* __restrict__ Qlo,
                      const __half* __restrict__ Khi, const __half* __restrict__ Klo,
                      const __half* __restrict__ Vhi,
                      const float* __restrict__ lq1, const float* __restrict__ lk1,
                      const float* __restrict__ lq2, const float* __restrict__ lk2,
                      const float* __restrict__ lnw, const float* __restrict__ lnb,
                      __half* __restrict__ Ahi, __half* __restrict__ Alo)
{
    extern __shared__ __align__(16) uint8_t smraw[];
    const uint32_t sbase = smem_u32(smraw);
    float* sOut = (float*)smraw;
    float* sLam = (float*)(smraw + FOFF_LAM);

    const int tid = threadIdx.x;
    const int lane = tid & 31;
    const int wid = tid >> 5;
    const int br = wid >> 2;
    const int rbase = (wid & 3) * 16;
    const int g = lane >> 2;
    const int tg = lane & 3;

    const int qt = (int)gridDim.x - 1 - (int)blockIdx.x;
    const int h = blockIdx.y;
    const int b = blockIdx.z;
    const int q0t = qt * 64;
    const size_t rowBase = (size_t)b * S_LEN;
    const int colH = h * 128;

    if (wid == 0) {
        float d1 = lq1[lane] * lk1[lane] + lq1[lane + 32] * lk1[lane + 32];
        float d2 = lq2[lane] * lk2[lane] + lq2[lane + 32] * lk2[lane + 32];
#pragma unroll
        for (int ofs = 16; ofs > 0; ofs >>= 1) {
            d1 += __shfl_xor_sync(0xffffffffu, d1, ofs);
            d2 += __shfl_xor_sync(0xffffffffu, d2, ofs);
        }
        if (lane == 0) sLam[0] = expf(d1) - expf(d2) + LAMBDA_INIT_F;
    }

    // ---- Q tiles ----
#pragma unroll
    for (int it = 0; it < 8; it++) {
        int idx = tid + 256 * it;
        int ch = idx & 7, r = (idx >> 3) & 63, t = idx >> 9;
        const __half* src = ((t & 1) ? Qlo : Qhi)
            + (rowBase + q0t + r) * D_EMB + colH + (t >> 1) * 64 + ch * 8;
        cp16(sbase + FOFF_Q + t * QK_TILE + r * PQB + ch * 16, src);
    }
    asm volatile("cp.async.commit_group;");
    asm volatile("cp.async.wait_group 0;");
    __syncthreads();

    uint32_t qh[4][4], ql[4][4];
    {
        uint32_t qoff = (uint32_t)(rbase + (lane & 15)) * PQB + ((lane >> 4) << 4);
        uint32_t bh_ = sbase + FOFF_Q + (br * 2) * QK_TILE;
#pragma unroll
        for (int s = 0; s < 4; s++) {
            ldmx4(qh[s], bh_ + qoff + s * 32);
            ldmx4(ql[s], bh_ + QK_TILE + qoff + s * 32);
        }
    }

    auto load_kv = [&](int kt) {
        uint32_t stb = sbase + FOFF_S0 + (kt & 1) * FSTG;
#pragma unroll
        for (int it = 0; it < 8; it++) {
            int idx = tid + 256 * it;
            int ch = idx & 7, r = (idx >> 3) & 63, t = idx >> 9;
            const __half* src = ((t & 1) ? Klo : Khi)
                + (rowBase + (size_t)kt * 64 + r) * D_EMB + colH + (t >> 1) * 64 + ch * 8;
            cp16(stb + t * QK_TILE + r * PQB + ch * 16, src);
        }
#pragma unroll
        for (int it = 0; it < 4; it++) {
            int idx = tid + 256 * it;
            int ch = idx & 15, r = idx >> 4;
            const __half* src = Vhi
                + (rowBase + (size_t)kt * 64 + r) * D_EMB + colH + ch * 8;
            cp16(stb + 4 * QK_TILE + r * PVB + ch * 16, src);
        }
        asm volatile("cp.async.commit_group;");
    };

    float o[16][4];
#pragma unroll
    for (int i = 0; i < 16; i++)
#pragma unroll
        for (int j = 0; j < 4; j++) o[i][j] = 0.f;
    float m_a = -1e30f, m_b = -1e30f, l_a = 0.f, l_b = 0.f;

    load_kv(0);

    for (int kt = 0; kt <= qt; kt++) {
        if (kt < qt) {
            load_kv(kt + 1);
            asm volatile("cp.async.wait_group 1;");
        } else {
            asm volatile("cp.async.wait_group 0;");
        }
        __syncthreads();

        const uint32_t stb = sbase + FOFF_S0 + (kt & 1) * FSTG;

        float sc[8][4];
#pragma unroll
        for (int i = 0; i < 8; i++)
#pragma unroll
            for (int j = 0; j < 4; j++) sc[i][j] = 0.f;

        const uint32_t kbh = stb + (br * 2) * QK_TILE;
        const uint32_t koff = (uint32_t)(lane & 7) * PQB + ((lane >> 3) << 4);
#pragma unroll
        for (int nt = 0; nt < 8; nt++) {
            uint32_t a = koff + (uint32_t)nt * 8 * PQB;
            uint32_t kh0[4], kh1[4], kl0[4], kl1[4];
            ldmx4(kh0, kbh + a);
            ldmx4(kh1, kbh + a + 64);
            ldmx4(kl0, kbh + QK_TILE + a);
            ldmx4(kl1, kbh + QK_TILE + a + 64);
            mma_fp16(sc[nt], qh[0], &kh0[0]);
            mma_fp16(sc[nt], ql[0], &kh0[0]);
            mma_fp16(sc[nt], qh[0], &kl0[0]);
            mma_fp16(sc[nt], qh[1], &kh0[2]);
            mma_fp16(sc[nt], ql[1], &kh0[2]);
            mma_fp16(sc[nt], qh[1], &kl0[2]);
            mma_fp16(sc[nt], qh[2], &kh1[0]);
            mma_fp16(sc[nt], ql[2], &kh1[0]);
            mma_fp16(sc[nt], qh[2], &kl1[0]);
            mma_fp16(sc[nt], qh[3], &kh1[2]);
            mma_fp16(sc[nt], ql[3], &kh1[2]);
            mma_fp16(sc[nt], qh[3], &kl1[2]);
        }

        const bool diag = (kt == qt);
        float mxa = -1e30f, mxb = -1e30f;
#pragma unroll
        for (int nt = 0; nt < 8; nt++) {
            int c0 = nt * 8 + 2 * tg;
#pragma unroll
            for (int e = 0; e < 4; e++) {
                int row = rbase + g + ((e >> 1) << 3);
                int col = c0 + (e & 1);
                float v = sc[nt][e] * SCALE_LOG2;
                if (diag && col > row) v = -1e30f;
                sc[nt][e] = v;
            }
            mxa = fmaxf(mxa, fmaxf(sc[nt][0], sc[nt][1]));
            mxb = fmaxf(mxb, fmaxf(sc[nt][2], sc[nt][3]));
        }
        mxa = fmaxf(mxa, __shfl_xor_sync(0xffffffffu, mxa, 1));
        mxa = fmaxf(mxa, __shfl_xor_sync(0xffffffffu, mxa, 2));
        mxb = fmaxf(mxb, __shfl_xor_sync(0xffffffffu, mxb, 1));
        mxb = fmaxf(mxb, __shfl_xor_sync(0xffffffffu, mxb, 2));
        float mna = fmaxf(m_a, mxa), mnb = fmaxf(m_b, mxb);
        float alf_a = fexp2(m_a - mna), alf_b = fexp2(m_b - mnb);
        m_a = mna; m_b = mnb;

        float suma = 0.f, sumb = 0.f;
        uint32_t ph[4][4];
#pragma unroll
        for (int s2 = 0; s2 < 4; s2++) {
#pragma unroll
            for (int hf = 0; hf < 2; hf++) {
                int nt = 2 * s2 + hf;
                float p0 = fexp2(sc[nt][0] - m_a);
                float p1 = fexp2(sc[nt][1] - m_a);
                float p2 = fexp2(sc[nt][2] - m_b);
                float p3 = fexp2(sc[nt][3] - m_b);
                suma += p0 + p1; sumb += p2 + p3;
                ph[s2][hf * 2 + 0] = pack_f16(p0, p1);
                ph[s2][hf * 2 + 1] = pack_f16(p2, p3);
            }
        }
        suma += __shfl_xor_sync(0xffffffffu, suma, 1);
        suma += __shfl_xor_sync(0xffffffffu, suma, 2);
        sumb += __shfl_xor_sync(0xffffffffu, sumb, 1);
        sumb += __shfl_xor_sync(0xffffffffu, sumb, 2);
        l_a = alf_a * l_a + suma;
        l_b = alf_b * l_b + sumb;

#pragma unroll
        for (int vt = 0; vt < 16; vt++) {
            o[vt][0] *= alf_a; o[vt][1] *= alf_a;
            o[vt][2] *= alf_b; o[vt][3] *= alf_b;
        }

        // ---- O += P V (single-precision V) ----
        const uint32_t vb = stb + 4 * QK_TILE;
        const uint32_t vrow4 = (uint32_t)(lane & 15) * PVB + ((lane >> 4) << 4);
#pragma unroll
        for (int vt2 = 0; vt2 < 8; vt2++) {
#pragma unroll
            for (int s2 = 0; s2 < 4; s2++) {
                uint32_t addr = (uint32_t)(s2 * 16) * PVB + vrow4 + vt2 * 32;
                uint32_t bh4[4];
                ldmx4t(bh4, vb + addr);
                mma_fp16(o[2 * vt2],     ph[s2], &bh4[0]);
                mma_fp16(o[2 * vt2 + 1], ph[s2], &bh4[2]);
            }
        }
        __syncthreads();
    }

    float lam = sLam[0];
    float ra = 1.0f / l_a, rb = 1.0f / l_b;

    if (br == 0) {
#pragma unroll
        for (int vt = 0; vt < 16; vt++) {
            int c = vt * 8 + 2 * tg;
            *(float2*)&sOut[(rbase + g) * 128 + c] = make_float2(o[vt][0] * ra, o[vt][1] * ra);
            *(float2*)&sOut[(rbase + g + 8) * 128 + c] = make_float2(o[vt][2] * rb, o[vt][3] * rb);
        }
    }
    __syncthreads();
    if (br == 1) {
#pragma unroll
        for (int vt = 0; vt < 16; vt++) {
            int c = vt * 8 + 2 * tg;
            float2* p0 = (float2*)&sOut[(rbase + g) * 128 + c];
            float2 v0 = *p0;
            v0.x -= lam * o[vt][0] * ra; v0.y -= lam * o[vt][1] * ra;
            *p0 = v0;
            float2* p1 = (float2*)&sOut[(rbase + g + 8) * 128 + c];
            float2 v1 = *p1;
            v1.x -= lam * o[vt][2] * rb; v1.y -= lam * o[vt][3] * rb;
            *p1 = v1;
        }
    }
    __syncthreads();

    // ---- RMSNorm + scale + fp16 split write ----
    {
        int r = tid >> 2;
        int q4 = tid & 3;
        float ss = 0.f;
#pragma unroll
        for (int u = 0; u < 32; u++) {
            float v = sOut[r * 128 + q4 * 32 + u];
            ss += v * v;
        }
        ss += __shfl_xor_sync(0xffffffffu, ss, 1);
        ss += __shfl_xor_sync(0xffffffffu, ss, 2);
        float rn = rsqrtf(ss * (1.0f / 128.0f) + 1e-8f);
        size_t outrow = (rowBase + q0t + r) * D_EMB + colH;
#pragma unroll
        for (int u = 0; u < 32; u += 2) {
            int e = q4 * 32 + u;
            float v0 = (sOut[r * 128 + e] * rn * lnw[e] + lnb[e]) * ONE_MINUS_LI_F;
            float v1 = (sOut[r * 128 + e + 1] * rn * lnw[e + 1] + lnb[e + 1]) * ONE_MINUS_LI_F;
            uint32_t hw, lw;
            split2h(v0, v1, hw, lw);
            *(uint32_t*)&Ahi[outrow + e] = hw;
            *(uint32_t*)&Alo[outrow + e] = lw;
        }
    }
}

// ---------------- launch ---------------------------------------------------
extern "C" void kernel_launch(void* const* d_in, const int* in_sizes, int n_in,
                              void* d_out, int out_size)
{
    (void)in_sizes; (void)n_in; (void)out_size;
    const float* x   = (const float*)d_in[0];
    const float* Wq  = (const float*)d_in[1];
    const float* Wk  = (const float*)d_in[2];
    const float* Wv  = (const float*)d_in[3];
    const float* Wo  = (const float*)d_in[4];
    const float* lq1 = (const float*)d_in[5];
    const float* lk1 = (const float*)d_in[6];
    const float* lq2 = (const float*)d_in[7];
    const float* lk2 = (const float*)d_in[8];
    const float* lnw = (const float*)d_in[9];
    const float* lnb = (const float*)d_in[10];
    float* out = (float*)d_out;

    __half *xhi, *xlo, *w16, *ahi, *alo;
    __half *qhi, *qlo, *khi, *klo, *vhi;
    cudaGetSymbolAddress((void**)&xhi, g_x16h);
    cudaGetSymbolAddress((void**)&xlo, g_x16l);
    cudaGetSymbolAddress((void**)&w16, g_w16);
    cudaGetSymbolAddress((void**)&ahi, g_a16h);
    cudaGetSymbolAddress((void**)&alo, g_a16l);
    cudaGetSymbolAddress((void**)&qhi, g_Qhi);
    cudaGetSymbolAddress((void**)&qlo, g_Qlo);
    cudaGetSymbolAddress((void**)&khi, g_Khi);
    cudaGetSymbolAddress((void**)&klo, g_Klo);
    cudaGetSymbolAddress((void**)&vhi, g_Vhi);

    const int nx4 = (MROWS * D_EMB) / 4;
    const int nw4 = (D_EMB * D_EMB) / 4;

    dim3 wsg((nw4 + 255) / 256, 4);
    wsplit_all_kernel<<<wsg, 256>>>(Wq, Wk, Wv, Wo, w16);
    split_kernel<<<(nx4 + 255) / 256, 256>>>(x, xhi, xlo, nx4);

    cudaFuncSetAttribute(gemm_fp16x2<0>, cudaFuncAttributeMaxDynamicSharedMemorySize, G_SMEM);
    cudaFuncSetAttribute(gemm_fp16x2<1>, cudaFuncAttributeMaxDynamicSharedMemorySize, G_SMEM);

    // fused QKV projection + rope + fp16 split epilogue
    dim3 gqkv(NQKV / 128, MROWS / 128);   // (48, 32)
    gemm_fp16x2<1><<<gqkv, 256, G_SMEM>>>(xhi, xlo, w16, nullptr,
                                          MROWS, NQKV, D_EMB, WCOLS, 0);

    cudaFuncSetAttribute(flash_mma_kernel, cudaFuncAttributeMaxDynamicSharedMemorySize, FL_SMEM);
    flash_mma_kernel<<<dim3(32, NHEAD, BATCH), 256, FL_SMEM>>>(
        qhi, qlo, khi, klo, vhi, lq1, lk1, lq2, lk2, lnw, lnb, ahi, alo);

    // output projection
    dim3 go(D_EMB / 128, MROWS / 128);    // (16, 32)
    gemm_fp16x2<0><<<go, 256, G_SMEM>>>(ahi, alo, w16 + 6144, out,
                                        MROWS, D_EMB, D_EMB, WCOLS, D_EMB);
}

// round 16
// speedup vs baseline: 1.5042x; 1.0827x over previous
#include <cuda_runtime.h>
#include <cuda_bf16.h>
#include <cuda_fp16.h>
#include <cstdint>
#include <cstddef>

#define S_LEN 2048
#define D_EMB 2048
#define NHEAD 16
#define HDIM 64
#define DVDIM 128
#define BATCH 2
#define MROWS (BATCH * S_LEN)   // 4096
#define NQKV 6144
#define WCOLS 8192

#define LAMBDA_INIT_F 0.78360576653162435f
#define ONE_MINUS_LI_F 0.21639423346837565f
#define LN1E4_OVER_32 (9.210340371976184f / 32.0f)
#define SCALE_LOG2 0.18033688011112042f   // 0.125 * log2(e)

// ---------------- scratch (device globals) -------------------------------
__device__ float2 g_rope[S_LEN * 32];          // [s][j] -> (cos, sin)

__device__ __half g_x16h[(size_t)MROWS * D_EMB];
__device__ __half g_x16l[(size_t)MROWS * D_EMB];
__device__ __half g_w16[(size_t)D_EMB * WCOLS];   // [K, Wq|Wk|Wv|Wo], single fp16
__device__ __half g_a16h[(size_t)MROWS * D_EMB];
__device__ __half g_a16l[(size_t)MROWS * D_EMB];

// single-fp16 Q/K/V for flash
__device__ __half g_Q16[(size_t)MROWS * D_EMB];
__device__ __half g_K16[(size_t)MROWS * D_EMB];
__device__ __half g_V16[(size_t)MROWS * D_EMB];

// ---------------- common PTX helpers --------------------------------------
__device__ __forceinline__ uint32_t smem_u32(const void* p) {
    return (uint32_t)__cvta_generic_to_shared(p);
}
__device__ __forceinline__ void cp16(uint32_t s, const void* g) {
    asm volatile("cp.async.ca.shared.global [%0], [%1], 16;" :: "r"(s), "l"(g));
}
__device__ __forceinline__ void cp16cg(uint32_t s, const void* g) {
    asm volatile("cp.async.cg.shared.global [%0], [%1], 16;" :: "r"(s), "l"(g));
}
__device__ __forceinline__ void ldmx4(uint32_t r[4], uint32_t addr) {
    asm volatile("ldmatrix.sync.aligned.m8n8.x4.shared.b16 {%0,%1,%2,%3}, [%4];"
        : "=r"(r[0]), "=r"(r[1]), "=r"(r[2]), "=r"(r[3]) : "r"(addr));
}
__device__ __forceinline__ void ldmx4t(uint32_t r[4], uint32_t addr) {
    asm volatile("ldmatrix.sync.aligned.m8n8.x4.trans.shared.b16 {%0,%1,%2,%3}, [%4];"
        : "=r"(r[0]), "=r"(r[1]), "=r"(r[2]), "=r"(r[3]) : "r"(addr));
}
__device__ __forceinline__ void mma_fp16(float c[4], const uint32_t a[4], const uint32_t b[2]) {
    asm volatile("mma.sync.aligned.m16n8k16.row.col.f32.f16.f16.f32 "
        "{%0,%1,%2,%3}, {%4,%5,%6,%7}, {%8,%9}, {%0,%1,%2,%3};"
        : "+f"(c[0]), "+f"(c[1]), "+f"(c[2]), "+f"(c[3])
        : "r"(a[0]), "r"(a[1]), "r"(a[2]), "r"(a[3]), "r"(b[0]), "r"(b[1]));
}
__device__ __forceinline__ uint32_t pack_f16(float lo, float hi) {
    uint32_t r;
    asm("cvt.rn.f16x2.f32 %0, %1, %2;" : "=r"(r) : "f"(hi), "f"(lo));
    return r;
}
__device__ __forceinline__ float fexp2(float x) {
    float r;
    asm("ex2.approx.f32 %0, %1;" : "=f"(r) : "f"(x));
    return r;
}
__device__ __forceinline__ void split2h(float v0, float v1, uint32_t& hw, uint32_t& lw) {
    __half h0 = __float2half_rn(v0);
    __half h1 = __float2half_rn(v1);
    __half2 hh = __halves2half2(h0, h1);
    hw = *(uint32_t*)&hh;
    lw = pack_f16(v0 - __half2float(h0), v1 - __half2float(h1));
}

// =================== fp32 -> (fp16 hi, fp16 lo) split ====================
__global__ void split_kernel(const float* __restrict__ in,
                             __half* __restrict__ hi,
                             __half* __restrict__ lo, int n4)
{
    int i = blockIdx.x * blockDim.x + threadIdx.x;
    if (i >= n4) return;
    float4 v = ((const float4*)in)[i];
    uint32_t h0, l0, h1, l1;
    split2h(v.x, v.y, h0, l0);
    split2h(v.z, v.w, h1, l1);
    ((uint32_t*)hi)[2 * i]     = h0;
    ((uint32_t*)hi)[2 * i + 1] = h1;
    ((uint32_t*)lo)[2 * i]     = l0;
    ((uint32_t*)lo)[2 * i + 1] = l1;
}

// ===== all 4 W -> packed [2048, 8192] fp16; also fills rope table =====
__global__ void wsplit_all_kernel(const float* __restrict__ W0, const float* __restrict__ W1,
                                  const float* __restrict__ W2, const float* __restrict__ W3,
                                  __half* __restrict__ w)
{
    const int wsel = blockIdx.y;
    if (wsel == 0 && blockIdx.x < 256) {
        int idx = blockIdx.x * 256 + threadIdx.x;
        int s = idx >> 5, j = idx & 31;
        float inv = expf(-(float)j * LN1E4_OVER_32);
        float sn, cs;
        sincosf((float)s * inv, &sn, &cs);
        g_rope[idx] = make_float2(cs, sn);
    }
    int i = blockIdx.x * blockDim.x + threadIdx.x;
    if (i >= (D_EMB * D_EMB) / 4) return;
    const float* in = (wsel == 0) ? W0 : (wsel == 1) ? W1 : (wsel == 2) ? W2 : W3;
    int r = i >> 9;
    int c4 = (i & 511) << 2;
    float4 v = ((const float4*)in)[i];
    size_t o = ((size_t)r * WCOLS + wsel * 2048 + c4) >> 1;
    ((uint32_t*)w)[o]     = pack_f16(v.x, v.y);
    ((uint32_t*)w)[o + 1] = pack_f16(v.z, v.w);
}

// =================== tensor-core GEMM (fp16 x2 split) ====================
#define GBK 32
#define GAP 80
#define GBP 272
#define GOFF_AL (128 * GAP)               // 10240
#define GOFF_B  (2 * 128 * GAP)           // 20480
#define GSTAGE (GOFF_B + GBK * GBP)       // 29184
#define G_SMEM (3 * GSTAGE)               // 87552

template <int MODE>
__global__ __launch_bounds__(256, 2)
void gemm_fp16x2(const __half* __restrict__ Ahi, const __half* __restrict__ Alo,
                 const __half* __restrict__ B,
                 float* __restrict__ C, int M, int N, int K, int ldb, int ldc)
{
    extern __shared__ __align__(16) uint8_t gsm[];
    const uint32_t sbase = smem_u32(gsm);
    const int tid = threadIdx.x;
    const int lane = tid & 31;
    const int wid = tid >> 5;
    const int m0 = blockIdx.y * 128;
    const int n0 = blockIdx.x * 128;

    const int wm = wid & 3;
    const int wn = wid >> 2;

    const int KT = K / GBK;

    auto load_stage = [&](int t) {
        uint32_t st = sbase + (t % 3) * GSTAGE;
        int k0 = t * GBK;
#pragma unroll
        for (int j = 0; j < 6; j++) {
            int cid = tid + 256 * j;
            if (cid < 1024) {
                int hl = cid >> 9;
                int sub = cid & 511;
                int row = sub >> 2;
                int ch = sub & 3;
                const __half* src = (hl ? Alo : Ahi)
                    + (size_t)(m0 + row) * K + k0 + ch * 8;
                cp16cg(st + (hl ? GOFF_AL : 0) + row * GAP + ch * 16, src);
            } else {
                int c2 = cid - 1024;
                int row = c2 >> 4;
                int ch = c2 & 15;
                const __half* src = B + (size_t)(k0 + row) * ldb + n0 + ch * 8;
                cp16cg(st + GOFF_B + row * GBP + ch * 16, src);
            }
        }
        asm volatile("cp.async.commit_group;");
    };

    load_stage(0);
    load_stage(1);

    float acc[2][8][4];
#pragma unroll
    for (int i = 0; i < 2; i++)
#pragma unroll
        for (int j = 0; j < 8; j++)
#pragma unroll
            for (int l = 0; l < 4; l++) acc[i][j][l] = 0.f;

    const uint32_t aoff = (uint32_t)(wm * 32 + (lane & 15)) * GAP + ((lane >> 4) & 1) * 16;
    const uint32_t boff = (uint32_t)(lane & 15) * GBP + (uint32_t)wn * 128
                        + ((lane >> 4) & 1) * 16 + GOFF_B;

    for (int t = 0; t < KT; t++) {
        if (t + 1 < KT) asm volatile("cp.async.wait_group 1;");
        else            asm volatile("cp.async.wait_group 0;");
        __syncthreads();
        if (t + 2 < KT) load_stage(t + 2);

        uint32_t st = sbase + (t % 3) * GSTAGE;
#pragma unroll
        for (int kk = 0; kk < 2; kk++) {
            uint32_t ah[2][4], al[2][4];
            ldmx4(ah[0], st + aoff + kk * 32);
            ldmx4(ah[1], st + aoff + 16 * GAP + kk * 32);
            ldmx4(al[0], st + GOFF_AL + aoff + kk * 32);
            ldmx4(al[1], st + GOFF_AL + aoff + 16 * GAP + kk * 32);
            uint32_t bb = st + boff + (uint32_t)kk * 16 * GBP;
#pragma unroll
            for (int half = 0; half < 2; half++) {
                uint32_t b4[8];
                ldmx4t(&b4[0], bb + half * 64);
                ldmx4t(&b4[4], bb + half * 64 + 32);
#pragma unroll
                for (int mt = 0; mt < 2; mt++)
#pragma unroll
                    for (int nt = 0; nt < 4; nt++) {
                        int ng = half * 4 + nt;
                        mma_fp16(acc[mt][ng], ah[mt], &b4[nt * 2]);
                        mma_fp16(acc[mt][ng], al[mt], &b4[nt * 2]);
                    }
            }
        }
    }

    // epilogue
    const int gid = lane >> 2, tig = lane & 3;
    if (MODE == 0) {
#pragma unroll
        for (int mt = 0; mt < 2; mt++) {
            int row = m0 + wm * 32 + mt * 16 + gid;
#pragma unroll
            for (int nt = 0; nt < 8; nt++) {
                int col = n0 + wn * 64 + nt * 8 + 2 * tig;
                *(float2*)&C[(size_t)row * ldc + col] = make_float2(acc[mt][nt][0], acc[mt][nt][1]);
                *(float2*)&C[(size_t)(row + 8) * ldc + col] = make_float2(acc[mt][nt][2], acc[mt][nt][3]);
            }
        }
    } else {
        const int region = n0 >> 11;    // 0=Q, 1=K, 2=V
        __half* dh = (region == 0) ? g_Q16 : (region == 1) ? g_K16 : g_V16;
#pragma unroll
        for (int mt = 0; mt < 2; mt++) {
#pragma unroll
            for (int nt = 0; nt < 8; nt++) {
                int col = n0 + wn * 64 + nt * 8 + 2 * tig;
                int cl = col & 2047;
                int j = (cl & 63) >> 1;
#pragma unroll
                for (int rr = 0; rr < 2; rr++) {
                    int row = m0 + wm * 32 + mt * 16 + gid + rr * 8;
                    float v0 = acc[mt][nt][rr * 2 + 0];
                    float v1 = acc[mt][nt][rr * 2 + 1];
                    if (region < 2) {
                        int s = row & (S_LEN - 1);
                        float2 t = g_rope[(s << 5) + j];
                        float f0 = v0 * t.x - v1 * t.y;
                        float f1 = v1 * t.x + v0 * t.y;
                        v0 = f0; v1 = f1;
                    }
                    size_t o = ((size_t)row * D_EMB + cl) >> 1;
                    ((uint32_t*)dh)[o] = pack_f16(v0, v1);
                }
            }
        }
    }
}

// ====== MMA dual-branch flash attention (all single fp16) =================
#define PQB 144
#define PVB 272
#define QK_TILE (64 * PQB)              // 9216
#define V_TILE  (64 * PVB)              // 17408
#define FOFF_Q 0                        // 2 Q tiles (branch1, branch2)
#define FOFF_S0 (2 * QK_TILE)           // 18432
#define FSTG (2 * QK_TILE + V_TILE)     // 35840
#define FOFF_LAM (FOFF_S0 + 2 * FSTG)   // 90112
#define FL_SMEM (FOFF_LAM + 16)

__global__ __launch_bounds__(256, 1)
void flash_mma_kernel(const __half* __restrict__ Q16, const __half* __restrict__ K16,
                      const __half* __restrict__ V16,
                      const float* __restrict__ lq1, const float* __restrict__ lk1,
                      const float* __restrict__ lq2, const float* __restrict__ lk2,
                      const float* __restrict__ lnw, const float* __restrict__ lnb,
                      __half* __restrict__ Ahi, __half* __restrict__ Alo)
{
    extern __shared__ __align__(16) uint8_t smraw[];
    const uint32_t sbase = smem_u32(smraw);
    float* sOut = (float*)smraw;
    float* sLam = (float*)(smraw + FOFF_LAM);

    const int tid = threadIdx.x;
    const int lane = tid & 31;
    const int wid = tid >> 5;
    const int br = wid >> 2;
    const int rbase = (wid & 3) * 16;
    const int g = lane >> 2;
    const int tg = lane & 3;

    const int qt = (int)gridDim.x - 1 - (int)blockIdx.x;
    const int h = blockIdx.y;
    const int b = blockIdx.z;
    const int q0t = qt * 64;
    const size_t rowBase = (size_t)b * S_LEN;
    const int colH = h * 128;

    if (wid == 0) {
        float d1 = lq1[lane] * lk1[lane] + lq1[lane + 32] * lk1[lane + 32];
        float d2 = lq2[lane] * lk2[lane] + lq2[lane + 32] * lk2[lane + 32];
#pragma unroll
        for (int ofs = 16; ofs > 0; ofs >>= 1) {
            d1 += __shfl_xor_sync(0xffffffffu, d1, ofs);
            d2 += __shfl_xor_sync(0xffffffffu, d2, ofs);
        }
        if (lane == 0) sLam[0] = expf(d1) - expf(d2) + LAMBDA_INIT_F;
    }

    // ---- Q tiles (2: branch1, branch2) ----
#pragma unroll
    for (int it = 0; it < 4; it++) {
        int idx = tid + 256 * it;
        int ch = idx & 7, r = (idx >> 3) & 63, t = idx >> 9;
        const __half* src = Q16
            + (rowBase + q0t + r) * D_EMB + colH + t * 64 + ch * 8;
        cp16(sbase + FOFF_Q + t * QK_TILE + r * PQB + ch * 16, src);
    }
    asm volatile("cp.async.commit_group;");
    asm volatile("cp.async.wait_group 0;");
    __syncthreads();

    uint32_t qh[4][4];
    {
        uint32_t qoff = (uint32_t)(rbase + (lane & 15)) * PQB + ((lane >> 4) << 4);
        uint32_t qb = sbase + FOFF_Q + br * QK_TILE;
#pragma unroll
        for (int s = 0; s < 4; s++)
            ldmx4(qh[s], qb + qoff + s * 32);
    }

    auto load_kv = [&](int kt) {
        uint32_t stb = sbase + FOFF_S0 + (kt & 1) * FSTG;
#pragma unroll
        for (int it = 0; it < 4; it++) {
            int idx = tid + 256 * it;
            int ch = idx & 7, r = (idx >> 3) & 63, t = idx >> 9;
            const __half* src = K16
                + (rowBase + (size_t)kt * 64 + r) * D_EMB + colH + t * 64 + ch * 8;
            cp16(stb + t * QK_TILE + r * PQB + ch * 16, src);
        }
#pragma unroll
        for (int it = 0; it < 4; it++) {
            int idx = tid + 256 * it;
            int ch = idx & 15, r = idx >> 4;
            const __half* src = V16
                + (rowBase + (size_t)kt * 64 + r) * D_EMB + colH + ch * 8;
            cp16(stb + 2 * QK_TILE + r * PVB + ch * 16, src);
        }
        asm volatile("cp.async.commit_group;");
    };

    float o[16][4];
#pragma unroll
    for (int i = 0; i < 16; i++)
#pragma unroll
        for (int j = 0; j < 4; j++) o[i][j] = 0.f;
    float m_a = -1e30f, m_b = -1e30f, l_a = 0.f, l_b = 0.f;

    load_kv(0);

    for (int kt = 0; kt <= qt; kt++) {
        if (kt < qt) {
            load_kv(kt + 1);
            asm volatile("cp.async.wait_group 1;");
        } else {
            asm volatile("cp.async.wait_group 0;");
        }
        __syncthreads();

        const uint32_t stb = sbase + FOFF_S0 + (kt & 1) * FSTG;

        float sc[8][4];
#pragma unroll
        for (int i = 0; i < 8; i++)
#pragma unroll
            for (int j = 0; j < 4; j++) sc[i][j] = 0.f;

        const uint32_t kbh = stb + br * QK_TILE;
        const uint32_t koff = (uint32_t)(lane & 7) * PQB + ((lane >> 3) << 4);
#pragma unroll
        for (int nt = 0; nt < 8; nt++) {
            uint32_t a = koff + (uint32_t)nt * 8 * PQB;
            uint32_t kh0[4], kh1[4];
            ldmx4(kh0, kbh + a);
            ldmx4(kh1, kbh + a + 64);
            mma_fp16(sc[nt], qh[0], &kh0[0]);
            mma_fp16(sc[nt], qh[1], &kh0[2]);
            mma_fp16(sc[nt], qh[2], &kh1[0]);
            mma_fp16(sc[nt], qh[3], &kh1[2]);
        }

        const bool diag = (kt == qt);
        float mxa = -1e30f, mxb = -1e30f;
#pragma unroll
        for (int nt = 0; nt < 8; nt++) {
            int c0 = nt * 8 + 2 * tg;
#pragma unroll
            for (int e = 0; e < 4; e++) {
                int row = rbase + g + ((e >> 1) << 3);
                int col = c0 + (e & 1);
                float v = sc[nt][e] * SCALE_LOG2;
                if (diag && col > row) v = -1e30f;
                sc[nt][e] = v;
            }
            mxa = fmaxf(mxa, fmaxf(sc[nt][0], sc[nt][1]));
            mxb = fmaxf(mxb, fmaxf(sc[nt][2], sc[nt][3]));
        }
        mxa = fmaxf(mxa, __shfl_xor_sync(0xffffffffu, mxa, 1));
        mxa = fmaxf(mxa, __shfl_xor_sync(0xffffffffu, mxa, 2));
        mxb = fmaxf(mxb, __shfl_xor_sync(0xffffffffu, mxb, 1));
        mxb = fmaxf(mxb, __shfl_xor_sync(0xffffffffu, mxb, 2));
        float mna = fmaxf(m_a, mxa), mnb = fmaxf(m_b, mxb);
        float alf_a = fexp2(m_a - mna), alf_b = fexp2(m_b - mnb);
        m_a = mna; m_b = mnb;

        float suma = 0.f, sumb = 0.f;
        uint32_t ph[4][4];
#pragma unroll
        for (int s2 = 0; s2 < 4; s2++) {
#pragma unroll
            for (int hf = 0; hf < 2; hf++) {
                int nt = 2 * s2 + hf;
                float p0 = fexp2(sc[nt][0] - m_a);
                float p1 = fexp2(sc[nt][1] - m_a);
                float p2 = fexp2(sc[nt][2] - m_b);
                float p3 = fexp2(sc[nt][3] - m_b);
                suma += p0 + p1; sumb += p2 + p3;
                ph[s2][hf * 2 + 0] = pack_f16(p0, p1);
                ph[s2][hf * 2 + 1] = pack_f16(p2, p3);
            }
        }
        suma += __shfl_xor_sync(0xffffffffu, suma, 1);
        suma += __shfl_xor_sync(0xffffffffu, suma, 2);
        sumb += __shfl_xor_sync(0xffffffffu, sumb, 1);
        sumb += __shfl_xor_sync(0xffffffffu, sumb, 2);
        l_a = alf_a * l_a + suma;
        l_b = alf_b * l_b + sumb;

#pragma unroll
        for (int vt = 0; vt < 16; vt++) {
            o[vt][0] *= alf_a; o[vt][1] *= alf_a;
            o[vt][2] *= alf_b; o[vt][3] *= alf_b;
        }

        // ---- O += P V ----
        const uint32_t vb = stb + 2 * QK_TILE;
        const uint32_t vrow4 = (uint32_t)(lane & 15) * PVB + ((lane >> 4) << 4);
#pragma unroll
        for (int vt2 = 0; vt2 < 8; vt2++) {
#pragma unroll
            for (int s2 = 0; s2 < 4; s2++) {
                uint32_t addr = (uint32_t)(s2 * 16) * PVB + vrow4 + vt2 * 32;
                uint32_t bh4[4];
                ldmx4t(bh4, vb + addr);
                mma_fp16(o[2 * vt2],     ph[s2], &bh4[0]);
                mma_fp16(o[2 * vt2 + 1], ph[s2], &bh4[2]);
            }
        }
        __syncthreads();
    }

    float lam = sLam[0];
    float ra = 1.0f / l_a, rb = 1.0f / l_b;

    if (br == 0) {
#pragma unroll
        for (int vt = 0; vt < 16; vt++) {
            int c = vt * 8 + 2 * tg;
            *(float2*)&sOut[(rbase + g) * 128 + c] = make_float2(o[vt][0] * ra, o[vt][1] * ra);
            *(float2*)&sOut[(rbase + g + 8) * 128 + c] = make_float2(o[vt][2] * rb, o[vt][3] * rb);
        }
    }
    __syncthreads();
    if (br == 1) {
#pragma unroll
        for (int vt = 0; vt < 16; vt++) {
            int c = vt * 8 + 2 * tg;
            float2* p0 = (float2*)&sOut[(rbase + g) * 128 + c];
            float2 v0 = *p0;
            v0.x -= lam * o[vt][0] * ra; v0.y -= lam * o[vt][1] * ra;
            *p0 = v0;
            float2* p1 = (float2*)&sOut[(rbase + g + 8) * 128 + c];
            float2 v1 = *p1;
            v1.x -= lam * o[vt][2] * rb; v1.y -= lam * o[vt][3] * rb;
            *p1 = v1;
        }
    }
    __syncthreads();

    // ---- RMSNorm + scale + fp16 split write ----
    {
        int r = tid >> 2;
        int q4 = tid & 3;
        float ss = 0.f;
#pragma unroll
        for (int u = 0; u < 32; u++) {
            float v = sOut[r * 128 + q4 * 32 + u];
            ss += v * v;
        }
        ss += __shfl_xor_sync(0xffffffffu, ss, 1);
        ss += __shfl_xor_sync(0xffffffffu, ss, 2);
        float rn = rsqrtf(ss * (1.0f / 128.0f) + 1e-8f);
        size_t outrow = (rowBase + q0t + r) * D_EMB + colH;
#pragma unroll
        for (int u = 0; u < 32; u += 2) {
            int e = q4 * 32 + u;
            float v0 = (sOut[r * 128 + e] * rn * lnw[e] + lnb[e]) * ONE_MINUS_LI_F;
            float v1 = (sOut[r * 128 + e + 1] * rn * lnw[e + 1] + lnb[e + 1]) * ONE_MINUS_LI_F;
            uint32_t hw, lw;
            split2h(v0, v1, hw, lw);
            *(uint32_t*)&Ahi[outrow + e] = hw;
            *(uint32_t*)&Alo[outrow + e] = lw;
        }
    }
}

// ---------------- launch ---------------------------------------------------
extern "C" void kernel_launch(void* const* d_in, const int* in_sizes, int n_in,
                              void* d_out, int out_size)
{
    (void)in_sizes; (void)n_in; (void)out_size;
    const float* x   = (const float*)d_in[0];
    const float* Wq  = (const float*)d_in[1];
    const float* Wk  = (const float*)d_in[2];
    const float* Wv  = (const float*)d_in[3];
    const float* Wo  = (const float*)d_in[4];
    const float* lq1 = (const float*)d_in[5];
    const float* lk1 = (const float*)d_in[6];
    const float* lq2 = (const float*)d_in[7];
    const float* lk2 = (const float*)d_in[8];
    const float* lnw = (const float*)d_in[9];
    const float* lnb = (const float*)d_in[10];
    float* out = (float*)d_out;

    __half *xhi, *xlo, *w16, *ahi, *alo;
    __half *q16, *k16, *v16;
    cudaGetSymbolAddress((void**)&xhi, g_x16h);
    cudaGetSymbolAddress((void**)&xlo, g_x16l);
    cudaGetSymbolAddress((void**)&w16, g_w16);
    cudaGetSymbolAddress((void**)&ahi, g_a16h);
    cudaGetSymbolAddress((void**)&alo, g_a16l);
    cudaGetSymbolAddress((void**)&q16, g_Q16);
    cudaGetSymbolAddress((void**)&k16, g_K16);
    cudaGetSymbolAddress((void**)&v16, g_V16);

    const int nx4 = (MROWS * D_EMB) / 4;
    const int nw4 = (D_EMB * D_EMB) / 4;

    dim3 wsg((nw4 + 255) / 256, 4);
    wsplit_all_kernel<<<wsg, 256>>>(Wq, Wk, Wv, Wo, w16);
    split_kernel<<<(nx4 + 255) / 256, 256>>>(x, xhi, xlo, nx4);

    cudaFuncSetAttribute(gemm_fp16x2<0>, cudaFuncAttributeMaxDynamicSharedMemorySize, G_SMEM);
    cudaFuncSetAttribute(gemm_fp16x2<1>, cudaFuncAttributeMaxDynamicSharedMemorySize, G_SMEM);

    // fused QKV projection + rope + fp16 epilogue
    dim3 gqkv(NQKV / 128, MROWS / 128);   // (48, 32)
    gemm_fp16x2<1><<<gqkv, 256, G_SMEM>>>(xhi, xlo, w16, nullptr,
                                          MROWS, NQKV, D_EMB, WCOLS, 0);

    cudaFuncSetAttribute(flash_mma_kernel, cudaFuncAttributeMaxDynamicSharedMemorySize, FL_SMEM);
    flash_mma_kernel<<<dim3(32, NHEAD, BATCH), 256, FL_SMEM>>>(
        q16, k16, v16, lq1, lk1, lq2, lk2, lnw, lnb, ahi, alo);

    // output projection
    dim3 go(D_EMB / 128, MROWS / 128);    // (16, 32)
    gemm_fp16x2<0><<<go, 256, G_SMEM>>>(ahi, alo, w16 + 6144, out,
                                        MROWS, D_EMB, D_EMB, WCOLS, D_EMB);
}

// round 17
// speedup vs baseline: 1.9673x; 1.3079x over previous
#include <cuda_runtime.h>
#include <cuda_bf16.h>
#include <cuda_fp16.h>
#include <cstdint>
#include <cstddef>

#define S_LEN 2048
#define D_EMB 2048
#define NHEAD 16
#define HDIM 64
#define DVDIM 128
#define BATCH 2
#define MROWS (BATCH * S_LEN)   // 4096
#define NQKV 6144
#define WCOLS 8192

#define LAMBDA_INIT_F 0.78360576653162435f
#define ONE_MINUS_LI_F 0.21639423346837565f
#define LN1E4_OVER_32 (9.210340371976184f / 32.0f)
#define SCALE_LOG2 0.18033688011112042f   // 0.125 * log2(e)

// ---------------- scratch (device globals) -------------------------------
__device__ float2 g_rope[S_LEN * 32];          // [s][j] -> (cos, sin)

__device__ __half g_x16[(size_t)MROWS * D_EMB];
__device__ __half g_w16[(size_t)D_EMB * WCOLS];   // [K, Wq|Wk|Wv|Wo], single fp16
__device__ __half g_a16h[(size_t)MROWS * D_EMB];
__device__ __half g_a16l[(size_t)MROWS * D_EMB];

// single-fp16 Q/K/V for flash
__device__ __half g_Q16[(size_t)MROWS * D_EMB];
__device__ __half g_K16[(size_t)MROWS * D_EMB];
__device__ __half g_V16[(size_t)MROWS * D_EMB];

// ---------------- common PTX helpers --------------------------------------
__device__ __forceinline__ uint32_t smem_u32(const void* p) {
    return (uint32_t)__cvta_generic_to_shared(p);
}
__device__ __forceinline__ void cp16(uint32_t s, const void* g) {
    asm volatile("cp.async.ca.shared.global [%0], [%1], 16;" :: "r"(s), "l"(g));
}
__device__ __forceinline__ void cp16cg(uint32_t s, const void* g) {
    asm volatile("cp.async.cg.shared.global [%0], [%1], 16;" :: "r"(s), "l"(g));
}
__device__ __forceinline__ void ldmx4(uint32_t r[4], uint32_t addr) {
    asm volatile("ldmatrix.sync.aligned.m8n8.x4.shared.b16 {%0,%1,%2,%3}, [%4];"
        : "=r"(r[0]), "=r"(r[1]), "=r"(r[2]), "=r"(r[3]) : "r"(addr));
}
__device__ __forceinline__ void ldmx4t(uint32_t r[4], uint32_t addr) {
    asm volatile("ldmatrix.sync.aligned.m8n8.x4.trans.shared.b16 {%0,%1,%2,%3}, [%4];"
        : "=r"(r[0]), "=r"(r[1]), "=r"(r[2]), "=r"(r[3]) : "r"(addr));
}
__device__ __forceinline__ void mma_fp16(float c[4], const uint32_t a[4], const uint32_t b[2]) {
    asm volatile("mma.sync.aligned.m16n8k16.row.col.f32.f16.f16.f32 "
        "{%0,%1,%2,%3}, {%4,%5,%6,%7}, {%8,%9}, {%0,%1,%2,%3};"
        : "+f"(c[0]), "+f"(c[1]), "+f"(c[2]), "+f"(c[3])
        : "r"(a[0]), "r"(a[1]), "r"(a[2]), "r"(a[3]), "r"(b[0]), "r"(b[1]));
}
__device__ __forceinline__ uint32_t pack_f16(float lo, float hi) {
    uint32_t r;
    asm("cvt.rn.f16x2.f32 %0, %1, %2;" : "=r"(r) : "f"(hi), "f"(lo));
    return r;
}
__device__ __forceinline__ float fexp2(float x) {
    float r;
    asm("ex2.approx.f32 %0, %1;" : "=f"(r) : "f"(x));
    return r;
}
__device__ __forceinline__ void split2h(float v0, float v1, uint32_t& hw, uint32_t& lw) {
    __half h0 = __float2half_rn(v0);
    __half h1 = __float2half_rn(v1);
    __half2 hh = __halves2half2(h0, h1);
    hw = *(uint32_t*)&hh;
    lw = pack_f16(v0 - __half2float(h0), v1 - __half2float(h1));
}

// =================== fp32 -> fp16 convert ================================
__global__ void conv_kernel(const float* __restrict__ in,
                            __half* __restrict__ out, int n4)
{
    int i = blockIdx.x * blockDim.x + threadIdx.x;
    if (i >= n4) return;
    float4 v = ((const float4*)in)[i];
    ((uint32_t*)out)[2 * i]     = pack_f16(v.x, v.y);
    ((uint32_t*)out)[2 * i + 1] = pack_f16(v.z, v.w);
}

// ===== all 4 W -> packed [2048, 8192] fp16; also fills rope table =====
__global__ void wsplit_all_kernel(const float* __restrict__ W0, const float* __restrict__ W1,
                                  const float* __restrict__ W2, const float* __restrict__ W3,
                                  __half* __restrict__ w)
{
    const int wsel = blockIdx.y;
    if (wsel == 0 && blockIdx.x < 256) {
        int idx = blockIdx.x * 256 + threadIdx.x;
        int s = idx >> 5, j = idx & 31;
        float inv = expf(-(float)j * LN1E4_OVER_32);
        float sn, cs;
        sincosf((float)s * inv, &sn, &cs);
        g_rope[idx] = make_float2(cs, sn);
    }
    int i = blockIdx.x * blockDim.x + threadIdx.x;
    if (i >= (D_EMB * D_EMB) / 4) return;
    const float* in = (wsel == 0) ? W0 : (wsel == 1) ? W1 : (wsel == 2) ? W2 : W3;
    int r = i >> 9;
    int c4 = (i & 511) << 2;
    float4 v = ((const float4*)in)[i];
    size_t o = ((size_t)r * WCOLS + wsel * 2048 + c4) >> 1;
    ((uint32_t*)w)[o]     = pack_f16(v.x, v.y);
    ((uint32_t*)w)[o + 1] = pack_f16(v.z, v.w);
}

// =================== tensor-core GEMM (fp16, optional A split) ===========
// MODE 0: fp32 store (Wo).  MODE 1: rope+fp16 Q/K/V epilogue (QKV).
// ASPLIT 1: A = Ahi + Alo (2 MMAs). ASPLIT 0: A single (1 MMA).
#define GBK 32
#define GAP 80
#define GBP 272

template <int MODE, int ASPLIT>
__global__ __launch_bounds__(256, 2)
void gemm_fp16(const __half* __restrict__ Ahi, const __half* __restrict__ Alo,
               const __half* __restrict__ B,
               float* __restrict__ C, int M, int N, int K, int ldb, int ldc)
{
    constexpr uint32_t OFF_AL = 128 * GAP;                         // valid if ASPLIT
    constexpr uint32_t OFF_B  = (ASPLIT ? 2 : 1) * 128 * GAP;
    constexpr uint32_t STG    = OFF_B + GBK * GBP;
    constexpr int ACH         = ASPLIT ? 1024 : 512;               // A chunks/stage

    extern __shared__ __align__(16) uint8_t gsm[];
    const uint32_t sbase = smem_u32(gsm);
    const int tid = threadIdx.x;
    const int lane = tid & 31;
    const int wid = tid >> 5;
    const int m0 = blockIdx.y * 128;
    const int n0 = blockIdx.x * 128;

    const int wm = wid & 3;
    const int wn = wid >> 2;

    const int KT = K / GBK;

    auto load_stage = [&](int t) {
        uint32_t st = sbase + (t % 3) * STG;
        int k0 = t * GBK;
#pragma unroll
        for (int j = 0; j < (ACH + 512) / 256; j++) {
            int cid = tid + 256 * j;
            if (cid < ACH) {
                int hl = ASPLIT ? (cid >> 9) : 0;
                int sub = cid & 511;
                int row = sub >> 2;
                int ch = sub & 3;
                const __half* src = (hl ? Alo : Ahi)
                    + (size_t)(m0 + row) * K + k0 + ch * 8;
                cp16cg(st + (hl ? OFF_AL : 0) + row * GAP + ch * 16, src);
            } else {
                int c2 = cid - ACH;
                int row = c2 >> 4;
                int ch = c2 & 15;
                const __half* src = B + (size_t)(k0 + row) * ldb + n0 + ch * 8;
                cp16cg(st + OFF_B + row * GBP + ch * 16, src);
            }
        }
        asm volatile("cp.async.commit_group;");
    };

    load_stage(0);
    load_stage(1);

    float acc[2][8][4];
#pragma unroll
    for (int i = 0; i < 2; i++)
#pragma unroll
        for (int j = 0; j < 8; j++)
#pragma unroll
            for (int l = 0; l < 4; l++) acc[i][j][l] = 0.f;

    const uint32_t aoff = (uint32_t)(wm * 32 + (lane & 15)) * GAP + ((lane >> 4) & 1) * 16;
    const uint32_t boff = (uint32_t)(lane & 15) * GBP + (uint32_t)wn * 128
                        + ((lane >> 4) & 1) * 16 + OFF_B;

    for (int t = 0; t < KT; t++) {
        if (t + 1 < KT) asm volatile("cp.async.wait_group 1;");
        else            asm volatile("cp.async.wait_group 0;");
        __syncthreads();
        if (t + 2 < KT) load_stage(t + 2);

        uint32_t st = sbase + (t % 3) * STG;
#pragma unroll
        for (int kk = 0; kk < 2; kk++) {
            uint32_t ah[2][4], al[2][4];
            ldmx4(ah[0], st + aoff + kk * 32);
            ldmx4(ah[1], st + aoff + 16 * GAP + kk * 32);
            if (ASPLIT) {
                ldmx4(al[0], st + OFF_AL + aoff + kk * 32);
                ldmx4(al[1], st + OFF_AL + aoff + 16 * GAP + kk * 32);
            }
            uint32_t bb = st + boff + (uint32_t)kk * 16 * GBP;
#pragma unroll
            for (int half = 0; half < 2; half++) {
                uint32_t b4[8];
                ldmx4t(&b4[0], bb + half * 64);
                ldmx4t(&b4[4], bb + half * 64 + 32);
#pragma unroll
                for (int mt = 0; mt < 2; mt++)
#pragma unroll
                    for (int nt = 0; nt < 4; nt++) {
                        int ng = half * 4 + nt;
                        mma_fp16(acc[mt][ng], ah[mt], &b4[nt * 2]);
                        if (ASPLIT) mma_fp16(acc[mt][ng], al[mt], &b4[nt * 2]);
                    }
            }
        }
    }

    // epilogue
    const int gid = lane >> 2, tig = lane & 3;
    if (MODE == 0) {
#pragma unroll
        for (int mt = 0; mt < 2; mt++) {
            int row = m0 + wm * 32 + mt * 16 + gid;
#pragma unroll
            for (int nt = 0; nt < 8; nt++) {
                int col = n0 + wn * 64 + nt * 8 + 2 * tig;
                *(float2*)&C[(size_t)row * ldc + col] = make_float2(acc[mt][nt][0], acc[mt][nt][1]);
                *(float2*)&C[(size_t)(row + 8) * ldc + col] = make_float2(acc[mt][nt][2], acc[mt][nt][3]);
            }
        }
    } else {
        const int region = n0 >> 11;    // 0=Q, 1=K, 2=V
        __half* dh = (region == 0) ? g_Q16 : (region == 1) ? g_K16 : g_V16;
#pragma unroll
        for (int mt = 0; mt < 2; mt++) {
#pragma unroll
            for (int nt = 0; nt < 8; nt++) {
                int col = n0 + wn * 64 + nt * 8 + 2 * tig;
                int cl = col & 2047;
                int j = (cl & 63) >> 1;
#pragma unroll
                for (int rr = 0; rr < 2; rr++) {
                    int row = m0 + wm * 32 + mt * 16 + gid + rr * 8;
                    float v0 = acc[mt][nt][rr * 2 + 0];
                    float v1 = acc[mt][nt][rr * 2 + 1];
                    if (region < 2) {
                        int s = row & (S_LEN - 1);
                        float2 t = g_rope[(s << 5) + j];
                        float f0 = v0 * t.x - v1 * t.y;
                        float f1 = v1 * t.x + v0 * t.y;
                        v0 = f0; v1 = f1;
                    }
                    size_t o = ((size_t)row * D_EMB + cl) >> 1;
                    ((uint32_t*)dh)[o] = pack_f16(v0, v1);
                }
            }
        }
    }
}

#define G_SMEM_X1 (3 * (128 * GAP + GBK * GBP))       // 56832
#define G_SMEM_X2 (3 * (2 * 128 * GAP + GBK * GBP))   // 87552

// ====== MMA dual-branch flash attention (all single fp16) =================
#define PQB 144
#define PVB 272
#define QK_TILE (64 * PQB)              // 9216
#define V_TILE  (64 * PVB)              // 17408
#define FOFF_Q 0
#define FOFF_S0 (2 * QK_TILE)           // 18432
#define FSTG (2 * QK_TILE + V_TILE)     // 35840
#define FOFF_LAM (FOFF_S0 + 2 * FSTG)   // 90112
#define FL_SMEM (FOFF_LAM + 16)

__global__ __launch_bounds__(256, 1)
void flash_mma_kernel(const __half* __restrict__ Q16, const __half* __restrict__ K16,
                      const __half* __restrict__ V16,
                      const float* __restrict__ lq1, const float* __restrict__ lk1,
                      const float* __restrict__ lq2, const float* __restrict__ lk2,
                      const float* __restrict__ lnw, const float* __restrict__ lnb,
                      __half* __restrict__ Ahi, __half* __restrict__ Alo)
{
    extern __shared__ __align__(16) uint8_t smraw[];
    const uint32_t sbase = smem_u32(smraw);
    float* sOut = (float*)smraw;
    float* sLam = (float*)(smraw + FOFF_LAM);

    const int tid = threadIdx.x;
    const int lane = tid & 31;
    const int wid = tid >> 5;
    const int br = wid >> 2;
    const int rbase = (wid & 3) * 16;
    const int g = lane >> 2;
    const int tg = lane & 3;

    const int qt = (int)gridDim.x - 1 - (int)blockIdx.x;
    const int h = blockIdx.y;
    const int b = blockIdx.z;
    const int q0t = qt * 64;
    const size_t rowBase = (size_t)b * S_LEN;
    const int colH = h * 128;

    if (wid == 0) {
        float d1 = lq1[lane] * lk1[lane] + lq1[lane + 32] * lk1[lane + 32];
        float d2 = lq2[lane] * lk2[lane] + lq2[lane + 32] * lk2[lane + 32];
#pragma unroll
        for (int ofs = 16; ofs > 0; ofs >>= 1) {
            d1 += __shfl_xor_sync(0xffffffffu, d1, ofs);
            d2 += __shfl_xor_sync(0xffffffffu, d2, ofs);
        }
        if (lane == 0) sLam[0] = expf(d1) - expf(d2) + LAMBDA_INIT_F;
    }

    // ---- Q tiles (branch1, branch2) ----
#pragma unroll
    for (int it = 0; it < 4; it++) {
        int idx = tid + 256 * it;
        int ch = idx & 7, r = (idx >> 3) & 63, t = idx >> 9;
        const __half* src = Q16
            + (rowBase + q0t + r) * D_EMB + colH + t * 64 + ch * 8;
        cp16(sbase + FOFF_Q + t * QK_TILE + r * PQB + ch * 16, src);
    }
    asm volatile("cp.async.commit_group;");
    asm volatile("cp.async.wait_group 0;");
    __syncthreads();

    uint32_t qh[4][4];
    {
        uint32_t qoff = (uint32_t)(rbase + (lane & 15)) * PQB + ((lane >> 4) << 4);
        uint32_t qb = sbase + FOFF_Q + br * QK_TILE;
#pragma unroll
        for (int s = 0; s < 4; s++)
            ldmx4(qh[s], qb + qoff + s * 32);
    }

    auto load_kv = [&](int kt) {
        uint32_t stb = sbase + FOFF_S0 + (kt & 1) * FSTG;
#pragma unroll
        for (int it = 0; it < 4; it++) {
            int idx = tid + 256 * it;
            int ch = idx & 7, r = (idx >> 3) & 63, t = idx >> 9;
            const __half* src = K16
                + (rowBase + (size_t)kt * 64 + r) * D_EMB + colH + t * 64 + ch * 8;
            cp16(stb + t * QK_TILE + r * PQB + ch * 16, src);
        }
#pragma unroll
        for (int it = 0; it < 4; it++) {
            int idx = tid + 256 * it;
            int ch = idx & 15, r = idx >> 4;
            const __half* src = V16
                + (rowBase + (size_t)kt * 64 + r) * D_EMB + colH + ch * 8;
            cp16(stb + 2 * QK_TILE + r * PVB + ch * 16, src);
        }
        asm volatile("cp.async.commit_group;");
    };

    float o[16][4];
#pragma unroll
    for (int i = 0; i < 16; i++)
#pragma unroll
        for (int j = 0; j < 4; j++) o[i][j] = 0.f;
    float m_a = -1e30f, m_b = -1e30f, l_a = 0.f, l_b = 0.f;

    load_kv(0);

    for (int kt = 0; kt <= qt; kt++) {
        if (kt < qt) {
            load_kv(kt + 1);
            asm volatile("cp.async.wait_group 1;");
        } else {
            asm volatile("cp.async.wait_group 0;");
        }
        __syncthreads();

        const uint32_t stb = sbase + FOFF_S0 + (kt & 1) * FSTG;

        float sc[8][4];
#pragma unroll
        for (int i = 0; i < 8; i++)
#pragma unroll
            for (int j = 0; j < 4; j++) sc[i][j] = 0.f;

        const uint32_t kbh = stb + br * QK_TILE;
        const uint32_t koff = (uint32_t)(lane & 7) * PQB + ((lane >> 3) << 4);
#pragma unroll
        for (int nt = 0; nt < 8; nt++) {
            uint32_t a = koff + (uint32_t)nt * 8 * PQB;
            uint32_t kh0[4], kh1[4];
            ldmx4(kh0, kbh + a);
            ldmx4(kh1, kbh + a + 64);
            mma_fp16(sc[nt], qh[0], &kh0[0]);
            mma_fp16(sc[nt], qh[1], &kh0[2]);
            mma_fp16(sc[nt], qh[2], &kh1[0]);
            mma_fp16(sc[nt], qh[3], &kh1[2]);
        }

        const bool diag = (kt == qt);
        float mxa = -1e30f, mxb = -1e30f;
#pragma unroll
        for (int nt = 0; nt < 8; nt++) {
            int c0 = nt * 8 + 2 * tg;
#pragma unroll
            for (int e = 0; e < 4; e++) {
                int row = rbase + g + ((e >> 1) << 3);
                int col = c0 + (e & 1);
                float v = sc[nt][e] * SCALE_LOG2;
                if (diag && col > row) v = -1e30f;
                sc[nt][e] = v;
            }
            mxa = fmaxf(mxa, fmaxf(sc[nt][0], sc[nt][1]));
            mxb = fmaxf(mxb, fmaxf(sc[nt][2], sc[nt][3]));
        }
        mxa = fmaxf(mxa, __shfl_xor_sync(0xffffffffu, mxa, 1));
        mxa = fmaxf(mxa, __shfl_xor_sync(0xffffffffu, mxa, 2));
        mxb = fmaxf(mxb, __shfl_xor_sync(0xffffffffu, mxb, 1));
        mxb = fmaxf(mxb, __shfl_xor_sync(0xffffffffu, mxb, 2));
        float mna = fmaxf(m_a, mxa), mnb = fmaxf(m_b, mxb);
        float alf_a = fexp2(m_a - mna), alf_b = fexp2(m_b - mnb);
        m_a = mna; m_b = mnb;

        float suma = 0.f, sumb = 0.f;
        uint32_t ph[4][4];
#pragma unroll
        for (int s2 = 0; s2 < 4; s2++) {
#pragma unroll
            for (int hf = 0; hf < 2; hf++) {
                int nt = 2 * s2 + hf;
                float p0 = fexp2(sc[nt][0] - m_a);
                float p1 = fexp2(sc[nt][1] - m_a);
                float p2 = fexp2(sc[nt][2] - m_b);
                float p3 = fexp2(sc[nt][3] - m_b);
                suma += p0 + p1; sumb += p2 + p3;
                ph[s2][hf * 2 + 0] = pack_f16(p0, p1);
                ph[s2][hf * 2 + 1] = pack_f16(p2, p3);
            }
        }
        suma += __shfl_xor_sync(0xffffffffu, suma, 1);
        suma += __shfl_xor_sync(0xffffffffu, suma, 2);
        sumb += __shfl_xor_sync(0xffffffffu, sumb, 1);
        sumb += __shfl_xor_sync(0xffffffffu, sumb, 2);
        l_a = alf_a * l_a + suma;
        l_b = alf_b * l_b + sumb;

#pragma unroll
        for (int vt = 0; vt < 16; vt++) {
            o[vt][0] *= alf_a; o[vt][1] *= alf_a;
            o[vt][2] *= alf_b; o[vt][3] *= alf_b;
        }

        // ---- O += P V ----
        const uint32_t vb = stb + 2 * QK_TILE;
        const uint32_t vrow4 = (uint32_t)(lane & 15) * PVB + ((lane >> 4) << 4);
#pragma unroll
        for (int vt2 = 0; vt2 < 8; vt2++) {
#pragma unroll
            for (int s2 = 0; s2 < 4; s2++) {
                uint32_t addr = (uint32_t)(s2 * 16) * PVB + vrow4 + vt2 * 32;
                uint32_t bh4[4];
                ldmx4t(bh4, vb + addr);
                mma_fp16(o[2 * vt2],     ph[s2], &bh4[0]);
                mma_fp16(o[2 * vt2 + 1], ph[s2], &bh4[2]);
            }
        }
        __syncthreads();
    }

    float lam = sLam[0];
    float ra = 1.0f / l_a, rb = 1.0f / l_b;

    if (br == 0) {
#pragma unroll
        for (int vt = 0; vt < 16; vt++) {
            int c = vt * 8 + 2 * tg;
            *(float2*)&sOut[(rbase + g) * 128 + c] = make_float2(o[vt][0] * ra, o[vt][1] * ra);
            *(float2*)&sOut[(rbase + g + 8) * 128 + c] = make_float2(o[vt][2] * rb, o[vt][3] * rb);
        }
    }
    __syncthreads();
    if (br == 1) {
#pragma unroll
        for (int vt = 0; vt < 16; vt++) {
            int c = vt * 8 + 2 * tg;
            float2* p0 = (float2*)&sOut[(rbase + g) * 128 + c];
            float2 v0 = *p0;
            v0.x -= lam * o[vt][0] * ra; v0.y -= lam * o[vt][1] * ra;
            *p0 = v0;
            float2* p1 = (float2*)&sOut[(rbase + g + 8) * 128 + c];
            float2 v1 = *p1;
            v1.x -= lam * o[vt][2] * rb; v1.y -= lam * o[vt][3] * rb;
            *p1 = v1;
        }
    }
    __syncthreads();

    // ---- RMSNorm + scale + fp16 split write ----
    {
        int r = tid >> 2;
        int q4 = tid & 3;
        float ss = 0.f;
#pragma unroll
        for (int u = 0; u < 32; u++) {
            float v = sOut[r * 128 + q4 * 32 + u];
            ss += v * v;
        }
        ss += __shfl_xor_sync(0xffffffffu, ss, 1);
        ss += __shfl_xor_sync(0xffffffffu, ss, 2);
        float rn = rsqrtf(ss * (1.0f / 128.0f) + 1e-8f);
        size_t outrow = (rowBase + q0t + r) * D_EMB + colH;
#pragma unroll
        for (int u = 0; u < 32; u += 2) {
            int e = q4 * 32 + u;
            float v0 = (sOut[r * 128 + e] * rn * lnw[e] + lnb[e]) * ONE_MINUS_LI_F;
            float v1 = (sOut[r * 128 + e + 1] * rn * lnw[e + 1] + lnb[e + 1]) * ONE_MINUS_LI_F;
            uint32_t hw, lw;
            split2h(v0, v1, hw, lw);
            *(uint32_t*)&Ahi[outrow + e] = hw;
            *(uint32_t*)&Alo[outrow + e] = lw;
        }
    }
}

// ---------------- launch ---------------------------------------------------
extern "C" void kernel_launch(void* const* d_in, const int* in_sizes, int n_in,
                              void* d_out, int out_size)
{
    (void)in_sizes; (void)n_in; (void)out_size;
    const float* x   = (const float*)d_in[0];
    const float* Wq  = (const float*)d_in[1];
    const float* Wk  = (const float*)d_in[2];
    const float* Wv  = (const float*)d_in[3];
    const float* Wo  = (const float*)d_in[4];
    const float* lq1 = (const float*)d_in[5];
    const float* lk1 = (const float*)d_in[6];
    const float* lq2 = (const float*)d_in[7];
    const float* lk2 = (const float*)d_in[8];
    const float* lnw = (const float*)d_in[9];
    const float* lnb = (const float*)d_in[10];
    float* out = (float*)d_out;

    __half *x16, *w16, *ahi, *alo;
    __half *q16, *k16, *v16;
    cudaGetSymbolAddress((void**)&x16, g_x16);
    cudaGetSymbolAddress((void**)&w16, g_w16);
    cudaGetSymbolAddress((void**)&ahi, g_a16h);
    cudaGetSymbolAddress((void**)&alo, g_a16l);
    cudaGetSymbolAddress((void**)&q16, g_Q16);
    cudaGetSymbolAddress((void**)&k16, g_K16);
    cudaGetSymbolAddress((void**)&v16, g_V16);

    const int nx4 = (MROWS * D_EMB) / 4;
    const int nw4 = (D_EMB * D_EMB) / 4;

    dim3 wsg((nw4 + 255) / 256, 4);
    wsplit_all_kernel<<<wsg, 256>>>(Wq, Wk, Wv, Wo, w16);
    conv_kernel<<<(nx4 + 255) / 256, 256>>>(x, x16, nx4);

    cudaFuncSetAttribute((const void*)gemm_fp16<1, 0>,
                         cudaFuncAttributeMaxDynamicSharedMemorySize, G_SMEM_X1);
    cudaFuncSetAttribute((const void*)gemm_fp16<0, 1>,
                         cudaFuncAttributeMaxDynamicSharedMemorySize, G_SMEM_X2);

    // fused QKV projection (single-fp16 A) + rope + fp16 epilogue
    dim3 gqkv(NQKV / 128, MROWS / 128);   // (48, 32)
    gemm_fp16<1, 0><<<gqkv, 256, G_SMEM_X1>>>(x16, nullptr, w16, nullptr,
                                              MROWS, NQKV, D_EMB, WCOLS, 0);

    cudaFuncSetAttribute(flash_mma_kernel, cudaFuncAttributeMaxDynamicSharedMemorySize, FL_SMEM);
    flash_mma_kernel<<<dim3(32, NHEAD, BATCH), 256, FL_SMEM>>>(
        q16, k16, v16, lq1, lk1, lq2, lk2, lnw, lnb, ahi, alo);

    // output projection (x2 split A — error is output-direct)
    dim3 go(D_EMB / 128, MROWS / 128);    // (16, 32)
    gemm_fp16<0, 1><<<go, 256, G_SMEM_X2>>>(ahi, alo, w16 + 6144, out,
                                            MROWS, D_EMB, D_EMB, WCOLS, D_EMB);
}